// round 14
// baseline (speedup 1.0000x reference)
#include <cuda_runtime.h>
#include <cuda_bf16.h>
#include <math.h>
#include <stdint.h>

// ---------------------------------------------------------------------------
// Problem constants: x (N=128, V=25, T=64, C=64), IC=16, S=3, TS=2
// ---------------------------------------------------------------------------
#define NN 128
#define NVT 204800          // N*V*T == N*T*V
#define TPAD 70             // T + 6 (conv halo)
#define MPAD 224000         // N*TPAD*V rows for padded z
#define GUARD 4800          // 3*V*C guard floats (75 rows) before/after padded z
#define QKOFF 9830400       // bf16 elems per Q plane: 128*3*25600
#define QTN 26214400        // bf16 elems per qkt plane: NVT*128

// ---------------------------------------------------------------------------
// Scratch (static device globals; no runtime allocation allowed)
// ---------------------------------------------------------------------------
__device__ float g_bufA[(size_t)NVT * 256];                 // ycat / zcat
__device__ float g_bufB[(size_t)NVT * 128];                 // Q/K bf16 planes / qkt bf16 planes
__device__ float g_bufC[(size_t)NVT * 64];                  // gemm outputs / att_s partials
__device__ float g_bufD[(size_t)NVT * 64];                  // y1 / z-mid / conv out
__device__ float g_bufE[(size_t)NVT * 64];                  // y transposed (n,t,v,c)
__device__ float g_bufF[GUARD + (size_t)MPAD * 64 + GUARD]; // padded z + guards
__device__ float g_attS[(size_t)NN * 625 * 3];
__device__ float g_attT[(size_t)NN * 4 * 64 * 64];
__device__ float g_bis[96];                                 // b_in_s col-permuted
__device__ float g_bit[128];                                // b_in_t col-permuted
__device__ float g_bnstats[128];                            // sum[64], sumsq[64]

// Pre-packed mma.sync B fragments: per (k16-chunk, ntile, lane) a uint4 =
// {b_hi_reg0, b_hi_reg1, b_lo_reg0, b_lo_reg1}
__device__ uint4 g_Fqk[4 * 12 * 32];      // K=64,  Nc=96
__device__ uint4 g_Fouts[12 * 8 * 32];    // K=192, Nc=64
__device__ uint4 g_Fffs[4 * 8 * 32];      // K=64,  Nc=64
__device__ uint4 g_Fint[4 * 16 * 32];     // K=64,  Nc=128 (col-permuted j*16+ic)
__device__ uint4 g_Foutt[16 * 8 * 32];    // K=256, Nc=64
__device__ uint4 g_Ffft[4 * 8 * 32];      // K=64,  Nc=64
__device__ uint4 g_Fconv[28 * 8 * 32];    // K=448, Nc=64

__device__ __forceinline__ float gelu_f(float x) {
    return 0.5f * x * (1.f + erff(x * 0.70710678118654752f));
}

__device__ __forceinline__ uint32_t smem_u32(const void* p) {
    uint32_t a;
    asm("{ .reg .u64 t; cvta.to.shared.u64 t, %1; cvt.u32.u64 %0, t; }" : "=r"(a) : "l"(p));
    return a;
}
__device__ __forceinline__ void ldm4(uint32_t* r, uint32_t addr) {
    asm volatile("ldmatrix.sync.aligned.m8n8.x4.shared.b16 {%0,%1,%2,%3}, [%4];"
                 : "=r"(r[0]), "=r"(r[1]), "=r"(r[2]), "=r"(r[3]) : "r"(addr));
}
__device__ __forceinline__ void ldm4t(uint32_t* r, uint32_t addr) {
    asm volatile("ldmatrix.sync.aligned.m8n8.x4.trans.shared.b16 {%0,%1,%2,%3}, [%4];"
                 : "=r"(r[0]), "=r"(r[1]), "=r"(r[2]), "=r"(r[3]) : "r"(addr));
}
__device__ __forceinline__ void mma16816(float* c, const uint32_t* a,
                                         uint32_t b0, uint32_t b1) {
    asm volatile(
        "mma.sync.aligned.m16n8k16.row.col.f32.bf16.bf16.f32 "
        "{%0,%1,%2,%3}, {%4,%5,%6,%7}, {%8,%9}, {%0,%1,%2,%3};"
        : "+f"(c[0]), "+f"(c[1]), "+f"(c[2]), "+f"(c[3])
        : "r"(a[0]), "r"(a[1]), "r"(a[2]), "r"(a[3]), "r"(b0), "r"(b1));
}
__device__ __forceinline__ uint32_t pkbf(float a, float b) {
    __nv_bfloat162 t = __floats2bfloat162_rn(a, b);
    return *(uint32_t*)&t;
}

// ---------------------------------------------------------------------------
// Prep: build B fragments (hi/lo split, permuted), permuted biases, zero bn
// ---------------------------------------------------------------------------
__device__ __forceinline__ void mk_frag(uint4* dst, int i, int NT,
                                        float w00, float w01, float w10, float w11) {
    float h00 = __bfloat162float(__float2bfloat16_rn(w00));
    float h01 = __bfloat162float(__float2bfloat16_rn(w01));
    float h10 = __bfloat162float(__float2bfloat16_rn(w10));
    float h11 = __bfloat162float(__float2bfloat16_rn(w11));
    dst[i] = make_uint4(pkbf(h00, h01), pkbf(h10, h11),
                        pkbf(w00 - h00, w01 - h01), pkbf(w10 - h10, w11 - h11));
}
#define FRAG_IDX(NT) \
    int lane = i & 31, nt = (i >> 5) % (NT), kc = (i >> 5) / (NT); \
    int g = lane >> 2, tig = lane & 3; \
    int n = nt * 8 + g; int k0 = kc * 16 + 2 * tig; (void)kc;

__global__ void prep_kernel(const float* __restrict__ wqk, const float* __restrict__ bqk,
                            const float* __restrict__ ws, const float* __restrict__ wffs,
                            const float* __restrict__ wint, const float* __restrict__ bint,
                            const float* __restrict__ wt,
                            const float* __restrict__ wfft, const float* __restrict__ cw) {
    int i = blockIdx.x * 256 + threadIdx.x;
    if (i < 4 * 12 * 32) {     // qk: Nc=96, K=64
        FRAG_IDX(12)
        int cc = (n < 48) ? n : n - 48;
        int s = cc >> 4, ic = cc & 15;
        int old = ic * 6 + s + ((n < 48) ? 0 : 3);
        mk_frag(g_Fqk, i, 12,
                wqk[k0 * 96 + old], wqk[(k0 + 1) * 96 + old],
                wqk[(k0 + 8) * 96 + old], wqk[(k0 + 9) * 96 + old]);
    }
    if (i < 96) {
        int cc = (i < 48) ? i : i - 48;
        int s = cc >> 4, ic = cc & 15;
        g_bis[i] = bqk[ic * 6 + s + ((i < 48) ? 0 : 3)];
    }
    if (i < 128) {             // in_t bias: new col n = j*16+ic -> old ic*8+j
        int j = i >> 4, ic = i & 15;
        g_bit[i] = bint[ic * 8 + j];
    }
    if (i < 12 * 8 * 32) {     // out_s: k = s*64+c -> orig row c*3+s, Nc=64
        FRAG_IDX(8)
        float w[4];
#pragma unroll
        for (int e = 0; e < 4; e++) {
            int k = k0 + (e >> 1) * 8 + (e & 1);
            int s = k >> 6, c = k & 63;
            w[e] = ws[(c * 3 + s) * 64 + n];
        }
        mk_frag(g_Fouts, i, 8, w[0], w[1], w[2], w[3]);
    }
    if (i < 4 * 8 * 32) {      // ff_s / ff_t: [K=64][64]
        FRAG_IDX(8)
        mk_frag(g_Fffs, i, 8, wffs[k0 * 64 + n], wffs[(k0 + 1) * 64 + n],
                wffs[(k0 + 8) * 64 + n], wffs[(k0 + 9) * 64 + n]);
        mk_frag(g_Ffft, i, 8, wfft[k0 * 64 + n], wfft[(k0 + 1) * 64 + n],
                wfft[(k0 + 8) * 64 + n], wfft[(k0 + 9) * 64 + n]);
    }
    if (i < 4 * 16 * 32) {     // in_t: [K=64][128], cols permuted n=j*16+ic
        FRAG_IDX(16)
        int j = n >> 4, ic = n & 15;
        int old = ic * 8 + j;
        mk_frag(g_Fint, i, 16, wint[k0 * 128 + old], wint[(k0 + 1) * 128 + old],
                wint[(k0 + 8) * 128 + old], wint[(k0 + 9) * 128 + old]);
    }
    if (i < 16 * 8 * 32) {     // out_t: k = dir*128+s*64+c -> orig dir*128+c*2+s
        FRAG_IDX(8)
        float w[4];
#pragma unroll
        for (int e = 0; e < 4; e++) {
            int k = k0 + (e >> 1) * 8 + (e & 1);
            int dir = k >> 7, s = (k >> 6) & 1, c = k & 63;
            w[e] = wt[(dir * 128 + c * 2 + s) * 64 + n];
        }
        mk_frag(g_Foutt, i, 8, w[0], w[1], w[2], w[3]);
    }
    if (i < 28 * 8 * 32) {     // conv: k = dt*64+ci, orig (co,ci,dt)
        FRAG_IDX(8)
        float w[4];
#pragma unroll
        for (int e = 0; e < 4; e++) {
            int k = k0 + (e >> 1) * 8 + (e & 1);
            int dt = k >> 6, ci = k & 63;
            w[e] = cw[(n * 64 + ci) * 7 + dt];
        }
        mk_frag(g_Fconv, i, 8, w[0], w[1], w[2], w[3]);
    }
    if (i < 128) g_bnstats[i] = 0.f;
}

__global__ void zero_pads_kernel(float* __restrict__ zbase) {
    int e = blockIdx.x * 256 + threadIdx.x;   // over 128*6*1600
    int n = e / 9600, r = e - n * 9600;
    int k = r / 1600, rem = r - k * 1600;
    int tp = (k < 3) ? k : (k + 64);          // pad rows {0,1,2,67,68,69}
    zbase[((size_t)(n * TPAD + tp)) * 1600 + rem] = 0.f;
}

// ---------------------------------------------------------------------------
// Shared GEMM mainloop macro (MF=1, round-8 proven config): fp32 A -> bf16
// hi/lo smem, 3xHMMA per k16. 256 thr, 128-row M tile. B fragments in gmem.
// ---------------------------------------------------------------------------
#define AST 72   // smem bf16 row stride (144 B) -> conflict-free ldmatrix

#define GEMM_MAINLOOP(NT_, CONV_)                                                  \
    int tid = threadIdx.x, warp = tid >> 5, lane = tid & 31;                       \
    int g = lane >> 2, tig = lane & 3;                                             \
    int bm = blockIdx.x << 7;                                                      \
    int lda = (CONV_) ? 64 : K;                                                    \
    float acc[NT_][4];                                                             \
    _Pragma("unroll") for (int i_ = 0; i_ < NT_; i_++)                             \
        _Pragma("unroll") for (int j_ = 0; j_ < 4; j_++) acc[i_][j_] = 0.f;        \
    uint32_t arow_off =                                                            \
        (uint32_t)(((warp << 4) + (lane & 15)) * (AST * 2) + ((lane >> 4) << 4));  \
    uint32_t ah_addr = smem_u32(sAh) + arow_off;                                   \
    uint32_t al_addr = smem_u32(sAl) + arow_off;                                   \
    int crow = tid >> 1, ccol = (tid & 1) << 5;                                    \
    char* sh = (char*)sAh + crow * (AST * 2) + ccol * 2;                           \
    char* sl = (char*)sAl + crow * (AST * 2) + ccol * 2;                           \
    int chunks = K >> 6;                                                           \
    for (int ch = 0; ch < chunks; ch++) {                                          \
        long rshift = (CONV_) ? (long)(ch - 3) * 25 : 0;                           \
        int col0 = (CONV_) ? 0 : (ch << 6);                                        \
        const float* ap = A + ((long)bm + rshift + crow) * lda + col0 + ccol;      \
        _Pragma("unroll") for (int j = 0; j < 8; j++) {                            \
            float4 v = *(const float4*)(ap + (j << 2));                            \
            float hx = __bfloat162float(__float2bfloat16_rn(v.x));                 \
            float hy = __bfloat162float(__float2bfloat16_rn(v.y));                 \
            float hz = __bfloat162float(__float2bfloat16_rn(v.z));                 \
            float hw = __bfloat162float(__float2bfloat16_rn(v.w));                 \
            *(uint2*)(sh + (j << 3)) = make_uint2(pkbf(hx, hy), pkbf(hz, hw));     \
            *(uint2*)(sl + (j << 3)) =                                             \
                make_uint2(pkbf(v.x - hx, v.y - hy), pkbf(v.z - hz, v.w - hw));    \
        }                                                                          \
        __syncthreads();                                                           \
        _Pragma("unroll") for (int ks = 0; ks < 4; ks++) {                         \
            uint32_t a_h[4], a_l[4];                                               \
            ldm4(a_h, ah_addr + ks * 32);                                          \
            ldm4(a_l, al_addr + ks * 32);                                          \
            const uint4* Fp = F + ((size_t)((ch << 2) + ks) * NT_) * 32 + lane;    \
            _Pragma("unroll") for (int nt = 0; nt < NT_; nt++) {                   \
                uint4 bf = Fp[nt * 32];                                            \
                mma16816(acc[nt], a_h, bf.x, bf.y);                                \
                mma16816(acc[nt], a_h, bf.z, bf.w);                                \
                mma16816(acc[nt], a_l, bf.x, bf.y);                                \
            }                                                                      \
        }                                                                          \
        __syncthreads();                                                           \
    }

// ---------------------------------------------------------------------------
// Plain GEMM (out_t/ff_t Nc=64)
// ---------------------------------------------------------------------------
template <int NC>
__global__ void __launch_bounds__(256)
mma_gemm_kernel(const float* __restrict__ A, const uint4* __restrict__ F,
                const float* __restrict__ bias, float* __restrict__ C, int K) {
    __shared__ __align__(16) __nv_bfloat16 sAh[128 * AST];
    __shared__ __align__(16) __nv_bfloat16 sAl[128 * AST];
    constexpr int NT = NC / 8;
    GEMM_MAINLOOP(NT, 0)
    size_t r0 = (size_t)bm + (warp << 4) + g;
#pragma unroll
    for (int nt = 0; nt < NT; nt++) {
        int col = (nt << 3) + (tig << 1);
        float bx = bias[col], by = bias[col + 1];
        *(float2*)&C[r0 * NC + col] = make_float2(acc[nt][0] + bx, acc[nt][1] + by);
        *(float2*)&C[(r0 + 8) * NC + col] = make_float2(acc[nt][2] + bx, acc[nt][3] + by);
    }
}

// ---------------------------------------------------------------------------
// qk GEMM (Nc=96): epilogue writes bf16 hi/lo PLANES directly.
// Q hi plane [0,QKOFF), Q lo [QKOFF,2Q), K hi [2Q,3Q), K lo [3Q,4Q);
// elem offset within plane: (n*3+s)*25600 + u*1024 + t*16 + ic.
// ---------------------------------------------------------------------------
__global__ void __launch_bounds__(256)
mma_gemm_qk_kernel(const float* __restrict__ A, const uint4* __restrict__ F,
                   const float* __restrict__ bias, __nv_bfloat16* __restrict__ QKbf,
                   int K) {
    __shared__ __align__(16) __nv_bfloat16 sAh[128 * AST];
    __shared__ __align__(16) __nv_bfloat16 sAl[128 * AST];
    GEMM_MAINLOOP(12, 0)
    size_t r0 = (size_t)bm + (warp << 4) + g;
    int n = (int)(r0 / 1600);
    int rem = (int)(r0 - (size_t)n * 1600);
    int u = rem >> 6, t0 = rem & 63;
#pragma unroll
    for (int nt = 0; nt < 12; nt++) {
        int col = (nt << 3) + (tig << 1);
        float bx = bias[col], by = bias[col + 1];
        int half = col >= 48;
        int cc = col - (half ? 48 : 0);
        int s = cc >> 4, ic = cc & 15;
        __nv_bfloat16* hi = QKbf + (size_t)(half ? 2 : 0) * QKOFF +
                            (size_t)(n * 3 + s) * 25600 + u * 1024 + ic;
        __nv_bfloat16* lo = hi + QKOFF;
        float v0 = acc[nt][0] + bx, v1 = acc[nt][1] + by;
        float h0 = __bfloat162float(__float2bfloat16_rn(v0));
        float h1 = __bfloat162float(__float2bfloat16_rn(v1));
        *(uint32_t*)&hi[t0 << 4] = pkbf(v0, v1);
        *(uint32_t*)&lo[t0 << 4] = pkbf(v0 - h0, v1 - h1);
        float v2 = acc[nt][2] + bx, v3 = acc[nt][3] + by;
        float h2 = __bfloat162float(__float2bfloat16_rn(v2));
        float h3 = __bfloat162float(__float2bfloat16_rn(v3));
        *(uint32_t*)&hi[(t0 + 8) << 4] = pkbf(v2, v3);
        *(uint32_t*)&lo[(t0 + 8) << 4] = pkbf(v2 - h2, v3 - h3);
    }
}

// ---------------------------------------------------------------------------
// in_t GEMM (Nc=128): epilogue writes qkt as bf16 hi/lo planes.
// hi plane [0,QTN), lo plane [QTN,2*QTN); elem = row*128 + col.
// ---------------------------------------------------------------------------
__global__ void __launch_bounds__(256)
mma_gemm_int_kernel(const float* __restrict__ A, const uint4* __restrict__ F,
                    const float* __restrict__ bias, __nv_bfloat16* __restrict__ QT,
                    int K) {
    __shared__ __align__(16) __nv_bfloat16 sAh[128 * AST];
    __shared__ __align__(16) __nv_bfloat16 sAl[128 * AST];
    GEMM_MAINLOOP(16, 0)
    size_t r0 = (size_t)bm + (warp << 4) + g;
    __nv_bfloat16* QTL = QT + (size_t)QTN;
#pragma unroll
    for (int nt = 0; nt < 16; nt++) {
        int col = (nt << 3) + (tig << 1);
        float bx = bias[col], by = bias[col + 1];
        float v0 = acc[nt][0] + bx, v1 = acc[nt][1] + by;
        float h0 = __bfloat162float(__float2bfloat16_rn(v0));
        float h1 = __bfloat162float(__float2bfloat16_rn(v1));
        size_t e0 = (r0 << 7) + col;
        *(uint32_t*)&QT[e0] = pkbf(v0, v1);
        *(uint32_t*)&QTL[e0] = pkbf(v0 - h0, v1 - h1);
        float v2 = acc[nt][2] + bx, v3 = acc[nt][3] + by;
        float h2 = __bfloat162float(__float2bfloat16_rn(v2));
        float h3 = __bfloat162float(__float2bfloat16_rn(v3));
        size_t e1 = ((r0 + 8) << 7) + col;
        *(uint32_t*)&QT[e1] = pkbf(v2, v3);
        *(uint32_t*)&QTL[e1] = pkbf(v2 - h2, v3 - h3);
    }
}

// ---------------------------------------------------------------------------
// GEMM + LayerNorm((T,C) groups of 64 rows) + residual + GELU fused epilogue.
// ---------------------------------------------------------------------------
template <int TRANSPOSE>
__global__ void __launch_bounds__(256)
mma_gemm_lns_kernel(const float* __restrict__ A, const uint4* __restrict__ F,
                    const float* __restrict__ bias, const float* __restrict__ resid,
                    const float* __restrict__ gg, const float* __restrict__ bb,
                    float* __restrict__ out, int K) {
    __shared__ __align__(16) __nv_bfloat16 sAh[128 * AST];
    __shared__ __align__(16) __nv_bfloat16 sAl[128 * AST];
    __shared__ float wsum[8], wsq[8];
    GEMM_MAINLOOP(8, 0)

    float vals[8][4];
    float psum = 0.f;
#pragma unroll
    for (int nt = 0; nt < 8; nt++) {
        int col = (nt << 3) + (tig << 1);
        float bx = bias[col], by = bias[col + 1];
        vals[nt][0] = acc[nt][0] + bx; vals[nt][1] = acc[nt][1] + by;
        vals[nt][2] = acc[nt][2] + bx; vals[nt][3] = acc[nt][3] + by;
        psum += vals[nt][0] + vals[nt][1] + vals[nt][2] + vals[nt][3];
    }
#pragma unroll
    for (int o = 16; o; o >>= 1) psum += __shfl_xor_sync(0xffffffffu, psum, o);
    if (lane == 0) wsum[warp] = psum;
    __syncthreads();
    int grp4 = (warp >> 2) << 2;
    float mean = (wsum[grp4] + wsum[grp4 + 1] + wsum[grp4 + 2] + wsum[grp4 + 3]) *
                 (1.f / 4096.f);
    float psq = 0.f;
#pragma unroll
    for (int nt = 0; nt < 8; nt++)
#pragma unroll
        for (int j = 0; j < 4; j++) { float d = vals[nt][j] - mean; psq += d * d; }
#pragma unroll
    for (int o = 16; o; o >>= 1) psq += __shfl_xor_sync(0xffffffffu, psq, o);
    if (lane == 0) wsq[warp] = psq;
    __syncthreads();
    float inv = rsqrtf((wsq[grp4] + wsq[grp4 + 1] + wsq[grp4 + 2] + wsq[grp4 + 3]) *
                           (1.f / 4096.f) + 1e-5f);

    size_t r0 = (size_t)bm + (warp << 4) + g;
    size_t r1 = r0 + 8;
    int tl0 = (int)(r0 & 63), tl1 = tl0 + 8;
    size_t oa0, oa1;
    if (TRANSPOSE) {
        int n0 = (int)(r0 / 1600), rem0 = (int)(r0 - (size_t)n0 * 1600);
        int v0 = rem0 >> 6;
        oa0 = ((size_t)(n0 * 64 + tl0) * 25 + v0) << 6;
        oa1 = ((size_t)(n0 * 64 + tl1) * 25 + v0) << 6;
    } else {
        oa0 = r0 << 6; oa1 = r1 << 6;
    }
#pragma unroll
    for (int nt = 0; nt < 8; nt++) {
        int col = (nt << 3) + (tig << 1);
        float2 g0 = *(const float2*)&gg[tl0 * 64 + col];
        float2 b0 = *(const float2*)&bb[tl0 * 64 + col];
        float2 g1 = *(const float2*)&gg[tl1 * 64 + col];
        float2 b1 = *(const float2*)&bb[tl1 * 64 + col];
        float2 rx0 = *(const float2*)&resid[(r0 << 6) + col];
        float2 rx1 = *(const float2*)&resid[(r1 << 6) + col];
        float2 o0, o1;
        o0.x = gelu_f(rx0.x + (vals[nt][0] - mean) * inv * g0.x + b0.x);
        o0.y = gelu_f(rx0.y + (vals[nt][1] - mean) * inv * g0.y + b0.y);
        o1.x = gelu_f(rx1.x + (vals[nt][2] - mean) * inv * g1.x + b1.x);
        o1.y = gelu_f(rx1.y + (vals[nt][3] - mean) * inv * g1.y + b1.y);
        *(float2*)&out[oa0 + col] = o0;
        *(float2*)&out[oa1 + col] = o1;
    }
}

// ---------------------------------------------------------------------------
// Conv implicit-GEMM (K=448, row-shifted A) + fused BN partial-sum reduce.
// ---------------------------------------------------------------------------
__global__ void __launch_bounds__(256)
mma_gemm_conv_kernel(const float* __restrict__ A, const uint4* __restrict__ F,
                     const float* __restrict__ bias, float* __restrict__ C, int K) {
    __shared__ __align__(16) __nv_bfloat16 sAh[128 * AST];
    __shared__ __align__(16) __nv_bfloat16 sAl[128 * AST];
    __shared__ float ss[64], sqq[64];
    if (threadIdx.x < 64) { ss[threadIdx.x] = 0.f; sqq[threadIdx.x] = 0.f; }
    GEMM_MAINLOOP(8, 1)

    size_t r0 = (size_t)bm + (warp << 4) + g;
    size_t r1 = r0 + 8;
    int rem0 = (int)(r0 % 1750), rem1 = (int)(r1 % 1750);
    bool va0 = (rem0 >= 75) && (rem0 < 1675);
    bool va1 = (rem1 >= 75) && (rem1 < 1675);
#pragma unroll
    for (int nt = 0; nt < 8; nt++) {
        int col = (nt << 3) + (tig << 1);
        float bx = bias[col], by = bias[col + 1];
        float v00 = acc[nt][0] + bx, v01 = acc[nt][1] + by;
        float v10 = acc[nt][2] + bx, v11 = acc[nt][3] + by;
        *(float2*)&C[(r0 << 6) + col] = make_float2(v00, v01);
        *(float2*)&C[(r1 << 6) + col] = make_float2(v10, v11);
        float s0 = (va0 ? v00 : 0.f) + (va1 ? v10 : 0.f);
        float s1 = (va0 ? v01 : 0.f) + (va1 ? v11 : 0.f);
        float q0 = (va0 ? v00 * v00 : 0.f) + (va1 ? v10 * v10 : 0.f);
        float q1 = (va0 ? v01 * v01 : 0.f) + (va1 ? v11 * v11 : 0.f);
        atomicAdd(&ss[col], s0); atomicAdd(&ss[col + 1], s1);
        atomicAdd(&sqq[col], q0); atomicAdd(&sqq[col + 1], q1);
    }
    __syncthreads();
    if (tid < 64) {
        atomicAdd(&g_bnstats[tid], ss[tid]);
        atomicAdd(&g_bnstats[64 + tid], sqq[tid]);
    }
}

// ---------------------------------------------------------------------------
// Spatial attention via HMMA, split-K z=4 (2 chunks each). Q/K pre-split bf16
// planes -> load loop is pure uint2 copies (no conversion ALU).
// ---------------------------------------------------------------------------
#define QST 136   // bf16 row stride (272 B)
__global__ void __launch_bounds__(256)
att_s_hmma_kernel(const __nv_bfloat16* __restrict__ QKbf, float* __restrict__ part) {
    extern __shared__ char dsm[];
    __nv_bfloat16* sQh = (__nv_bfloat16*)dsm;
    __nv_bfloat16* sQl = (__nv_bfloat16*)(dsm + 8704);
    __nv_bfloat16* sKh = (__nv_bfloat16*)(dsm + 17408);
    __nv_bfloat16* sKl = (__nv_bfloat16*)(dsm + 26112);
    float* psum = (float*)(dsm + 34816);   // [4 kg][32 u][32 v]
    int n = blockIdx.x, s = blockIdx.y, z = blockIdx.z;
    int tid = threadIdx.x, warp = tid >> 5, lane = tid & 31;
    int g = lane >> 2, tig = lane & 3;
    int mt = warp & 1, kg = warp >> 1;

    for (int i = tid; i < 476; i += 256) {
        int u = 25 + i / 68, c2 = i % 68;
        ((uint32_t*)(sQh + u * QST))[c2] = 0u;
        ((uint32_t*)(sQl + u * QST))[c2] = 0u;
        ((uint32_t*)(sKh + u * QST))[c2] = 0u;
        ((uint32_t*)(sKl + u * QST))[c2] = 0u;
    }

    size_t pb = (size_t)(n * 3 + s) * 25600;
    const __nv_bfloat16* QH = QKbf + pb;
    const __nv_bfloat16* QL = QKbf + (size_t)QKOFF + pb;
    const __nv_bfloat16* KH = QKbf + (size_t)2 * QKOFF + pb;
    const __nv_bfloat16* KL = QKbf + (size_t)3 * QKOFF + pb;

    uint32_t q_off = (uint32_t)(((mt << 4) + (lane & 15)) * (QST * 2) +
                                ((lane >> 4) << 4));
    uint32_t k_off = (uint32_t)((lane & 15) * (QST * 2) + ((lane >> 4) << 4));
    uint32_t qh_a = smem_u32(sQh) + q_off, ql_a = smem_u32(sQl) + q_off;
    uint32_t kh_a = smem_u32(sKh) + k_off, kl_a = smem_u32(sKl) + k_off;

    float acc[4][4];
#pragma unroll
    for (int i = 0; i < 4; i++)
#pragma unroll
        for (int j = 0; j < 4; j++) acc[i][j] = 0.f;

    for (int cc = 0; cc < 2; cc++) {
        int ch = (z << 1) + cc;
        __syncthreads();
        for (int idx = tid; idx < 1600; idx += 256) {
            int half = idx >= 800;
            int id = idx - (half ? 800 : 0);
            int u = id >> 5, w = id & 31;
            int e = u * 1024 + (ch << 7) + (w << 2);
            uint2 vh = *(const uint2*)((half ? KH : QH) + e);
            uint2 vl = *(const uint2*)((half ? KL : QL) + e);
            int so = u * QST + (w << 2);
            if (half) {
                *(uint2*)&sKh[so] = vh;
                *(uint2*)&sKl[so] = vl;
            } else {
                *(uint2*)&sQh[so] = vh;
                *(uint2*)&sQl[so] = vl;
            }
        }
        __syncthreads();
#pragma unroll
        for (int ks2 = 0; ks2 < 2; ks2++) {
            int ks = (kg << 1) + ks2;
            uint32_t qh[4], ql[4];
            ldm4(qh, qh_a + ks * 32);
            ldm4(ql, ql_a + ks * 32);
            uint32_t kh[4], kl[4];
            ldm4(kh, kh_a + ks * 32);
            ldm4(kl, kl_a + ks * 32);
            mma16816(acc[0], qh, kh[0], kh[2]);
            mma16816(acc[0], qh, kl[0], kl[2]);
            mma16816(acc[0], ql, kh[0], kh[2]);
            mma16816(acc[1], qh, kh[1], kh[3]);
            mma16816(acc[1], qh, kl[1], kl[3]);
            mma16816(acc[1], ql, kh[1], kh[3]);
            uint32_t kh2[4], kl2[4];
            ldm4(kh2, kh_a + 16 * (QST * 2) + ks * 32);
            ldm4(kl2, kl_a + 16 * (QST * 2) + ks * 32);
            mma16816(acc[2], qh, kh2[0], kh2[2]);
            mma16816(acc[2], qh, kl2[0], kl2[2]);
            mma16816(acc[2], ql, kh2[0], kh2[2]);
            mma16816(acc[3], qh, kh2[1], kh2[3]);
            mma16816(acc[3], qh, kl2[1], kl2[3]);
            mma16816(acc[3], ql, kh2[1], kh2[3]);
        }
    }
    int row0 = (mt << 4) + g;
#pragma unroll
    for (int nt = 0; nt < 4; nt++) {
        int col = ((nt & 1) << 3) + ((nt >> 1) << 4) + (tig << 1);
        psum[((kg << 5) + row0) * 32 + col] = acc[nt][0];
        psum[((kg << 5) + row0) * 32 + col + 1] = acc[nt][1];
        psum[((kg << 5) + row0 + 8) * 32 + col] = acc[nt][2];
        psum[((kg << 5) + row0 + 8) * 32 + col + 1] = acc[nt][3];
    }
    __syncthreads();
    for (int idx = tid; idx < 1024; idx += 256) {
        int u = idx >> 5, v = idx & 31;
        if (u < 25 && v < 25) {
            float raw = psum[idx] + psum[1024 + idx] + psum[2048 + idx] +
                        psum[3072 + idx];
            int p = u * 25 + v;
            part[((size_t)z * 128 + n) * 1875 + p * 3 + s] = raw;
        }
    }
}

// ---------------------------------------------------------------------------
// att_s combine: sum 4 K-split partials, apply tanh*alpha + att0
// ---------------------------------------------------------------------------
__global__ void att_s2_kernel(const float* __restrict__ part,
                              const float* __restrict__ alphas,
                              const float* __restrict__ att0, float* __restrict__ attS) {
    int e = blockIdx.x * 256 + threadIdx.x;
    if (e >= 240000) return;
    float raw = part[e] + part[240000 + e] + part[480000 + e] + part[720000 + e];
    int s = e % 3;
    attS[e] = tanhf(raw * (1.f / 1024.f)) * alphas[s] + att0[e % 1875];
}

// ---------------------------------------------------------------------------
// mix_s via HMMA (round-11 proven)
// ---------------------------------------------------------------------------
#define MXA 40   // A smem stride (elems)
#define MXB 136  // B smem stride (elems)
__global__ void __launch_bounds__(256)
mix_s_hmma_kernel(const float* __restrict__ x, const float* __restrict__ attS,
                  float* __restrict__ ycat) {
    __shared__ __align__(16) __nv_bfloat16 sAh[80 * MXA], sAl[80 * MXA];
    __shared__ __align__(16) __nv_bfloat16 sBh[32 * MXB], sBl[32 * MXB];
    int n = blockIdx.x, ch = blockIdx.y;
    int tid = threadIdx.x, warp = tid >> 5, lane = tid & 31;
    int g = lane >> 2, tig = lane & 3;

    for (int i = tid; i < 1600; i += 256) {
        ((uint32_t*)sAh)[i] = 0u;
        ((uint32_t*)sAl)[i] = 0u;
    }
    for (int i = tid; i < 7 * 68; i += 256) {
        int u = 25 + i / 68, c2 = (i % 68);
        ((uint32_t*)(sBh + u * MXB))[c2] = 0u;
        ((uint32_t*)(sBl + u * MXB))[c2] = 0u;
    }
    __syncthreads();

    for (int e = tid; e < 1875; e += 256) {
        float a = attS[(size_t)n * 1875 + e];
        int u = e / 75, m = e - u * 75;
        float h = __bfloat162float(__float2bfloat16_rn(a));
        sAh[m * MXA + u] = __float2bfloat16_rn(h);
        sAl[m * MXA + u] = __float2bfloat16_rn(a - h);
    }
    for (int idx = tid; idx < 800; idx += 256) {
        int u = idx >> 5, c4 = (idx & 31) << 2;
        float4 v = *(const float4*)&x[((size_t)(n * 25 + u)) * 4096 + (ch << 7) + c4];
        float h0 = __bfloat162float(__float2bfloat16_rn(v.x));
        float h1 = __bfloat162float(__float2bfloat16_rn(v.y));
        float h2 = __bfloat162float(__float2bfloat16_rn(v.z));
        float h3 = __bfloat162float(__float2bfloat16_rn(v.w));
        *(uint2*)&sBh[u * MXB + c4] = make_uint2(pkbf(h0, h1), pkbf(h2, h3));
        *(uint2*)&sBl[u * MXB + c4] =
            make_uint2(pkbf(v.x - h0, v.y - h1), pkbf(v.z - h2, v.w - h3));
    }
    __syncthreads();

    uint32_t a_base = smem_u32(sAh) + (uint32_t)((lane & 15) * (MXA * 2) +
                                                 ((lane >> 4) << 4));
    uint32_t al_base = smem_u32(sAl) + (uint32_t)((lane & 15) * (MXA * 2) +
                                                  ((lane >> 4) << 4));
    uint32_t b_off = (uint32_t)(((lane & 7) + (lane & 8)) * (MXB * 2) +
                                (((warp << 4) + ((lane >> 4) << 3)) << 1));
    uint32_t bh_addr = smem_u32(sBh) + b_off;
    uint32_t bl_addr = smem_u32(sBl) + b_off;

    float acc[5][2][4];
#pragma unroll
    for (int mt = 0; mt < 5; mt++)
#pragma unroll
        for (int q = 0; q < 2; q++)
#pragma unroll
            for (int j = 0; j < 4; j++) acc[mt][q][j] = 0.f;

#pragma unroll
    for (int ks = 0; ks < 2; ks++) {
        uint32_t bh[4], bl[4];
        uint32_t ko = (uint32_t)(ks * 16 * (MXB * 2));
        ldm4t(bh, bh_addr + ko);
        ldm4t(bl, bl_addr + ko);
#pragma unroll
        for (int mt = 0; mt < 5; mt++) {
            uint32_t ah[4], al[4];
            uint32_t ao = (uint32_t)(mt * 16 * (MXA * 2) + ks * 32);
            ldm4(ah, a_base + ao);
            ldm4(al, al_base + ao);
            mma16816(acc[mt][0], ah, bh[0], bh[1]);
            mma16816(acc[mt][0], ah, bl[0], bl[1]);
            mma16816(acc[mt][0], al, bh[0], bh[1]);
            mma16816(acc[mt][1], ah, bh[2], bh[3]);
            mma16816(acc[mt][1], ah, bl[2], bl[3]);
            mma16816(acc[mt][1], al, bh[2], bh[3]);
        }
    }

#pragma unroll
    for (int mt = 0; mt < 5; mt++) {
#pragma unroll
        for (int nt8 = 0; nt8 < 2; nt8++) {
            int col = (warp << 4) + (nt8 << 3) + (tig << 1);
            int tc = (ch << 7) + col;
            int t = tc >> 6, c = tc & 63;
#pragma unroll
            for (int h = 0; h < 2; h++) {
                int m = (mt << 4) + g + (h << 3);
                if (m < 75) {
                    int v = m / 3, s = m - 3 * v;
                    size_t oa = (((size_t)(n * 25 + v)) * 64 + t) * 192 + s * 64 + c;
                    *(float2*)&ycat[oa] =
                        make_float2(acc[mt][nt8][h << 1], acc[mt][nt8][(h << 1) + 1]);
                }
            }
        }
    }
}

// ---------------------------------------------------------------------------
// LayerNorm over (V,C) per (n,t) + residual + GELU; padded=1 -> conv z buffer
// ---------------------------------------------------------------------------
__global__ void ln_t_kernel(const float* __restrict__ in, const float* __restrict__ resid,
                            const float* __restrict__ gg, const float* __restrict__ bb,
                            float* __restrict__ out, int padded) {
    int grp = blockIdx.x;   // n*64+t
    int tid = threadIdx.x;
    const float* ip = in + (size_t)grp * 1600;
    float vals[7];
    float s = 0.f;
#pragma unroll
    for (int r = 0; r < 7; r++) {
        int i = tid + (r << 8);
        vals[r] = (i < 1600) ? ip[i] : 0.f;
        s += vals[r];
    }
    __shared__ float red[256];
    red[tid] = s; __syncthreads();
    for (int o = 128; o; o >>= 1) { if (tid < o) red[tid] += red[tid + o]; __syncthreads(); }
    float mean = red[0] * (1.f / 1600.f);
    float sq = 0.f;
#pragma unroll
    for (int r = 0; r < 7; r++) {
        int i = tid + (r << 8);
        float d = (i < 1600) ? (vals[r] - mean) : 0.f;
        sq += d * d;
    }
    __syncthreads();
    red[tid] = sq; __syncthreads();
    for (int o = 128; o; o >>= 1) { if (tid < o) red[tid] += red[tid + o]; __syncthreads(); }
    float inv = rsqrtf(red[0] * (1.f / 1600.f) + 1e-5f);
    const float* rp = resid + (size_t)grp * 1600;
    int n = grp >> 6, t = grp & 63;
    size_t obase = padded ? ((size_t)(n * TPAD + 3 + t) * 1600) : ((size_t)grp * 1600);
#pragma unroll
    for (int r = 0; r < 7; r++) {
        int i = tid + (r << 8);
        if (i < 1600) {
            float y = (vals[r] - mean) * inv * gg[i] + bb[i];
            out[obase + i] = gelu_f(rp[i] + y);
        }
    }
}

// ---------------------------------------------------------------------------
// Temporal attention via HMMA; qkt pre-split bf16 planes (no conversion ALU).
// ---------------------------------------------------------------------------
#define BST 88
__global__ void __launch_bounds__(256)
att_t_hmma_kernel(const __nv_bfloat16* __restrict__ qkt, const float* __restrict__ af,
                  const float* __restrict__ ab, float* __restrict__ attO) {
    __shared__ __align__(16) __nv_bfloat16 sQh[64 * BST], sQl[64 * BST];
    __shared__ __align__(16) __nv_bfloat16 sKh[64 * BST], sKl[64 * BST];
    int n = blockIdx.x, combo = blockIdx.y;
    int dir = combo >> 1, s = combo & 1;
    int jq = (dir * 2 + s) << 4, jk = (4 + dir * 2 + s) << 4;
    int tid = threadIdx.x, warp = tid >> 5, lane = tid & 31;
    int g = lane >> 2, tig = lane & 3;
    int mtile = warp & 3, nbase = (warp >> 2) << 5;
    float acc[4][4];
#pragma unroll
    for (int i = 0; i < 4; i++)
#pragma unroll
        for (int j = 0; j < 4; j++) acc[i][j] = 0.f;

    const __nv_bfloat16* bh_g = qkt + (size_t)n * 204800;
    const __nv_bfloat16* bl_g = bh_g + (size_t)QTN;
    uint32_t q_off = (uint32_t)((((mtile << 4) + (lane & 15)) * (BST * 2)) +
                                ((lane >> 4) << 4));
    uint32_t k_off = (uint32_t)(((nbase + (lane & 15)) * (BST * 2)) +
                                ((lane >> 4) << 4));
    uint32_t qh_a = smem_u32(sQh) + q_off, ql_a = smem_u32(sQl) + q_off;
    uint32_t kh_a = smem_u32(sKh) + k_off, kl_a = smem_u32(sKl) + k_off;

    for (int vc = 0; vc < 5; vc++) {
        for (int idx = tid; idx < 2560; idx += 256) {
            int half = idx >= 1280;
            int id = idx - (half ? 1280 : 0);
            int t = id / 20, cq = id - t * 20;
            int vi = cq >> 2, icq = (cq & 3) << 2;
            int e = (t * 25 + vc * 5 + vi) * 128 + (half ? jk : jq) + icq;
            uint2 vh = *(const uint2*)(bh_g + e);
            uint2 vl = *(const uint2*)(bl_g + e);
            int so = t * BST + (vi << 4) + icq;
            if (half) {
                *(uint2*)&sKh[so] = vh;
                *(uint2*)&sKl[so] = vl;
            } else {
                *(uint2*)&sQh[so] = vh;
                *(uint2*)&sQl[so] = vl;
            }
        }
        __syncthreads();
#pragma unroll
        for (int ks = 0; ks < 5; ks++) {
            uint32_t qh[4], ql[4];
            ldm4(qh, qh_a + ks * 32);
            ldm4(ql, ql_a + ks * 32);
            uint32_t kh[4], kl[4];
            ldm4(kh, kh_a + ks * 32);
            ldm4(kl, kl_a + ks * 32);
            mma16816(acc[0], qh, kh[0], kh[2]);
            mma16816(acc[0], qh, kl[0], kl[2]);
            mma16816(acc[0], ql, kh[0], kh[2]);
            mma16816(acc[1], qh, kh[1], kh[3]);
            mma16816(acc[1], qh, kl[1], kl[3]);
            mma16816(acc[1], ql, kh[1], kh[3]);
            uint32_t kh2[4], kl2[4];
            ldm4(kh2, kh_a + 16 * (BST * 2) + ks * 32);
            ldm4(kl2, kl_a + 16 * (BST * 2) + ks * 32);
            mma16816(acc[2], qh, kh2[0], kh2[2]);
            mma16816(acc[2], qh, kl2[0], kl2[2]);
            mma16816(acc[2], ql, kh2[0], kh2[2]);
            mma16816(acc[3], qh, kh2[1], kh2[3]);
            mma16816(acc[3], qh, kl2[1], kl2[3]);
            mma16816(acc[3], ql, kh2[1], kh2[3]);
        }
        __syncthreads();
    }
    float alpha = dir ? ab[s] : af[s];
    size_t ob = ((size_t)n * 4 + combo) << 12;
    int t0 = (mtile << 4) + g;
#pragma unroll
    for (int nt = 0; nt < 4; nt++) {
        int q = nbase + ((nt & 1) << 3) + ((nt >> 1) << 4) + (tig << 1);
        float v00 = tanhf(acc[nt][0] * (1.f / 400.f)) * alpha;
        float v01 = tanhf(acc[nt][1] * (1.f / 400.f)) * alpha;
        float v10 = tanhf(acc[nt][2] * (1.f / 400.f)) * alpha;
        float v11 = tanhf(acc[nt][3] * (1.f / 400.f)) * alpha;
        int t1 = t0 + 8;
        bool k00 = dir ? (q >= t0) : (t0 >= q);
        bool k01 = dir ? (q + 1 >= t0) : (t0 >= q + 1);
        bool k10 = dir ? (q >= t1) : (t1 >= q);
        bool k11 = dir ? (q + 1 >= t1) : (t1 >= q + 1);
        *(float2*)&attO[ob + (t0 << 6) + q] =
            make_float2(k00 ? v00 : 0.f, k01 ? v01 : 0.f);
        *(float2*)&attO[ob + (t1 << 6) + q] =
            make_float2(k10 ? v10 : 0.f, k11 ? v11 : 0.f);
    }
}

// ---------------------------------------------------------------------------
// mix_t via HMMA (round-8 proven)
// ---------------------------------------------------------------------------
__global__ void __launch_bounds__(256)
mix_t_hmma_kernel(const float* __restrict__ attT_g, const float* __restrict__ yt,
                  float* __restrict__ zcat) {
    __shared__ __align__(16) __nv_bfloat16 sAh[64 * AST], sAl[64 * AST];
    __shared__ __align__(16) __nv_bfloat16 sBh[64 * AST], sBl[64 * AST];
    int n = blockIdx.x, combo = blockIdx.y, vg = blockIdx.z;
    int tid = threadIdx.x, warp = tid >> 5, lane = tid & 31;
    int g = lane >> 2, tig = lane & 3;
    int mtile = warp & 3, nbase = (warp >> 2) << 5;

    const float* ap = attT_g + (((size_t)n * 4 + combo) << 12);
    for (int i = tid; i < 1024; i += 256) {
        int t = i >> 4, q4 = (i & 15) << 2;
        float4 v = *(const float4*)&ap[(t << 6) + q4];
        float h0 = __bfloat162float(__float2bfloat16_rn(v.x));
        float h1 = __bfloat162float(__float2bfloat16_rn(v.y));
        float h2 = __bfloat162float(__float2bfloat16_rn(v.z));
        float h3 = __bfloat162float(__float2bfloat16_rn(v.w));
        sAh[(q4 + 0) * AST + t] = __float2bfloat16_rn(h0);
        sAh[(q4 + 1) * AST + t] = __float2bfloat16_rn(h1);
        sAh[(q4 + 2) * AST + t] = __float2bfloat16_rn(h2);
        sAh[(q4 + 3) * AST + t] = __float2bfloat16_rn(h3);
        sAl[(q4 + 0) * AST + t] = __float2bfloat16_rn(v.x - h0);
        sAl[(q4 + 1) * AST + t] = __float2bfloat16_rn(v.y - h1);
        sAl[(q4 + 2) * AST + t] = __float2bfloat16_rn(v.z - h2);
        sAl[(q4 + 3) * AST + t] = __float2bfloat16_rn(v.w - h3);
    }

    uint32_t a_off = (uint32_t)(((mtile << 4) + (lane & 15)) * (AST * 2) +
                                ((lane >> 4) << 4));
    uint32_t ah_addr = smem_u32(sAh) + a_off;
    uint32_t al_addr = smem_u32(sAl) + a_off;
    uint32_t b_off = (uint32_t)(((lane & 7) + (lane & 8)) * (AST * 2) +
                                ((nbase + ((lane >> 4) << 3)) << 1));
    uint32_t bh_addr = smem_u32(sBh) + b_off;
    uint32_t bl_addr = smem_u32(sBl) + b_off;

    for (int vi = 0; vi < 5; vi++) {
        int v = vg * 5 + vi;
        for (int i = tid; i < 1024; i += 256) {
            int t = i >> 4, c4 = (i & 15) << 2;
            float4 w = *(const float4*)&yt[((size_t)(n * 64 + t) * 25 + v) * 64 + c4];
            float h0 = __bfloat162float(__float2bfloat16_rn(w.x));
            float h1 = __bfloat162float(__float2bfloat16_rn(w.y));
            float h2 = __bfloat162float(__float2bfloat16_rn(w.z));
            float h3 = __bfloat162float(__float2bfloat16_rn(w.w));
            *(uint2*)&sBh[t * AST + c4] =
                make_uint2(pkbf(h0, h1), pkbf(h2, h3));
            *(uint2*)&sBl[t * AST + c4] =
                make_uint2(pkbf(w.x - h0, w.y - h1), pkbf(w.z - h2, w.w - h3));
        }
        __syncthreads();
        float acc[4][4];
#pragma unroll
        for (int i = 0; i < 4; i++)
#pragma unroll
            for (int j = 0; j < 4; j++) acc[i][j] = 0.f;
#pragma unroll
        for (int ks = 0; ks < 4; ks++) {
            uint32_t a_h[4], a_l[4];
            ldm4(a_h, ah_addr + ks * 32);
            ldm4(a_l, al_addr + ks * 32);
#pragma unroll
            for (int nt2 = 0; nt2 < 2; nt2++) {
                uint32_t bh[4], bl[4];
                uint32_t ko = (uint32_t)(ks * 16 * (AST * 2) + nt2 * 32);
                ldm4t(bh, bh_addr + ko);
                ldm4t(bl, bl_addr + ko);
                mma16816(acc[nt2 * 2 + 0], a_h, bh[0], bh[1]);
                mma16816(acc[nt2 * 2 + 0], a_h, bl[0], bl[1]);
                mma16816(acc[nt2 * 2 + 0], a_l, bh[0], bh[1]);
                mma16816(acc[nt2 * 2 + 1], a_h, bh[2], bh[3]);
                mma16816(acc[nt2 * 2 + 1], a_h, bl[2], bl[3]);
                mma16816(acc[nt2 * 2 + 1], a_l, bh[2], bh[3]);
            }
        }
        int q0 = (mtile << 4) + g;
        size_t ob0 = (((size_t)(n * 64 + q0) * 25 + v) << 8) + (combo << 6);
        size_t ob1 = (((size_t)(n * 64 + q0 + 8) * 25 + v) << 8) + (combo << 6);
#pragma unroll
        for (int nt = 0; nt < 4; nt++) {
            int col = nbase + (nt << 3) + (tig << 1);
            *(float2*)&zcat[ob0 + col] = make_float2(acc[nt][0], acc[nt][1]);
            *(float2*)&zcat[ob1 + col] = make_float2(acc[nt][2], acc[nt][3]);
        }
        __syncthreads();
    }
}

// ---------------------------------------------------------------------------
// BN apply + residual + GELU + final transpose to output (n,v,t,c)
// ---------------------------------------------------------------------------
__global__ void bn_final_kernel(const float* __restrict__ z, const float* __restrict__ z1,
                                const float* __restrict__ bg, const float* __restrict__ bb,
                                float* __restrict__ out) {
    size_t e = (size_t)blockIdx.x * 256 + threadIdx.x;
    int c = (int)(e & 63);
    size_t r = e >> 6;
    int t = (int)(r & 63);
    size_t r2 = r >> 6;
    int v = (int)(r2 % 25);
    int n = (int)(r2 / 25);
    size_t paddr = ((size_t)(n * TPAD + 3 + t) * 25 + v) * 64 + c;
    float mean = g_bnstats[c] * (1.f / 204800.f);
    float var = g_bnstats[64 + c] * (1.f / 204800.f) - mean * mean;
    float z1n = (z1[paddr] - mean) * rsqrtf(var + 1e-5f) * bg[c] + bb[c];
    out[e] = gelu_f(z[paddr] + z1n);
}

// ---------------------------------------------------------------------------
// Host launcher
// ---------------------------------------------------------------------------
extern "C" void kernel_launch(void* const* d_in, const int* in_sizes, int n_in,
                              void* d_out, int out_size) {
    const float* x          = (const float*)d_in[0];
    const float* w_in_s     = (const float*)d_in[1];
    const float* b_in_s     = (const float*)d_in[2];
    const float* alphas     = (const float*)d_in[3];
    const float* att0s      = (const float*)d_in[4];
    const float* w_out_s    = (const float*)d_in[5];
    const float* b_out_s    = (const float*)d_in[6];
    const float* ln_out_s_g = (const float*)d_in[7];
    const float* ln_out_s_b = (const float*)d_in[8];
    const float* w_ff_s     = (const float*)d_in[9];
    const float* b_ff_s     = (const float*)d_in[10];
    const float* ln_ff_s_g  = (const float*)d_in[11];
    const float* ln_ff_s_b  = (const float*)d_in[12];
    const float* w_in_t     = (const float*)d_in[13];
    const float* b_in_t     = (const float*)d_in[14];
    const float* alphat_f   = (const float*)d_in[15];
    const float* alphat_b   = (const float*)d_in[16];
    const float* w_out_t    = (const float*)d_in[17];
    const float* b_out_t    = (const float*)d_in[18];
    const float* ln_out_t_g = (const float*)d_in[19];
    const float* ln_out_t_b = (const float*)d_in[20];
    const float* w_ff_t     = (const float*)d_in[21];
    const float* b_ff_t     = (const float*)d_in[22];
    const float* ln_ff_t_g  = (const float*)d_in[23];
    const float* ln_ff_t_b  = (const float*)d_in[24];
    const float* conv_w     = (const float*)d_in[25];
    const float* conv_b     = (const float*)d_in[26];
    const float* bn_g       = (const float*)d_in[27];
    const float* bn_b       = (const float*)d_in[28];
    float* out = (float*)d_out;

    float *bufA, *bufB, *bufC, *bufD, *bufE, *bufF, *attS, *attT, *bis, *bit;
    cudaGetSymbolAddress((void**)&bufA, g_bufA);
    cudaGetSymbolAddress((void**)&bufB, g_bufB);
    cudaGetSymbolAddress((void**)&bufC, g_bufC);
    cudaGetSymbolAddress((void**)&bufD, g_bufD);
    cudaGetSymbolAddress((void**)&bufE, g_bufE);
    cudaGetSymbolAddress((void**)&bufF, g_bufF);
    cudaGetSymbolAddress((void**)&attS, g_attS);
    cudaGetSymbolAddress((void**)&attT, g_attT);
    cudaGetSymbolAddress((void**)&bis, g_bis);
    cudaGetSymbolAddress((void**)&bit, g_bit);
    uint4 *Fqk, *Fouts, *Fffs, *Fint, *Foutt, *Ffft, *Fconv;
    cudaGetSymbolAddress((void**)&Fqk, g_Fqk);
    cudaGetSymbolAddress((void**)&Fouts, g_Fouts);
    cudaGetSymbolAddress((void**)&Fffs, g_Fffs);
    cudaGetSymbolAddress((void**)&Fint, g_Fint);
    cudaGetSymbolAddress((void**)&Foutt, g_Foutt);
    cudaGetSymbolAddress((void**)&Ffft, g_Ffft);
    cudaGetSymbolAddress((void**)&Fconv, g_Fconv);
    float* zbase = bufF + GUARD;
    __nv_bfloat16* bf16B = (__nv_bfloat16*)bufB;

    cudaFuncSetAttribute(att_s_hmma_kernel,
                         cudaFuncAttributeMaxDynamicSharedMemorySize, 51200);

    prep_kernel<<<28, 256>>>(w_in_s, b_in_s, w_out_s, w_ff_s, w_in_t, b_in_t,
                             w_out_t, w_ff_t, conv_w);
    zero_pads_kernel<<<4800, 256>>>(zbase);

    // ---- spatial stage ----
    mma_gemm_qk_kernel<<<1600, 256>>>(x, Fqk, bis, bf16B, 64);
    att_s_hmma_kernel<<<dim3(NN, 3, 4), 256, 51200>>>(bf16B, bufC);
    att_s2_kernel<<<938, 256>>>(bufC, alphas, att0s, attS);
    mix_s_hmma_kernel<<<dim3(NN, 32), 256>>>(x, attS, bufA);
    mma_gemm_lns_kernel<0><<<1600, 256>>>(bufA, Fouts, b_out_s, x,
                                          ln_out_s_g, ln_out_s_b, bufD, 192);
    mma_gemm_lns_kernel<1><<<1600, 256>>>(bufD, Fffs, b_ff_s, x,
                                          ln_ff_s_g, ln_ff_s_b, bufE, 64);

    // ---- temporal stage ----
    mma_gemm_int_kernel<<<1600, 256>>>(bufE, Fint, bit, bf16B, 64);
    att_t_hmma_kernel<<<dim3(NN, 4), 256>>>(bf16B, alphat_f, alphat_b, attT);
    mix_t_hmma_kernel<<<dim3(NN, 4, 5), 256>>>(attT, bufE, bufA);
    mma_gemm_kernel<64><<<1600, 256>>>(bufA, Foutt, b_out_t, bufC, 256);
    ln_t_kernel<<<8192, 256>>>(bufC, bufE, ln_out_t_g, ln_out_t_b, bufD, 0);
    mma_gemm_kernel<64><<<1600, 256>>>(bufD, Ffft, b_ff_t, bufC, 64);
    ln_t_kernel<<<8192, 256>>>(bufC, bufE, ln_ff_t_g, ln_ff_t_b, zbase, 1);

    // ---- conv + batchnorm + output ----
    mma_gemm_conv_kernel<<<1750, 256>>>(zbase, Fconv, conv_b, bufD, 448);
    bn_final_kernel<<<51200, 256>>>(zbase, bufD, bn_g, bn_b, out);
}

// round 15
// speedup vs baseline: 1.0378x; 1.0378x over previous
#include <cuda_runtime.h>
#include <cuda_bf16.h>
#include <math.h>
#include <stdint.h>

// ---------------------------------------------------------------------------
// Problem constants: x (N=128, V=25, T=64, C=64), IC=16, S=3, TS=2
// ---------------------------------------------------------------------------
#define NN 128
#define NVT 204800          // N*V*T == N*T*V
#define TPAD 70             // T + 6 (conv halo)
#define MPAD 224000         // N*TPAD*V rows for padded z
#define GUARD 4800          // 3*V*C guard floats (75 rows) before/after padded z
#define QKOFF 9830400       // 128*3*25600 floats (Q region size; K follows)

// ---------------------------------------------------------------------------
// Scratch (static device globals; no runtime allocation allowed)
// ---------------------------------------------------------------------------
__device__ float g_bufA[(size_t)NVT * 256];                 // ycat / zcat
__device__ float g_bufB[(size_t)NVT * 128];                 // Q/K (spatial) / qkt
__device__ float g_bufC[(size_t)NVT * 64];                  // gemm outputs / att_s partials
__device__ float g_bufD[(size_t)NVT * 64];                  // y1 / z-mid / conv out
__device__ float g_bufE[(size_t)NVT * 64];                  // y transposed (n,t,v,c)
__device__ float g_bufF[GUARD + (size_t)MPAD * 64 + GUARD]; // padded z + guards
__device__ float g_attS[(size_t)NN * 625 * 3];
__device__ float g_attT[(size_t)NN * 4 * 64 * 64];
__device__ float g_bis[96];                                 // b_in_s col-permuted
__device__ float g_bit[128];                                // b_in_t col-permuted
__device__ float g_bnstats[128];                            // sum[64], sumsq[64]

// Pre-packed mma.sync B fragments: per (k16-chunk, ntile, lane) a uint4 =
// {b_hi_reg0, b_hi_reg1, b_lo_reg0, b_lo_reg1}
__device__ uint4 g_Fqk[4 * 12 * 32];      // K=64,  Nc=96
__device__ uint4 g_Fouts[12 * 8 * 32];    // K=192, Nc=64
__device__ uint4 g_Fffs[4 * 8 * 32];      // K=64,  Nc=64
__device__ uint4 g_Fint[4 * 16 * 32];     // K=64,  Nc=128 (col-permuted j*16+ic)
__device__ uint4 g_Foutt[16 * 8 * 32];    // K=256, Nc=64
__device__ uint4 g_Ffft[4 * 8 * 32];      // K=64,  Nc=64
__device__ uint4 g_Fconv[28 * 8 * 32];    // K=448, Nc=64

__device__ __forceinline__ float gelu_f(float x) {
    return 0.5f * x * (1.f + erff(x * 0.70710678118654752f));
}

__device__ __forceinline__ uint32_t smem_u32(const void* p) {
    uint32_t a;
    asm("{ .reg .u64 t; cvta.to.shared.u64 t, %1; cvt.u32.u64 %0, t; }" : "=r"(a) : "l"(p));
    return a;
}
__device__ __forceinline__ void ldm4(uint32_t* r, uint32_t addr) {
    asm volatile("ldmatrix.sync.aligned.m8n8.x4.shared.b16 {%0,%1,%2,%3}, [%4];"
                 : "=r"(r[0]), "=r"(r[1]), "=r"(r[2]), "=r"(r[3]) : "r"(addr));
}
__device__ __forceinline__ void ldm4t(uint32_t* r, uint32_t addr) {
    asm volatile("ldmatrix.sync.aligned.m8n8.x4.trans.shared.b16 {%0,%1,%2,%3}, [%4];"
                 : "=r"(r[0]), "=r"(r[1]), "=r"(r[2]), "=r"(r[3]) : "r"(addr));
}
__device__ __forceinline__ void mma16816(float* c, const uint32_t* a,
                                         uint32_t b0, uint32_t b1) {
    asm volatile(
        "mma.sync.aligned.m16n8k16.row.col.f32.bf16.bf16.f32 "
        "{%0,%1,%2,%3}, {%4,%5,%6,%7}, {%8,%9}, {%0,%1,%2,%3};"
        : "+f"(c[0]), "+f"(c[1]), "+f"(c[2]), "+f"(c[3])
        : "r"(a[0]), "r"(a[1]), "r"(a[2]), "r"(a[3]), "r"(b0), "r"(b1));
}
__device__ __forceinline__ uint32_t pkbf(float a, float b) {
    __nv_bfloat162 t = __floats2bfloat162_rn(a, b);
    return *(uint32_t*)&t;
}

// ---------------------------------------------------------------------------
// Prep: build B fragments (hi/lo split, permuted), permuted biases, zero bn
// ---------------------------------------------------------------------------
__device__ __forceinline__ void mk_frag(uint4* dst, int i, int NT,
                                        float w00, float w01, float w10, float w11) {
    float h00 = __bfloat162float(__float2bfloat16_rn(w00));
    float h01 = __bfloat162float(__float2bfloat16_rn(w01));
    float h10 = __bfloat162float(__float2bfloat16_rn(w10));
    float h11 = __bfloat162float(__float2bfloat16_rn(w11));
    dst[i] = make_uint4(pkbf(h00, h01), pkbf(h10, h11),
                        pkbf(w00 - h00, w01 - h01), pkbf(w10 - h10, w11 - h11));
}
#define FRAG_IDX(NT) \
    int lane = i & 31, nt = (i >> 5) % (NT), kc = (i >> 5) / (NT); \
    int g = lane >> 2, tig = lane & 3; \
    int n = nt * 8 + g; int k0 = kc * 16 + 2 * tig; (void)kc;

__global__ void prep_kernel(const float* __restrict__ wqk, const float* __restrict__ bqk,
                            const float* __restrict__ ws, const float* __restrict__ wffs,
                            const float* __restrict__ wint, const float* __restrict__ bint,
                            const float* __restrict__ wt,
                            const float* __restrict__ wfft, const float* __restrict__ cw) {
    int i = blockIdx.x * 256 + threadIdx.x;
    if (i < 4 * 12 * 32) {     // qk: Nc=96, K=64
        FRAG_IDX(12)
        int cc = (n < 48) ? n : n - 48;
        int s = cc >> 4, ic = cc & 15;
        int old = ic * 6 + s + ((n < 48) ? 0 : 3);
        mk_frag(g_Fqk, i, 12,
                wqk[k0 * 96 + old], wqk[(k0 + 1) * 96 + old],
                wqk[(k0 + 8) * 96 + old], wqk[(k0 + 9) * 96 + old]);
    }
    if (i < 96) {
        int cc = (i < 48) ? i : i - 48;
        int s = cc >> 4, ic = cc & 15;
        g_bis[i] = bqk[ic * 6 + s + ((i < 48) ? 0 : 3)];
    }
    if (i < 128) {             // in_t bias: new col n = j*16+ic -> old ic*8+j
        int j = i >> 4, ic = i & 15;
        g_bit[i] = bint[ic * 8 + j];
    }
    if (i < 12 * 8 * 32) {     // out_s: k = s*64+c -> orig row c*3+s, Nc=64
        FRAG_IDX(8)
        float w[4];
#pragma unroll
        for (int e = 0; e < 4; e++) {
            int k = k0 + (e >> 1) * 8 + (e & 1);
            int s = k >> 6, c = k & 63;
            w[e] = ws[(c * 3 + s) * 64 + n];
        }
        mk_frag(g_Fouts, i, 8, w[0], w[1], w[2], w[3]);
    }
    if (i < 4 * 8 * 32) {      // ff_s / ff_t: [K=64][64]
        FRAG_IDX(8)
        mk_frag(g_Fffs, i, 8, wffs[k0 * 64 + n], wffs[(k0 + 1) * 64 + n],
                wffs[(k0 + 8) * 64 + n], wffs[(k0 + 9) * 64 + n]);
        mk_frag(g_Ffft, i, 8, wfft[k0 * 64 + n], wfft[(k0 + 1) * 64 + n],
                wfft[(k0 + 8) * 64 + n], wfft[(k0 + 9) * 64 + n]);
    }
    if (i < 4 * 16 * 32) {     // in_t: [K=64][128], cols permuted n=j*16+ic
        FRAG_IDX(16)
        int j = n >> 4, ic = n & 15;
        int old = ic * 8 + j;
        mk_frag(g_Fint, i, 16, wint[k0 * 128 + old], wint[(k0 + 1) * 128 + old],
                wint[(k0 + 8) * 128 + old], wint[(k0 + 9) * 128 + old]);
    }
    if (i < 16 * 8 * 32) {     // out_t: k = dir*128+s*64+c -> orig dir*128+c*2+s
        FRAG_IDX(8)
        float w[4];
#pragma unroll
        for (int e = 0; e < 4; e++) {
            int k = k0 + (e >> 1) * 8 + (e & 1);
            int dir = k >> 7, s = (k >> 6) & 1, c = k & 63;
            w[e] = wt[(dir * 128 + c * 2 + s) * 64 + n];
        }
        mk_frag(g_Foutt, i, 8, w[0], w[1], w[2], w[3]);
    }
    if (i < 28 * 8 * 32) {     // conv: k = dt*64+ci, orig (co,ci,dt)
        FRAG_IDX(8)
        float w[4];
#pragma unroll
        for (int e = 0; e < 4; e++) {
            int k = k0 + (e >> 1) * 8 + (e & 1);
            int dt = k >> 6, ci = k & 63;
            w[e] = cw[(n * 64 + ci) * 7 + dt];
        }
        mk_frag(g_Fconv, i, 8, w[0], w[1], w[2], w[3]);
    }
    if (i < 128) g_bnstats[i] = 0.f;
}

__global__ void zero_pads_kernel(float* __restrict__ zbase) {
    int e = blockIdx.x * 256 + threadIdx.x;   // over 128*6*1600
    int n = e / 9600, r = e - n * 9600;
    int k = r / 1600, rem = r - k * 1600;
    int tp = (k < 3) ? k : (k + 64);          // pad rows {0,1,2,67,68,69}
    zbase[((size_t)(n * TPAD + tp)) * 1600 + rem] = 0.f;
}

// ---------------------------------------------------------------------------
// Shared GEMM mainloop macro (MF=1, round-8 proven config): fp32 A -> bf16
// hi/lo smem, 3xHMMA per k16. 256 thr, 128-row M tile. B fragments in gmem.
// ---------------------------------------------------------------------------
#define AST 72   // smem bf16 row stride (144 B) -> conflict-free ldmatrix

#define GEMM_MAINLOOP(NT_, CONV_)                                                  \
    int tid = threadIdx.x, warp = tid >> 5, lane = tid & 31;                       \
    int g = lane >> 2, tig = lane & 3;                                             \
    int bm = blockIdx.x << 7;                                                      \
    int lda = (CONV_) ? 64 : K;                                                    \
    float acc[NT_][4];                                                             \
    _Pragma("unroll") for (int i_ = 0; i_ < NT_; i_++)                             \
        _Pragma("unroll") for (int j_ = 0; j_ < 4; j_++) acc[i_][j_] = 0.f;        \
    uint32_t arow_off =                                                            \
        (uint32_t)(((warp << 4) + (lane & 15)) * (AST * 2) + ((lane >> 4) << 4));  \
    uint32_t ah_addr = smem_u32(sAh) + arow_off;                                   \
    uint32_t al_addr = smem_u32(sAl) + arow_off;                                   \
    int crow = tid >> 1, ccol = (tid & 1) << 5;                                    \
    char* sh = (char*)sAh + crow * (AST * 2) + ccol * 2;                           \
    char* sl = (char*)sAl + crow * (AST * 2) + ccol * 2;                           \
    int chunks = K >> 6;                                                           \
    for (int ch = 0; ch < chunks; ch++) {                                          \
        long rshift = (CONV_) ? (long)(ch - 3) * 25 : 0;                           \
        int col0 = (CONV_) ? 0 : (ch << 6);                                        \
        const float* ap = A + ((long)bm + rshift + crow) * lda + col0 + ccol;      \
        _Pragma("unroll") for (int j = 0; j < 8; j++) {                            \
            float4 v = *(const float4*)(ap + (j << 2));                            \
            float hx = __bfloat162float(__float2bfloat16_rn(v.x));                 \
            float hy = __bfloat162float(__float2bfloat16_rn(v.y));                 \
            float hz = __bfloat162float(__float2bfloat16_rn(v.z));                 \
            float hw = __bfloat162float(__float2bfloat16_rn(v.w));                 \
            *(uint2*)(sh + (j << 3)) = make_uint2(pkbf(hx, hy), pkbf(hz, hw));     \
            *(uint2*)(sl + (j << 3)) =                                             \
                make_uint2(pkbf(v.x - hx, v.y - hy), pkbf(v.z - hz, v.w - hw));    \
        }                                                                          \
        __syncthreads();                                                           \
        _Pragma("unroll") for (int ks = 0; ks < 4; ks++) {                         \
            uint32_t a_h[4], a_l[4];                                               \
            ldm4(a_h, ah_addr + ks * 32);                                          \
            ldm4(a_l, al_addr + ks * 32);                                          \
            const uint4* Fp = F + ((size_t)((ch << 2) + ks) * NT_) * 32 + lane;    \
            _Pragma("unroll") for (int nt = 0; nt < NT_; nt++) {                   \
                uint4 bf = Fp[nt * 32];                                            \
                mma16816(acc[nt], a_h, bf.x, bf.y);                                \
                mma16816(acc[nt], a_h, bf.z, bf.w);                                \
                mma16816(acc[nt], a_l, bf.x, bf.y);                                \
            }                                                                      \
        }                                                                          \
        __syncthreads();                                                           \
    }

// ---------------------------------------------------------------------------
// Plain GEMM (in_t Nc=128, out_t/ff_t Nc=64)
// ---------------------------------------------------------------------------
template <int NC>
__global__ void __launch_bounds__(256)
mma_gemm_kernel(const float* __restrict__ A, const uint4* __restrict__ F,
                const float* __restrict__ bias, float* __restrict__ C, int K) {
    __shared__ __align__(16) __nv_bfloat16 sAh[128 * AST];
    __shared__ __align__(16) __nv_bfloat16 sAl[128 * AST];
    constexpr int NT = NC / 8;
    GEMM_MAINLOOP(NT, 0)
    size_t r0 = (size_t)bm + (warp << 4) + g;
#pragma unroll
    for (int nt = 0; nt < NT; nt++) {
        int col = (nt << 3) + (tig << 1);
        float bx = bias[col], by = bias[col + 1];
        *(float2*)&C[r0 * NC + col] = make_float2(acc[nt][0] + bx, acc[nt][1] + by);
        *(float2*)&C[(r0 + 8) * NC + col] = make_float2(acc[nt][2] + bx, acc[nt][3] + by);
    }
}

// ---------------------------------------------------------------------------
// qk GEMM (Nc=96) with att-friendly epilogue: Q at [(n*3+s)*25600 + u*1024 +
// t*16 + ic], K at +QKOFF.
// ---------------------------------------------------------------------------
__global__ void __launch_bounds__(256)
mma_gemm_qk_kernel(const float* __restrict__ A, const uint4* __restrict__ F,
                   const float* __restrict__ bias, float* __restrict__ QK, int K) {
    __shared__ __align__(16) __nv_bfloat16 sAh[128 * AST];
    __shared__ __align__(16) __nv_bfloat16 sAl[128 * AST];
    GEMM_MAINLOOP(12, 0)
    size_t r0 = (size_t)bm + (warp << 4) + g;
    int n = (int)(r0 / 1600);
    int rem = (int)(r0 - (size_t)n * 1600);
    int u = rem >> 6, t0 = rem & 63;
#pragma unroll
    for (int nt = 0; nt < 12; nt++) {
        int col = (nt << 3) + (tig << 1);
        float bx = bias[col], by = bias[col + 1];
        int half = col >= 48;
        int cc = col - (half ? 48 : 0);
        int s = cc >> 4, ic = cc & 15;
        float* dst = QK + (half ? QKOFF : 0) +
                     ((size_t)(n * 3 + s) * 25600) + u * 1024 + ic;
        *(float2*)&dst[t0 << 4] = make_float2(acc[nt][0] + bx, acc[nt][1] + by);
        *(float2*)&dst[(t0 + 8) << 4] = make_float2(acc[nt][2] + bx, acc[nt][3] + by);
    }
}

// ---------------------------------------------------------------------------
// GEMM + LayerNorm((T,C) groups of 64 rows) + residual + GELU fused epilogue.
// ---------------------------------------------------------------------------
template <int TRANSPOSE>
__global__ void __launch_bounds__(256)
mma_gemm_lns_kernel(const float* __restrict__ A, const uint4* __restrict__ F,
                    const float* __restrict__ bias, const float* __restrict__ resid,
                    const float* __restrict__ gg, const float* __restrict__ bb,
                    float* __restrict__ out, int K) {
    __shared__ __align__(16) __nv_bfloat16 sAh[128 * AST];
    __shared__ __align__(16) __nv_bfloat16 sAl[128 * AST];
    __shared__ float wsum[8], wsq[8];
    GEMM_MAINLOOP(8, 0)

    float vals[8][4];
    float psum = 0.f;
#pragma unroll
    for (int nt = 0; nt < 8; nt++) {
        int col = (nt << 3) + (tig << 1);
        float bx = bias[col], by = bias[col + 1];
        vals[nt][0] = acc[nt][0] + bx; vals[nt][1] = acc[nt][1] + by;
        vals[nt][2] = acc[nt][2] + bx; vals[nt][3] = acc[nt][3] + by;
        psum += vals[nt][0] + vals[nt][1] + vals[nt][2] + vals[nt][3];
    }
#pragma unroll
    for (int o = 16; o; o >>= 1) psum += __shfl_xor_sync(0xffffffffu, psum, o);
    if (lane == 0) wsum[warp] = psum;
    __syncthreads();
    int grp4 = (warp >> 2) << 2;
    float mean = (wsum[grp4] + wsum[grp4 + 1] + wsum[grp4 + 2] + wsum[grp4 + 3]) *
                 (1.f / 4096.f);
    float psq = 0.f;
#pragma unroll
    for (int nt = 0; nt < 8; nt++)
#pragma unroll
        for (int j = 0; j < 4; j++) { float d = vals[nt][j] - mean; psq += d * d; }
#pragma unroll
    for (int o = 16; o; o >>= 1) psq += __shfl_xor_sync(0xffffffffu, psq, o);
    if (lane == 0) wsq[warp] = psq;
    __syncthreads();
    float inv = rsqrtf((wsq[grp4] + wsq[grp4 + 1] + wsq[grp4 + 2] + wsq[grp4 + 3]) *
                           (1.f / 4096.f) + 1e-5f);

    size_t r0 = (size_t)bm + (warp << 4) + g;
    size_t r1 = r0 + 8;
    int tl0 = (int)(r0 & 63), tl1 = tl0 + 8;
    size_t oa0, oa1;
    if (TRANSPOSE) {
        int n0 = (int)(r0 / 1600), rem0 = (int)(r0 - (size_t)n0 * 1600);
        int v0 = rem0 >> 6;
        oa0 = ((size_t)(n0 * 64 + tl0) * 25 + v0) << 6;
        oa1 = ((size_t)(n0 * 64 + tl1) * 25 + v0) << 6;
    } else {
        oa0 = r0 << 6; oa1 = r1 << 6;
    }
#pragma unroll
    for (int nt = 0; nt < 8; nt++) {
        int col = (nt << 3) + (tig << 1);
        float2 g0 = *(const float2*)&gg[tl0 * 64 + col];
        float2 b0 = *(const float2*)&bb[tl0 * 64 + col];
        float2 g1 = *(const float2*)&gg[tl1 * 64 + col];
        float2 b1 = *(const float2*)&bb[tl1 * 64 + col];
        float2 rx0 = *(const float2*)&resid[(r0 << 6) + col];
        float2 rx1 = *(const float2*)&resid[(r1 << 6) + col];
        float2 o0, o1;
        o0.x = gelu_f(rx0.x + (vals[nt][0] - mean) * inv * g0.x + b0.x);
        o0.y = gelu_f(rx0.y + (vals[nt][1] - mean) * inv * g0.y + b0.y);
        o1.x = gelu_f(rx1.x + (vals[nt][2] - mean) * inv * g1.x + b1.x);
        o1.y = gelu_f(rx1.y + (vals[nt][3] - mean) * inv * g1.y + b1.y);
        *(float2*)&out[oa0 + col] = o0;
        *(float2*)&out[oa1 + col] = o1;
    }
}

// ---------------------------------------------------------------------------
// Conv implicit-GEMM (K=448, row-shifted A) + fused BN partial-sum reduce.
// ---------------------------------------------------------------------------
__global__ void __launch_bounds__(256)
mma_gemm_conv_kernel(const float* __restrict__ A, const uint4* __restrict__ F,
                     const float* __restrict__ bias, float* __restrict__ C, int K) {
    __shared__ __align__(16) __nv_bfloat16 sAh[128 * AST];
    __shared__ __align__(16) __nv_bfloat16 sAl[128 * AST];
    __shared__ float ss[64], sqq[64];
    if (threadIdx.x < 64) { ss[threadIdx.x] = 0.f; sqq[threadIdx.x] = 0.f; }
    GEMM_MAINLOOP(8, 1)

    size_t r0 = (size_t)bm + (warp << 4) + g;
    size_t r1 = r0 + 8;
    int rem0 = (int)(r0 % 1750), rem1 = (int)(r1 % 1750);
    bool va0 = (rem0 >= 75) && (rem0 < 1675);
    bool va1 = (rem1 >= 75) && (rem1 < 1675);
#pragma unroll
    for (int nt = 0; nt < 8; nt++) {
        int col = (nt << 3) + (tig << 1);
        float bx = bias[col], by = bias[col + 1];
        float v00 = acc[nt][0] + bx, v01 = acc[nt][1] + by;
        float v10 = acc[nt][2] + bx, v11 = acc[nt][3] + by;
        *(float2*)&C[(r0 << 6) + col] = make_float2(v00, v01);
        *(float2*)&C[(r1 << 6) + col] = make_float2(v10, v11);
        float s0 = (va0 ? v00 : 0.f) + (va1 ? v10 : 0.f);
        float s1 = (va0 ? v01 : 0.f) + (va1 ? v11 : 0.f);
        float q0 = (va0 ? v00 * v00 : 0.f) + (va1 ? v10 * v10 : 0.f);
        float q1 = (va0 ? v01 * v01 : 0.f) + (va1 ? v11 * v11 : 0.f);
        atomicAdd(&ss[col], s0); atomicAdd(&ss[col + 1], s1);
        atomicAdd(&sqq[col], q0); atomicAdd(&sqq[col + 1], q1);
    }
    __syncthreads();
    if (tid < 64) {
        atomicAdd(&g_bnstats[tid], ss[tid]);
        atomicAdd(&g_bnstats[64 + tid], sqq[tid]);
    }
}

// ---------------------------------------------------------------------------
// Spatial attention via HMMA, split-K z=4 (2 chunks each). One block per
// (n,s,z). Writes RAW partial 25x25 sums to part buffer. (round-12 proven)
// ---------------------------------------------------------------------------
#define QST 136   // bf16 row stride (272 B)
__global__ void __launch_bounds__(256)
att_s_hmma_kernel(const float* __restrict__ QK, float* __restrict__ part) {
    extern __shared__ char dsm[];
    __nv_bfloat16* sQh = (__nv_bfloat16*)dsm;
    __nv_bfloat16* sQl = (__nv_bfloat16*)(dsm + 8704);
    __nv_bfloat16* sKh = (__nv_bfloat16*)(dsm + 17408);
    __nv_bfloat16* sKl = (__nv_bfloat16*)(dsm + 26112);
    float* psum = (float*)(dsm + 34816);   // [4 kg][32 u][32 v]
    int n = blockIdx.x, s = blockIdx.y, z = blockIdx.z;
    int tid = threadIdx.x, warp = tid >> 5, lane = tid & 31;
    int g = lane >> 2, tig = lane & 3;
    int mt = warp & 1, kg = warp >> 1;

    for (int i = tid; i < 476; i += 256) {
        int u = 25 + i / 68, c2 = i % 68;
        ((uint32_t*)(sQh + u * QST))[c2] = 0u;
        ((uint32_t*)(sQl + u * QST))[c2] = 0u;
        ((uint32_t*)(sKh + u * QST))[c2] = 0u;
        ((uint32_t*)(sKl + u * QST))[c2] = 0u;
    }

    const float* Qb = QK + (size_t)(n * 3 + s) * 25600;
    const float* Kb = Qb + QKOFF;

    uint32_t q_off = (uint32_t)(((mt << 4) + (lane & 15)) * (QST * 2) +
                                ((lane >> 4) << 4));
    uint32_t k_off = (uint32_t)((lane & 15) * (QST * 2) + ((lane >> 4) << 4));
    uint32_t qh_a = smem_u32(sQh) + q_off, ql_a = smem_u32(sQl) + q_off;
    uint32_t kh_a = smem_u32(sKh) + k_off, kl_a = smem_u32(sKl) + k_off;

    float acc[4][4];
#pragma unroll
    for (int i = 0; i < 4; i++)
#pragma unroll
        for (int j = 0; j < 4; j++) acc[i][j] = 0.f;

    for (int cc = 0; cc < 2; cc++) {
        int ch = (z << 1) + cc;
        __syncthreads();
        for (int idx = tid; idx < 1600; idx += 256) {
            int half = idx >= 800;
            int id = idx - (half ? 800 : 0);
            int u = id >> 5, w = id & 31;
            const float* src = (half ? Kb : Qb) + u * 1024 + (ch << 7) + (w << 2);
            float4 v = *(const float4*)src;
            float h0 = __bfloat162float(__float2bfloat16_rn(v.x));
            float h1 = __bfloat162float(__float2bfloat16_rn(v.y));
            float h2 = __bfloat162float(__float2bfloat16_rn(v.z));
            float h3 = __bfloat162float(__float2bfloat16_rn(v.w));
            int so = u * QST + (w << 2);
            if (half) {
                *(uint2*)&sKh[so] = make_uint2(pkbf(h0, h1), pkbf(h2, h3));
                *(uint2*)&sKl[so] = make_uint2(pkbf(v.x - h0, v.y - h1),
                                               pkbf(v.z - h2, v.w - h3));
            } else {
                *(uint2*)&sQh[so] = make_uint2(pkbf(h0, h1), pkbf(h2, h3));
                *(uint2*)&sQl[so] = make_uint2(pkbf(v.x - h0, v.y - h1),
                                               pkbf(v.z - h2, v.w - h3));
            }
        }
        __syncthreads();
#pragma unroll
        for (int ks2 = 0; ks2 < 2; ks2++) {
            int ks = (kg << 1) + ks2;
            uint32_t qh[4], ql[4];
            ldm4(qh, qh_a + ks * 32);
            ldm4(ql, ql_a + ks * 32);
            uint32_t kh[4], kl[4];
            ldm4(kh, kh_a + ks * 32);
            ldm4(kl, kl_a + ks * 32);
            mma16816(acc[0], qh, kh[0], kh[2]);
            mma16816(acc[0], qh, kl[0], kl[2]);
            mma16816(acc[0], ql, kh[0], kh[2]);
            mma16816(acc[1], qh, kh[1], kh[3]);
            mma16816(acc[1], qh, kl[1], kl[3]);
            mma16816(acc[1], ql, kh[1], kh[3]);
            uint32_t kh2[4], kl2[4];
            ldm4(kh2, kh_a + 16 * (QST * 2) + ks * 32);
            ldm4(kl2, kl_a + 16 * (QST * 2) + ks * 32);
            mma16816(acc[2], qh, kh2[0], kh2[2]);
            mma16816(acc[2], qh, kl2[0], kl2[2]);
            mma16816(acc[2], ql, kh2[0], kh2[2]);
            mma16816(acc[3], qh, kh2[1], kh2[3]);
            mma16816(acc[3], qh, kl2[1], kl2[3]);
            mma16816(acc[3], ql, kh2[1], kh2[3]);
        }
    }
    int row0 = (mt << 4) + g;
#pragma unroll
    for (int nt = 0; nt < 4; nt++) {
        int col = ((nt & 1) << 3) + ((nt >> 1) << 4) + (tig << 1);
        psum[((kg << 5) + row0) * 32 + col] = acc[nt][0];
        psum[((kg << 5) + row0) * 32 + col + 1] = acc[nt][1];
        psum[((kg << 5) + row0 + 8) * 32 + col] = acc[nt][2];
        psum[((kg << 5) + row0 + 8) * 32 + col + 1] = acc[nt][3];
    }
    __syncthreads();
    for (int idx = tid; idx < 1024; idx += 256) {
        int u = idx >> 5, v = idx & 31;
        if (u < 25 && v < 25) {
            float raw = psum[idx] + psum[1024 + idx] + psum[2048 + idx] +
                        psum[3072 + idx];
            int p = u * 25 + v;
            part[((size_t)z * 128 + n) * 1875 + p * 3 + s] = raw;
        }
    }
}

// ---------------------------------------------------------------------------
// att_s combine: sum 4 K-split partials, apply tanh*alpha + att0
// ---------------------------------------------------------------------------
__global__ void att_s2_kernel(const float* __restrict__ part,
                              const float* __restrict__ alphas,
                              const float* __restrict__ att0, float* __restrict__ attS) {
    int e = blockIdx.x * 256 + threadIdx.x;
    if (e >= 240000) return;
    float raw = part[e] + part[240000 + e] + part[480000 + e] + part[720000 + e];
    int s = e % 3;
    attS[e] = tanhf(raw * (1.f / 1024.f)) * alphas[s] + att0[e % 1875];
}

// ---------------------------------------------------------------------------
// mix_s via HMMA (round-11 proven)
// ---------------------------------------------------------------------------
#define MXA 40   // A smem stride (elems)
#define MXB 136  // B smem stride (elems)
__global__ void __launch_bounds__(256)
mix_s_hmma_kernel(const float* __restrict__ x, const float* __restrict__ attS,
                  float* __restrict__ ycat) {
    __shared__ __align__(16) __nv_bfloat16 sAh[80 * MXA], sAl[80 * MXA];
    __shared__ __align__(16) __nv_bfloat16 sBh[32 * MXB], sBl[32 * MXB];
    int n = blockIdx.x, ch = blockIdx.y;
    int tid = threadIdx.x, warp = tid >> 5, lane = tid & 31;
    int g = lane >> 2, tig = lane & 3;

    for (int i = tid; i < 1600; i += 256) {
        ((uint32_t*)sAh)[i] = 0u;
        ((uint32_t*)sAl)[i] = 0u;
    }
    for (int i = tid; i < 7 * 68; i += 256) {
        int u = 25 + i / 68, c2 = (i % 68);
        ((uint32_t*)(sBh + u * MXB))[c2] = 0u;
        ((uint32_t*)(sBl + u * MXB))[c2] = 0u;
    }
    __syncthreads();

    for (int e = tid; e < 1875; e += 256) {
        float a = attS[(size_t)n * 1875 + e];
        int u = e / 75, m = e - u * 75;
        float h = __bfloat162float(__float2bfloat16_rn(a));
        sAh[m * MXA + u] = __float2bfloat16_rn(h);
        sAl[m * MXA + u] = __float2bfloat16_rn(a - h);
    }
    for (int idx = tid; idx < 800; idx += 256) {
        int u = idx >> 5, c4 = (idx & 31) << 2;
        float4 v = *(const float4*)&x[((size_t)(n * 25 + u)) * 4096 + (ch << 7) + c4];
        float h0 = __bfloat162float(__float2bfloat16_rn(v.x));
        float h1 = __bfloat162float(__float2bfloat16_rn(v.y));
        float h2 = __bfloat162float(__float2bfloat16_rn(v.z));
        float h3 = __bfloat162float(__float2bfloat16_rn(v.w));
        *(uint2*)&sBh[u * MXB + c4] = make_uint2(pkbf(h0, h1), pkbf(h2, h3));
        *(uint2*)&sBl[u * MXB + c4] =
            make_uint2(pkbf(v.x - h0, v.y - h1), pkbf(v.z - h2, v.w - h3));
    }
    __syncthreads();

    uint32_t a_base = smem_u32(sAh) + (uint32_t)((lane & 15) * (MXA * 2) +
                                                 ((lane >> 4) << 4));
    uint32_t al_base = smem_u32(sAl) + (uint32_t)((lane & 15) * (MXA * 2) +
                                                  ((lane >> 4) << 4));
    uint32_t b_off = (uint32_t)(((lane & 7) + (lane & 8)) * (MXB * 2) +
                                (((warp << 4) + ((lane >> 4) << 3)) << 1));
    uint32_t bh_addr = smem_u32(sBh) + b_off;
    uint32_t bl_addr = smem_u32(sBl) + b_off;

    float acc[5][2][4];
#pragma unroll
    for (int mt = 0; mt < 5; mt++)
#pragma unroll
        for (int q = 0; q < 2; q++)
#pragma unroll
            for (int j = 0; j < 4; j++) acc[mt][q][j] = 0.f;

#pragma unroll
    for (int ks = 0; ks < 2; ks++) {
        uint32_t bh[4], bl[4];
        uint32_t ko = (uint32_t)(ks * 16 * (MXB * 2));
        ldm4t(bh, bh_addr + ko);
        ldm4t(bl, bl_addr + ko);
#pragma unroll
        for (int mt = 0; mt < 5; mt++) {
            uint32_t ah[4], al[4];
            uint32_t ao = (uint32_t)(mt * 16 * (MXA * 2) + ks * 32);
            ldm4(ah, a_base + ao);
            ldm4(al, al_base + ao);
            mma16816(acc[mt][0], ah, bh[0], bh[1]);
            mma16816(acc[mt][0], ah, bl[0], bl[1]);
            mma16816(acc[mt][0], al, bh[0], bh[1]);
            mma16816(acc[mt][1], ah, bh[2], bh[3]);
            mma16816(acc[mt][1], ah, bl[2], bl[3]);
            mma16816(acc[mt][1], al, bh[2], bh[3]);
        }
    }

#pragma unroll
    for (int mt = 0; mt < 5; mt++) {
#pragma unroll
        for (int nt8 = 0; nt8 < 2; nt8++) {
            int col = (warp << 4) + (nt8 << 3) + (tig << 1);
            int tc = (ch << 7) + col;
            int t = tc >> 6, c = tc & 63;
#pragma unroll
            for (int h = 0; h < 2; h++) {
                int m = (mt << 4) + g + (h << 3);
                if (m < 75) {
                    int v = m / 3, s = m - 3 * v;
                    size_t oa = (((size_t)(n * 25 + v)) * 64 + t) * 192 + s * 64 + c;
                    *(float2*)&ycat[oa] =
                        make_float2(acc[mt][nt8][h << 1], acc[mt][nt8][(h << 1) + 1]);
                }
            }
        }
    }
}

// ---------------------------------------------------------------------------
// LayerNorm over (V,C) per (n,t) + residual + GELU; padded=1 -> conv z buffer.
// Warp-shuffle reduction (2 syncs total instead of 16).
// ---------------------------------------------------------------------------
__global__ void ln_t_kernel(const float* __restrict__ in, const float* __restrict__ resid,
                            const float* __restrict__ gg, const float* __restrict__ bb,
                            float* __restrict__ out, int padded) {
    int grp = blockIdx.x;   // n*64+t
    int tid = threadIdx.x;
    int warp = tid >> 5, lane = tid & 31;
    __shared__ float wred[8];
    const float* ip = in + (size_t)grp * 1600;
    float vals[7];
    float s = 0.f;
#pragma unroll
    for (int r = 0; r < 7; r++) {
        int i = tid + (r << 8);
        vals[r] = (i < 1600) ? ip[i] : 0.f;
        s += vals[r];
    }
#pragma unroll
    for (int o = 16; o; o >>= 1) s += __shfl_xor_sync(0xffffffffu, s, o);
    if (lane == 0) wred[warp] = s;
    __syncthreads();
    float mean = (wred[0] + wred[1] + wred[2] + wred[3] +
                  wred[4] + wred[5] + wred[6] + wred[7]) * (1.f / 1600.f);
    float sq = 0.f;
#pragma unroll
    for (int r = 0; r < 7; r++) {
        int i = tid + (r << 8);
        float d = (i < 1600) ? (vals[r] - mean) : 0.f;
        sq += d * d;
    }
#pragma unroll
    for (int o = 16; o; o >>= 1) sq += __shfl_xor_sync(0xffffffffu, sq, o);
    __syncthreads();   // wred reuse: all reads of pass-1 done
    if (lane == 0) wred[warp] = sq;
    __syncthreads();
    float inv = rsqrtf((wred[0] + wred[1] + wred[2] + wred[3] +
                        wred[4] + wred[5] + wred[6] + wred[7]) * (1.f / 1600.f) + 1e-5f);
    const float* rp = resid + (size_t)grp * 1600;
    int n = grp >> 6, t = grp & 63;
    size_t obase = padded ? ((size_t)(n * TPAD + 3 + t) * 1600) : ((size_t)grp * 1600);
#pragma unroll
    for (int r = 0; r < 7; r++) {
        int i = tid + (r << 8);
        if (i < 1600) {
            float y = (vals[r] - mean) * inv * gg[i] + bb[i];
            out[obase + i] = gelu_f(rp[i] + y);
        }
    }
}

// ---------------------------------------------------------------------------
// Temporal attention via HMMA (round-8 proven)
// ---------------------------------------------------------------------------
#define BST 88
__global__ void __launch_bounds__(256)
att_t_hmma_kernel(const float* __restrict__ qkt, const float* __restrict__ af,
                  const float* __restrict__ ab, float* __restrict__ attO) {
    __shared__ __align__(16) __nv_bfloat16 sQh[64 * BST], sQl[64 * BST];
    __shared__ __align__(16) __nv_bfloat16 sKh[64 * BST], sKl[64 * BST];
    int n = blockIdx.x, combo = blockIdx.y;
    int dir = combo >> 1, s = combo & 1;
    int jq = (dir * 2 + s) << 4, jk = (4 + dir * 2 + s) << 4;
    int tid = threadIdx.x, warp = tid >> 5, lane = tid & 31;
    int g = lane >> 2, tig = lane & 3;
    int mtile = warp & 3, nbase = (warp >> 2) << 5;
    float acc[4][4];
#pragma unroll
    for (int i = 0; i < 4; i++)
#pragma unroll
        for (int j = 0; j < 4; j++) acc[i][j] = 0.f;

    const float* base = qkt + (size_t)n * 204800;
    uint32_t q_off = (uint32_t)((((mtile << 4) + (lane & 15)) * (BST * 2)) +
                                ((lane >> 4) << 4));
    uint32_t k_off = (uint32_t)(((nbase + (lane & 15)) * (BST * 2)) +
                                ((lane >> 4) << 4));
    uint32_t qh_a = smem_u32(sQh) + q_off, ql_a = smem_u32(sQl) + q_off;
    uint32_t kh_a = smem_u32(sKh) + k_off, kl_a = smem_u32(sKl) + k_off;

    for (int vc = 0; vc < 5; vc++) {
        for (int idx = tid; idx < 2560; idx += 256) {
            int half = idx >= 1280;
            int id = idx - (half ? 1280 : 0);
            int t = id / 20, cq = id - t * 20;
            int vi = cq >> 2, icq = (cq & 3) << 2;
            const float* p = base + (size_t)(t * 25 + vc * 5 + vi) * 128 +
                             (half ? jk : jq) + icq;
            float4 v = *(const float4*)p;
            float h0 = __bfloat162float(__float2bfloat16_rn(v.x));
            float h1 = __bfloat162float(__float2bfloat16_rn(v.y));
            float h2 = __bfloat162float(__float2bfloat16_rn(v.z));
            float h3 = __bfloat162float(__float2bfloat16_rn(v.w));
            int so = t * BST + (vi << 4) + icq;
            if (half) {
                *(uint2*)&sKh[so] = make_uint2(pkbf(h0, h1), pkbf(h2, h3));
                *(uint2*)&sKl[so] = make_uint2(pkbf(v.x - h0, v.y - h1),
                                               pkbf(v.z - h2, v.w - h3));
            } else {
                *(uint2*)&sQh[so] = make_uint2(pkbf(h0, h1), pkbf(h2, h3));
                *(uint2*)&sQl[so] = make_uint2(pkbf(v.x - h0, v.y - h1),
                                               pkbf(v.z - h2, v.w - h3));
            }
        }
        __syncthreads();
#pragma unroll
        for (int ks = 0; ks < 5; ks++) {
            uint32_t qh[4], ql[4];
            ldm4(qh, qh_a + ks * 32);
            ldm4(ql, ql_a + ks * 32);
            uint32_t kh[4], kl[4];
            ldm4(kh, kh_a + ks * 32);
            ldm4(kl, kl_a + ks * 32);
            mma16816(acc[0], qh, kh[0], kh[2]);
            mma16816(acc[0], qh, kl[0], kl[2]);
            mma16816(acc[0], ql, kh[0], kh[2]);
            mma16816(acc[1], qh, kh[1], kh[3]);
            mma16816(acc[1], qh, kl[1], kl[3]);
            mma16816(acc[1], ql, kh[1], kh[3]);
            uint32_t kh2[4], kl2[4];
            ldm4(kh2, kh_a + 16 * (BST * 2) + ks * 32);
            ldm4(kl2, kl_a + 16 * (BST * 2) + ks * 32);
            mma16816(acc[2], qh, kh2[0], kh2[2]);
            mma16816(acc[2], qh, kl2[0], kl2[2]);
            mma16816(acc[2], ql, kh2[0], kh2[2]);
            mma16816(acc[3], qh, kh2[1], kh2[3]);
            mma16816(acc[3], qh, kl2[1], kl2[3]);
            mma16816(acc[3], ql, kh2[1], kh2[3]);
        }
        __syncthreads();
    }
    float alpha = dir ? ab[s] : af[s];
    size_t ob = ((size_t)n * 4 + combo) << 12;
    int t0 = (mtile << 4) + g;
#pragma unroll
    for (int nt = 0; nt < 4; nt++) {
        int q = nbase + ((nt & 1) << 3) + ((nt >> 1) << 4) + (tig << 1);
        float v00 = tanhf(acc[nt][0] * (1.f / 400.f)) * alpha;
        float v01 = tanhf(acc[nt][1] * (1.f / 400.f)) * alpha;
        float v10 = tanhf(acc[nt][2] * (1.f / 400.f)) * alpha;
        float v11 = tanhf(acc[nt][3] * (1.f / 400.f)) * alpha;
        int t1 = t0 + 8;
        bool k00 = dir ? (q >= t0) : (t0 >= q);
        bool k01 = dir ? (q + 1 >= t0) : (t0 >= q + 1);
        bool k10 = dir ? (q >= t1) : (t1 >= q);
        bool k11 = dir ? (q + 1 >= t1) : (t1 >= q + 1);
        *(float2*)&attO[ob + (t0 << 6) + q] =
            make_float2(k00 ? v00 : 0.f, k01 ? v01 : 0.f);
        *(float2*)&attO[ob + (t1 << 6) + q] =
            make_float2(k10 ? v10 : 0.f, k11 ? v11 : 0.f);
    }
}

// ---------------------------------------------------------------------------
// mix_t via HMMA (round-8 proven)
// ---------------------------------------------------------------------------
__global__ void __launch_bounds__(256)
mix_t_hmma_kernel(const float* __restrict__ attT_g, const float* __restrict__ yt,
                  float* __restrict__ zcat) {
    __shared__ __align__(16) __nv_bfloat16 sAh[64 * AST], sAl[64 * AST];
    __shared__ __align__(16) __nv_bfloat16 sBh[64 * AST], sBl[64 * AST];
    int n = blockIdx.x, combo = blockIdx.y, vg = blockIdx.z;
    int tid = threadIdx.x, warp = tid >> 5, lane = tid & 31;
    int g = lane >> 2, tig = lane & 3;
    int mtile = warp & 3, nbase = (warp >> 2) << 5;

    const float* ap = attT_g + (((size_t)n * 4 + combo) << 12);
    for (int i = tid; i < 1024; i += 256) {
        int t = i >> 4, q4 = (i & 15) << 2;
        float4 v = *(const float4*)&ap[(t << 6) + q4];
        float h0 = __bfloat162float(__float2bfloat16_rn(v.x));
        float h1 = __bfloat162float(__float2bfloat16_rn(v.y));
        float h2 = __bfloat162float(__float2bfloat16_rn(v.z));
        float h3 = __bfloat162float(__float2bfloat16_rn(v.w));
        sAh[(q4 + 0) * AST + t] = __float2bfloat16_rn(h0);
        sAh[(q4 + 1) * AST + t] = __float2bfloat16_rn(h1);
        sAh[(q4 + 2) * AST + t] = __float2bfloat16_rn(h2);
        sAh[(q4 + 3) * AST + t] = __float2bfloat16_rn(h3);
        sAl[(q4 + 0) * AST + t] = __float2bfloat16_rn(v.x - h0);
        sAl[(q4 + 1) * AST + t] = __float2bfloat16_rn(v.y - h1);
        sAl[(q4 + 2) * AST + t] = __float2bfloat16_rn(v.z - h2);
        sAl[(q4 + 3) * AST + t] = __float2bfloat16_rn(v.w - h3);
    }

    uint32_t a_off = (uint32_t)(((mtile << 4) + (lane & 15)) * (AST * 2) +
                                ((lane >> 4) << 4));
    uint32_t ah_addr = smem_u32(sAh) + a_off;
    uint32_t al_addr = smem_u32(sAl) + a_off;
    uint32_t b_off = (uint32_t)(((lane & 7) + (lane & 8)) * (AST * 2) +
                                ((nbase + ((lane >> 4) << 3)) << 1));
    uint32_t bh_addr = smem_u32(sBh) + b_off;
    uint32_t bl_addr = smem_u32(sBl) + b_off;

    for (int vi = 0; vi < 5; vi++) {
        int v = vg * 5 + vi;
        for (int i = tid; i < 1024; i += 256) {
            int t = i >> 4, c4 = (i & 15) << 2;
            float4 w = *(const float4*)&yt[((size_t)(n * 64 + t) * 25 + v) * 64 + c4];
            float h0 = __bfloat162float(__float2bfloat16_rn(w.x));
            float h1 = __bfloat162float(__float2bfloat16_rn(w.y));
            float h2 = __bfloat162float(__float2bfloat16_rn(w.z));
            float h3 = __bfloat162float(__float2bfloat16_rn(w.w));
            *(uint2*)&sBh[t * AST + c4] =
                make_uint2(pkbf(h0, h1), pkbf(h2, h3));
            *(uint2*)&sBl[t * AST + c4] =
                make_uint2(pkbf(w.x - h0, w.y - h1), pkbf(w.z - h2, w.w - h3));
        }
        __syncthreads();
        float acc[4][4];
#pragma unroll
        for (int i = 0; i < 4; i++)
#pragma unroll
            for (int j = 0; j < 4; j++) acc[i][j] = 0.f;
#pragma unroll
        for (int ks = 0; ks < 4; ks++) {
            uint32_t a_h[4], a_l[4];
            ldm4(a_h, ah_addr + ks * 32);
            ldm4(a_l, al_addr + ks * 32);
#pragma unroll
            for (int nt2 = 0; nt2 < 2; nt2++) {
                uint32_t bh[4], bl[4];
                uint32_t ko = (uint32_t)(ks * 16 * (AST * 2) + nt2 * 32);
                ldm4t(bh, bh_addr + ko);
                ldm4t(bl, bl_addr + ko);
                mma16816(acc[nt2 * 2 + 0], a_h, bh[0], bh[1]);
                mma16816(acc[nt2 * 2 + 0], a_h, bl[0], bl[1]);
                mma16816(acc[nt2 * 2 + 0], a_l, bh[0], bh[1]);
                mma16816(acc[nt2 * 2 + 1], a_h, bh[2], bh[3]);
                mma16816(acc[nt2 * 2 + 1], a_h, bl[2], bl[3]);
                mma16816(acc[nt2 * 2 + 1], a_l, bh[2], bh[3]);
            }
        }
        int q0 = (mtile << 4) + g;
        size_t ob0 = (((size_t)(n * 64 + q0) * 25 + v) << 8) + (combo << 6);
        size_t ob1 = (((size_t)(n * 64 + q0 + 8) * 25 + v) << 8) + (combo << 6);
#pragma unroll
        for (int nt = 0; nt < 4; nt++) {
            int col = nbase + (nt << 3) + (tig << 1);
            *(float2*)&zcat[ob0 + col] = make_float2(acc[nt][0], acc[nt][1]);
            *(float2*)&zcat[ob1 + col] = make_float2(acc[nt][2], acc[nt][3]);
        }
        __syncthreads();
    }
}

// ---------------------------------------------------------------------------
// BN apply + residual + GELU + final transpose to output (n,v,t,c)
// ---------------------------------------------------------------------------
__global__ void bn_final_kernel(const float* __restrict__ z, const float* __restrict__ z1,
                                const float* __restrict__ bg, const float* __restrict__ bb,
                                float* __restrict__ out) {
    size_t e = (size_t)blockIdx.x * 256 + threadIdx.x;
    int c = (int)(e & 63);
    size_t r = e >> 6;
    int t = (int)(r & 63);
    size_t r2 = r >> 6;
    int v = (int)(r2 % 25);
    int n = (int)(r2 / 25);
    size_t paddr = ((size_t)(n * TPAD + 3 + t) * 25 + v) * 64 + c;
    float mean = g_bnstats[c] * (1.f / 204800.f);
    float var = g_bnstats[64 + c] * (1.f / 204800.f) - mean * mean;
    float z1n = (z1[paddr] - mean) * rsqrtf(var + 1e-5f) * bg[c] + bb[c];
    out[e] = gelu_f(z[paddr] + z1n);
}

// ---------------------------------------------------------------------------
// Host launcher
// ---------------------------------------------------------------------------
extern "C" void kernel_launch(void* const* d_in, const int* in_sizes, int n_in,
                              void* d_out, int out_size) {
    const float* x          = (const float*)d_in[0];
    const float* w_in_s     = (const float*)d_in[1];
    const float* b_in_s     = (const float*)d_in[2];
    const float* alphas     = (const float*)d_in[3];
    const float* att0s      = (const float*)d_in[4];
    const float* w_out_s    = (const float*)d_in[5];
    const float* b_out_s    = (const float*)d_in[6];
    const float* ln_out_s_g = (const float*)d_in[7];
    const float* ln_out_s_b = (const float*)d_in[8];
    const float* w_ff_s     = (const float*)d_in[9];
    const float* b_ff_s     = (const float*)d_in[10];
    const float* ln_ff_s_g  = (const float*)d_in[11];
    const float* ln_ff_s_b  = (const float*)d_in[12];
    const float* w_in_t     = (const float*)d_in[13];
    const float* b_in_t     = (const float*)d_in[14];
    const float* alphat_f   = (const float*)d_in[15];
    const float* alphat_b   = (const float*)d_in[16];
    const float* w_out_t    = (const float*)d_in[17];
    const float* b_out_t    = (const float*)d_in[18];
    const float* ln_out_t_g = (const float*)d_in[19];
    const float* ln_out_t_b = (const float*)d_in[20];
    const float* w_ff_t     = (const float*)d_in[21];
    const float* b_ff_t     = (const float*)d_in[22];
    const float* ln_ff_t_g  = (const float*)d_in[23];
    const float* ln_ff_t_b  = (const float*)d_in[24];
    const float* conv_w     = (const float*)d_in[25];
    const float* conv_b     = (const float*)d_in[26];
    const float* bn_g       = (const float*)d_in[27];
    const float* bn_b       = (const float*)d_in[28];
    float* out = (float*)d_out;

    float *bufA, *bufB, *bufC, *bufD, *bufE, *bufF, *attS, *attT, *bis, *bit;
    cudaGetSymbolAddress((void**)&bufA, g_bufA);
    cudaGetSymbolAddress((void**)&bufB, g_bufB);
    cudaGetSymbolAddress((void**)&bufC, g_bufC);
    cudaGetSymbolAddress((void**)&bufD, g_bufD);
    cudaGetSymbolAddress((void**)&bufE, g_bufE);
    cudaGetSymbolAddress((void**)&bufF, g_bufF);
    cudaGetSymbolAddress((void**)&attS, g_attS);
    cudaGetSymbolAddress((void**)&attT, g_attT);
    cudaGetSymbolAddress((void**)&bis, g_bis);
    cudaGetSymbolAddress((void**)&bit, g_bit);
    uint4 *Fqk, *Fouts, *Fffs, *Fint, *Foutt, *Ffft, *Fconv;
    cudaGetSymbolAddress((void**)&Fqk, g_Fqk);
    cudaGetSymbolAddress((void**)&Fouts, g_Fouts);
    cudaGetSymbolAddress((void**)&Fffs, g_Fffs);
    cudaGetSymbolAddress((void**)&Fint, g_Fint);
    cudaGetSymbolAddress((void**)&Foutt, g_Foutt);
    cudaGetSymbolAddress((void**)&Ffft, g_Ffft);
    cudaGetSymbolAddress((void**)&Fconv, g_Fconv);
    float* zbase = bufF + GUARD;

    cudaFuncSetAttribute(att_s_hmma_kernel,
                         cudaFuncAttributeMaxDynamicSharedMemorySize, 51200);

    prep_kernel<<<28, 256>>>(w_in_s, b_in_s, w_out_s, w_ff_s, w_in_t, b_in_t,
                             w_out_t, w_ff_t, conv_w);
    zero_pads_kernel<<<4800, 256>>>(zbase);

    // ---- spatial stage ----
    mma_gemm_qk_kernel<<<1600, 256>>>(x, Fqk, bis, bufB, 64);
    att_s_hmma_kernel<<<dim3(NN, 3, 4), 256, 51200>>>(bufB, bufC);
    att_s2_kernel<<<938, 256>>>(bufC, alphas, att0s, attS);
    mix_s_hmma_kernel<<<dim3(NN, 32), 256>>>(x, attS, bufA);
    mma_gemm_lns_kernel<0><<<1600, 256>>>(bufA, Fouts, b_out_s, x,
                                          ln_out_s_g, ln_out_s_b, bufD, 192);
    mma_gemm_lns_kernel<1><<<1600, 256>>>(bufD, Fffs, b_ff_s, x,
                                          ln_ff_s_g, ln_ff_s_b, bufE, 64);

    // ---- temporal stage ----
    mma_gemm_kernel<128><<<1600, 256>>>(bufE, Fint, bit, bufB, 64);
    att_t_hmma_kernel<<<dim3(NN, 4), 256>>>(bufB, alphat_f, alphat_b, attT);
    mix_t_hmma_kernel<<<dim3(NN, 4, 5), 256>>>(attT, bufE, bufA);
    mma_gemm_kernel<64><<<1600, 256>>>(bufA, Foutt, b_out_t, bufC, 256);
    ln_t_kernel<<<8192, 256>>>(bufC, bufE, ln_out_t_g, ln_out_t_b, bufD, 0);
    mma_gemm_kernel<64><<<1600, 256>>>(bufD, Ffft, b_ff_t, bufC, 64);
    ln_t_kernel<<<8192, 256>>>(bufC, bufE, ln_ff_t_g, ln_ff_t_b, zbase, 1);

    // ---- conv + batchnorm + output ----
    mma_gemm_conv_kernel<<<1750, 256>>>(zbase, Fconv, conv_b, bufD, 448);
    bn_final_kernel<<<51200, 256>>>(zbase, bufD, bn_g, bn_b, out);
}

// round 16
// speedup vs baseline: 1.0628x; 1.0241x over previous
#include <cuda_runtime.h>
#include <cuda_bf16.h>
#include <math.h>
#include <stdint.h>

// ---------------------------------------------------------------------------
// Problem constants: x (N=128, V=25, T=64, C=64), IC=16, S=3, TS=2
// ---------------------------------------------------------------------------
#define NN 128
#define NVT 204800          // N*V*T == N*T*V
#define TPAD 70             // T + 6 (conv halo)
#define MPAD 224000         // N*TPAD*V rows for padded z
#define GUARD 4800          // 3*V*C guard floats (75 rows) before/after padded z
#define QKOFF 9830400       // 128*3*25600 floats (Q region size; K follows)

// ---------------------------------------------------------------------------
// Scratch (static device globals; no runtime allocation allowed)
// ---------------------------------------------------------------------------
__device__ float g_bufA[(size_t)NVT * 256];                 // ycat / zcat
__device__ float g_bufB[(size_t)NVT * 128];                 // Q/K (spatial) / qkt
__device__ float g_bufC[(size_t)NVT * 64];                  // gemm outputs / att_s partials
__device__ float g_bufD[(size_t)NVT * 64];                  // y1 / z-mid / conv out
__device__ float g_bufE[(size_t)NVT * 64];                  // y transposed (n,t,v,c)
__device__ float g_bufF[GUARD + (size_t)MPAD * 64 + GUARD]; // padded z + guards
__device__ float g_attS[(size_t)NN * 625 * 3];
__device__ float g_attT[(size_t)NN * 4 * 64 * 64];
__device__ float g_bis[96];                                 // b_in_s col-permuted
__device__ float g_bit[128];                                // b_in_t col-permuted
__device__ float g_bnstats[128];                            // sum[64], sumsq[64]

// Pre-packed mma.sync B fragments: per (k16-chunk, ntile, lane) a uint4 =
// {b_hi_reg0, b_hi_reg1, b_lo_reg0, b_lo_reg1}
__device__ uint4 g_Fqk[4 * 12 * 32];      // K=64,  Nc=96
__device__ uint4 g_Fouts[12 * 8 * 32];    // K=192, Nc=64
__device__ uint4 g_Fffs[4 * 8 * 32];      // K=64,  Nc=64
__device__ uint4 g_Fint[4 * 16 * 32];     // K=64,  Nc=128 (col-permuted j*16+ic)
__device__ uint4 g_Foutt[16 * 8 * 32];    // K=256, Nc=64
__device__ uint4 g_Ffft[4 * 8 * 32];      // K=64,  Nc=64
__device__ uint4 g_Fconv[28 * 8 * 32];    // K=448, Nc=64

__device__ __forceinline__ float gelu_f(float x) {
    return 0.5f * x * (1.f + erff(x * 0.70710678118654752f));
}

__device__ __forceinline__ uint32_t smem_u32(const void* p) {
    uint32_t a;
    asm("{ .reg .u64 t; cvta.to.shared.u64 t, %1; cvt.u32.u64 %0, t; }" : "=r"(a) : "l"(p));
    return a;
}
__device__ __forceinline__ void ldm4(uint32_t* r, uint32_t addr) {
    asm volatile("ldmatrix.sync.aligned.m8n8.x4.shared.b16 {%0,%1,%2,%3}, [%4];"
                 : "=r"(r[0]), "=r"(r[1]), "=r"(r[2]), "=r"(r[3]) : "r"(addr));
}
__device__ __forceinline__ void ldm4t(uint32_t* r, uint32_t addr) {
    asm volatile("ldmatrix.sync.aligned.m8n8.x4.trans.shared.b16 {%0,%1,%2,%3}, [%4];"
                 : "=r"(r[0]), "=r"(r[1]), "=r"(r[2]), "=r"(r[3]) : "r"(addr));
}
__device__ __forceinline__ void mma16816(float* c, const uint32_t* a,
                                         uint32_t b0, uint32_t b1) {
    asm volatile(
        "mma.sync.aligned.m16n8k16.row.col.f32.bf16.bf16.f32 "
        "{%0,%1,%2,%3}, {%4,%5,%6,%7}, {%8,%9}, {%0,%1,%2,%3};"
        : "+f"(c[0]), "+f"(c[1]), "+f"(c[2]), "+f"(c[3])
        : "r"(a[0]), "r"(a[1]), "r"(a[2]), "r"(a[3]), "r"(b0), "r"(b1));
}
__device__ __forceinline__ uint32_t pkbf(float a, float b) {
    __nv_bfloat162 t = __floats2bfloat162_rn(a, b);
    return *(uint32_t*)&t;
}

// ---------------------------------------------------------------------------
// Prep: build B fragments (hi/lo split, permuted), permuted biases, zero bn
// ---------------------------------------------------------------------------
__device__ __forceinline__ void mk_frag(uint4* dst, int i, int NT,
                                        float w00, float w01, float w10, float w11) {
    float h00 = __bfloat162float(__float2bfloat16_rn(w00));
    float h01 = __bfloat162float(__float2bfloat16_rn(w01));
    float h10 = __bfloat162float(__float2bfloat16_rn(w10));
    float h11 = __bfloat162float(__float2bfloat16_rn(w11));
    dst[i] = make_uint4(pkbf(h00, h01), pkbf(h10, h11),
                        pkbf(w00 - h00, w01 - h01), pkbf(w10 - h10, w11 - h11));
}
#define FRAG_IDX(NT) \
    int lane = i & 31, nt = (i >> 5) % (NT), kc = (i >> 5) / (NT); \
    int g = lane >> 2, tig = lane & 3; \
    int n = nt * 8 + g; int k0 = kc * 16 + 2 * tig; (void)kc;

__global__ void prep_kernel(const float* __restrict__ wqk, const float* __restrict__ bqk,
                            const float* __restrict__ ws, const float* __restrict__ wffs,
                            const float* __restrict__ wint, const float* __restrict__ bint,
                            const float* __restrict__ wt,
                            const float* __restrict__ wfft, const float* __restrict__ cw) {
    int i = blockIdx.x * 256 + threadIdx.x;
    if (i < 4 * 12 * 32) {     // qk: Nc=96, K=64
        FRAG_IDX(12)
        int cc = (n < 48) ? n : n - 48;
        int s = cc >> 4, ic = cc & 15;
        int old = ic * 6 + s + ((n < 48) ? 0 : 3);
        mk_frag(g_Fqk, i, 12,
                wqk[k0 * 96 + old], wqk[(k0 + 1) * 96 + old],
                wqk[(k0 + 8) * 96 + old], wqk[(k0 + 9) * 96 + old]);
    }
    if (i < 96) {
        int cc = (i < 48) ? i : i - 48;
        int s = cc >> 4, ic = cc & 15;
        g_bis[i] = bqk[ic * 6 + s + ((i < 48) ? 0 : 3)];
    }
    if (i < 128) {             // in_t bias: new col n = j*16+ic -> old ic*8+j
        int j = i >> 4, ic = i & 15;
        g_bit[i] = bint[ic * 8 + j];
    }
    if (i < 12 * 8 * 32) {     // out_s: k = s*64+c -> orig row c*3+s, Nc=64
        FRAG_IDX(8)
        float w[4];
#pragma unroll
        for (int e = 0; e < 4; e++) {
            int k = k0 + (e >> 1) * 8 + (e & 1);
            int s = k >> 6, c = k & 63;
            w[e] = ws[(c * 3 + s) * 64 + n];
        }
        mk_frag(g_Fouts, i, 8, w[0], w[1], w[2], w[3]);
    }
    if (i < 4 * 8 * 32) {      // ff_s / ff_t: [K=64][64]
        FRAG_IDX(8)
        mk_frag(g_Fffs, i, 8, wffs[k0 * 64 + n], wffs[(k0 + 1) * 64 + n],
                wffs[(k0 + 8) * 64 + n], wffs[(k0 + 9) * 64 + n]);
        mk_frag(g_Ffft, i, 8, wfft[k0 * 64 + n], wfft[(k0 + 1) * 64 + n],
                wfft[(k0 + 8) * 64 + n], wfft[(k0 + 9) * 64 + n]);
    }
    if (i < 4 * 16 * 32) {     // in_t: [K=64][128], cols permuted n=j*16+ic
        FRAG_IDX(16)
        int j = n >> 4, ic = n & 15;
        int old = ic * 8 + j;
        mk_frag(g_Fint, i, 16, wint[k0 * 128 + old], wint[(k0 + 1) * 128 + old],
                wint[(k0 + 8) * 128 + old], wint[(k0 + 9) * 128 + old]);
    }
    if (i < 16 * 8 * 32) {     // out_t: k = dir*128+s*64+c -> orig dir*128+c*2+s
        FRAG_IDX(8)
        float w[4];
#pragma unroll
        for (int e = 0; e < 4; e++) {
            int k = k0 + (e >> 1) * 8 + (e & 1);
            int dir = k >> 7, s = (k >> 6) & 1, c = k & 63;
            w[e] = wt[(dir * 128 + c * 2 + s) * 64 + n];
        }
        mk_frag(g_Foutt, i, 8, w[0], w[1], w[2], w[3]);
    }
    if (i < 28 * 8 * 32) {     // conv: k = dt*64+ci, orig (co,ci,dt)
        FRAG_IDX(8)
        float w[4];
#pragma unroll
        for (int e = 0; e < 4; e++) {
            int k = k0 + (e >> 1) * 8 + (e & 1);
            int dt = k >> 6, ci = k & 63;
            w[e] = cw[(n * 64 + ci) * 7 + dt];
        }
        mk_frag(g_Fconv, i, 8, w[0], w[1], w[2], w[3]);
    }
    if (i < 128) g_bnstats[i] = 0.f;
}

__global__ void zero_pads_kernel(float* __restrict__ zbase) {
    int e = blockIdx.x * 256 + threadIdx.x;   // over 128*6*1600
    int n = e / 9600, r = e - n * 9600;
    int k = r / 1600, rem = r - k * 1600;
    int tp = (k < 3) ? k : (k + 64);          // pad rows {0,1,2,67,68,69}
    zbase[((size_t)(n * TPAD + tp)) * 1600 + rem] = 0.f;
}

// ---------------------------------------------------------------------------
// Shared GEMM mainloop macro (MF=1, round-8 proven config): fp32 A -> bf16
// hi/lo smem, 3xHMMA per k16. 256 thr, 128-row M tile. B fragments in gmem.
// ---------------------------------------------------------------------------
#define AST 72   // smem bf16 row stride (144 B) -> conflict-free ldmatrix

#define GEMM_MAINLOOP(NT_, CONV_)                                                  \
    int tid = threadIdx.x, warp = tid >> 5, lane = tid & 31;                       \
    int g = lane >> 2, tig = lane & 3;                                             \
    int bm = blockIdx.x << 7;                                                      \
    int lda = (CONV_) ? 64 : K;                                                    \
    float acc[NT_][4];                                                             \
    _Pragma("unroll") for (int i_ = 0; i_ < NT_; i_++)                             \
        _Pragma("unroll") for (int j_ = 0; j_ < 4; j_++) acc[i_][j_] = 0.f;        \
    uint32_t arow_off =                                                            \
        (uint32_t)(((warp << 4) + (lane & 15)) * (AST * 2) + ((lane >> 4) << 4));  \
    uint32_t ah_addr = smem_u32(sAh) + arow_off;                                   \
    uint32_t al_addr = smem_u32(sAl) + arow_off;                                   \
    int crow = tid >> 1, ccol = (tid & 1) << 5;                                    \
    char* sh = (char*)sAh + crow * (AST * 2) + ccol * 2;                           \
    char* sl = (char*)sAl + crow * (AST * 2) + ccol * 2;                           \
    int chunks = K >> 6;                                                           \
    for (int ch = 0; ch < chunks; ch++) {                                          \
        long rshift = (CONV_) ? (long)(ch - 3) * 25 : 0;                           \
        int col0 = (CONV_) ? 0 : (ch << 6);                                        \
        const float* ap = A + ((long)bm + rshift + crow) * lda + col0 + ccol;      \
        _Pragma("unroll") for (int j = 0; j < 8; j++) {                            \
            float4 v = *(const float4*)(ap + (j << 2));                            \
            float hx = __bfloat162float(__float2bfloat16_rn(v.x));                 \
            float hy = __bfloat162float(__float2bfloat16_rn(v.y));                 \
            float hz = __bfloat162float(__float2bfloat16_rn(v.z));                 \
            float hw = __bfloat162float(__float2bfloat16_rn(v.w));                 \
            *(uint2*)(sh + (j << 3)) = make_uint2(pkbf(hx, hy), pkbf(hz, hw));     \
            *(uint2*)(sl + (j << 3)) =                                             \
                make_uint2(pkbf(v.x - hx, v.y - hy), pkbf(v.z - hz, v.w - hw));    \
        }                                                                          \
        __syncthreads();                                                           \
        _Pragma("unroll") for (int ks = 0; ks < 4; ks++) {                         \
            uint32_t a_h[4], a_l[4];                                               \
            ldm4(a_h, ah_addr + ks * 32);                                          \
            ldm4(a_l, al_addr + ks * 32);                                          \
            const uint4* Fp = F + ((size_t)((ch << 2) + ks) * NT_) * 32 + lane;    \
            _Pragma("unroll") for (int nt = 0; nt < NT_; nt++) {                   \
                uint4 bf = Fp[nt * 32];                                            \
                mma16816(acc[nt], a_h, bf.x, bf.y);                                \
                mma16816(acc[nt], a_h, bf.z, bf.w);                                \
                mma16816(acc[nt], a_l, bf.x, bf.y);                                \
            }                                                                      \
        }                                                                          \
        __syncthreads();                                                           \
    }

// ---------------------------------------------------------------------------
// Plain GEMM (in_t Nc=128, out_t/ff_t Nc=64)
// ---------------------------------------------------------------------------
template <int NC>
__global__ void __launch_bounds__(256)
mma_gemm_kernel(const float* __restrict__ A, const uint4* __restrict__ F,
                const float* __restrict__ bias, float* __restrict__ C, int K) {
    __shared__ __align__(16) __nv_bfloat16 sAh[128 * AST];
    __shared__ __align__(16) __nv_bfloat16 sAl[128 * AST];
    constexpr int NT = NC / 8;
    GEMM_MAINLOOP(NT, 0)
    size_t r0 = (size_t)bm + (warp << 4) + g;
#pragma unroll
    for (int nt = 0; nt < NT; nt++) {
        int col = (nt << 3) + (tig << 1);
        float bx = bias[col], by = bias[col + 1];
        *(float2*)&C[r0 * NC + col] = make_float2(acc[nt][0] + bx, acc[nt][1] + by);
        *(float2*)&C[(r0 + 8) * NC + col] = make_float2(acc[nt][2] + bx, acc[nt][3] + by);
    }
}

// ---------------------------------------------------------------------------
// qk GEMM (Nc=96) with att-friendly epilogue: Q at [(n*3+s)*25600 + u*1024 +
// t*16 + ic], K at +QKOFF.
// ---------------------------------------------------------------------------
__global__ void __launch_bounds__(256)
mma_gemm_qk_kernel(const float* __restrict__ A, const uint4* __restrict__ F,
                   const float* __restrict__ bias, float* __restrict__ QK, int K) {
    __shared__ __align__(16) __nv_bfloat16 sAh[128 * AST];
    __shared__ __align__(16) __nv_bfloat16 sAl[128 * AST];
    GEMM_MAINLOOP(12, 0)
    size_t r0 = (size_t)bm + (warp << 4) + g;
    int n = (int)(r0 / 1600);
    int rem = (int)(r0 - (size_t)n * 1600);
    int u = rem >> 6, t0 = rem & 63;
#pragma unroll
    for (int nt = 0; nt < 12; nt++) {
        int col = (nt << 3) + (tig << 1);
        float bx = bias[col], by = bias[col + 1];
        int half = col >= 48;
        int cc = col - (half ? 48 : 0);
        int s = cc >> 4, ic = cc & 15;
        float* dst = QK + (half ? QKOFF : 0) +
                     ((size_t)(n * 3 + s) * 25600) + u * 1024 + ic;
        *(float2*)&dst[t0 << 4] = make_float2(acc[nt][0] + bx, acc[nt][1] + by);
        *(float2*)&dst[(t0 + 8) << 4] = make_float2(acc[nt][2] + bx, acc[nt][3] + by);
    }
}

// ---------------------------------------------------------------------------
// GEMM + LayerNorm((T,C) groups of 64 rows) + residual + GELU fused epilogue.
// ---------------------------------------------------------------------------
template <int TRANSPOSE>
__global__ void __launch_bounds__(256)
mma_gemm_lns_kernel(const float* __restrict__ A, const uint4* __restrict__ F,
                    const float* __restrict__ bias, const float* __restrict__ resid,
                    const float* __restrict__ gg, const float* __restrict__ bb,
                    float* __restrict__ out, int K) {
    __shared__ __align__(16) __nv_bfloat16 sAh[128 * AST];
    __shared__ __align__(16) __nv_bfloat16 sAl[128 * AST];
    __shared__ float wsum[8], wsq[8];
    GEMM_MAINLOOP(8, 0)

    float vals[8][4];
    float psum = 0.f;
#pragma unroll
    for (int nt = 0; nt < 8; nt++) {
        int col = (nt << 3) + (tig << 1);
        float bx = bias[col], by = bias[col + 1];
        vals[nt][0] = acc[nt][0] + bx; vals[nt][1] = acc[nt][1] + by;
        vals[nt][2] = acc[nt][2] + bx; vals[nt][3] = acc[nt][3] + by;
        psum += vals[nt][0] + vals[nt][1] + vals[nt][2] + vals[nt][3];
    }
#pragma unroll
    for (int o = 16; o; o >>= 1) psum += __shfl_xor_sync(0xffffffffu, psum, o);
    if (lane == 0) wsum[warp] = psum;
    __syncthreads();
    int grp4 = (warp >> 2) << 2;
    float mean = (wsum[grp4] + wsum[grp4 + 1] + wsum[grp4 + 2] + wsum[grp4 + 3]) *
                 (1.f / 4096.f);
    float psq = 0.f;
#pragma unroll
    for (int nt = 0; nt < 8; nt++)
#pragma unroll
        for (int j = 0; j < 4; j++) { float d = vals[nt][j] - mean; psq += d * d; }
#pragma unroll
    for (int o = 16; o; o >>= 1) psq += __shfl_xor_sync(0xffffffffu, psq, o);
    if (lane == 0) wsq[warp] = psq;
    __syncthreads();
    float inv = rsqrtf((wsq[grp4] + wsq[grp4 + 1] + wsq[grp4 + 2] + wsq[grp4 + 3]) *
                           (1.f / 4096.f) + 1e-5f);

    size_t r0 = (size_t)bm + (warp << 4) + g;
    size_t r1 = r0 + 8;
    int tl0 = (int)(r0 & 63), tl1 = tl0 + 8;
    size_t oa0, oa1;
    if (TRANSPOSE) {
        int n0 = (int)(r0 / 1600), rem0 = (int)(r0 - (size_t)n0 * 1600);
        int v0 = rem0 >> 6;
        oa0 = ((size_t)(n0 * 64 + tl0) * 25 + v0) << 6;
        oa1 = ((size_t)(n0 * 64 + tl1) * 25 + v0) << 6;
    } else {
        oa0 = r0 << 6; oa1 = r1 << 6;
    }
#pragma unroll
    for (int nt = 0; nt < 8; nt++) {
        int col = (nt << 3) + (tig << 1);
        float2 g0 = *(const float2*)&gg[tl0 * 64 + col];
        float2 b0 = *(const float2*)&bb[tl0 * 64 + col];
        float2 g1 = *(const float2*)&gg[tl1 * 64 + col];
        float2 b1 = *(const float2*)&bb[tl1 * 64 + col];
        float2 rx0 = *(const float2*)&resid[(r0 << 6) + col];
        float2 rx1 = *(const float2*)&resid[(r1 << 6) + col];
        float2 o0, o1;
        o0.x = gelu_f(rx0.x + (vals[nt][0] - mean) * inv * g0.x + b0.x);
        o0.y = gelu_f(rx0.y + (vals[nt][1] - mean) * inv * g0.y + b0.y);
        o1.x = gelu_f(rx1.x + (vals[nt][2] - mean) * inv * g1.x + b1.x);
        o1.y = gelu_f(rx1.y + (vals[nt][3] - mean) * inv * g1.y + b1.y);
        *(float2*)&out[oa0 + col] = o0;
        *(float2*)&out[oa1 + col] = o1;
    }
}

// ---------------------------------------------------------------------------
// Conv implicit-GEMM (K=448, row-shifted A) + fused BN partial-sum reduce.
// ---------------------------------------------------------------------------
__global__ void __launch_bounds__(256)
mma_gemm_conv_kernel(const float* __restrict__ A, const uint4* __restrict__ F,
                     const float* __restrict__ bias, float* __restrict__ C, int K) {
    __shared__ __align__(16) __nv_bfloat16 sAh[128 * AST];
    __shared__ __align__(16) __nv_bfloat16 sAl[128 * AST];
    __shared__ float ss[64], sqq[64];
    if (threadIdx.x < 64) { ss[threadIdx.x] = 0.f; sqq[threadIdx.x] = 0.f; }
    GEMM_MAINLOOP(8, 1)

    size_t r0 = (size_t)bm + (warp << 4) + g;
    size_t r1 = r0 + 8;
    int rem0 = (int)(r0 % 1750), rem1 = (int)(r1 % 1750);
    bool va0 = (rem0 >= 75) && (rem0 < 1675);
    bool va1 = (rem1 >= 75) && (rem1 < 1675);
#pragma unroll
    for (int nt = 0; nt < 8; nt++) {
        int col = (nt << 3) + (tig << 1);
        float bx = bias[col], by = bias[col + 1];
        float v00 = acc[nt][0] + bx, v01 = acc[nt][1] + by;
        float v10 = acc[nt][2] + bx, v11 = acc[nt][3] + by;
        *(float2*)&C[(r0 << 6) + col] = make_float2(v00, v01);
        *(float2*)&C[(r1 << 6) + col] = make_float2(v10, v11);
        float s0 = (va0 ? v00 : 0.f) + (va1 ? v10 : 0.f);
        float s1 = (va0 ? v01 : 0.f) + (va1 ? v11 : 0.f);
        float q0 = (va0 ? v00 * v00 : 0.f) + (va1 ? v10 * v10 : 0.f);
        float q1 = (va0 ? v01 * v01 : 0.f) + (va1 ? v11 * v11 : 0.f);
        atomicAdd(&ss[col], s0); atomicAdd(&ss[col + 1], s1);
        atomicAdd(&sqq[col], q0); atomicAdd(&sqq[col + 1], q1);
    }
    __syncthreads();
    if (tid < 64) {
        atomicAdd(&g_bnstats[tid], ss[tid]);
        atomicAdd(&g_bnstats[64 + tid], sqq[tid]);
    }
}

// ---------------------------------------------------------------------------
// Spatial attention via HMMA, split-K z=4 (2 chunks each). One block per
// (n,s,z). Writes RAW partial 25x25 sums to part buffer. (round-12 proven)
// ---------------------------------------------------------------------------
#define QST 136   // bf16 row stride (272 B)
__global__ void __launch_bounds__(256)
att_s_hmma_kernel(const float* __restrict__ QK, float* __restrict__ part) {
    extern __shared__ char dsm[];
    __nv_bfloat16* sQh = (__nv_bfloat16*)dsm;
    __nv_bfloat16* sQl = (__nv_bfloat16*)(dsm + 8704);
    __nv_bfloat16* sKh = (__nv_bfloat16*)(dsm + 17408);
    __nv_bfloat16* sKl = (__nv_bfloat16*)(dsm + 26112);
    float* psum = (float*)(dsm + 34816);   // [4 kg][32 u][32 v]
    int n = blockIdx.x, s = blockIdx.y, z = blockIdx.z;
    int tid = threadIdx.x, warp = tid >> 5, lane = tid & 31;
    int g = lane >> 2, tig = lane & 3;
    int mt = warp & 1, kg = warp >> 1;

    for (int i = tid; i < 476; i += 256) {
        int u = 25 + i / 68, c2 = i % 68;
        ((uint32_t*)(sQh + u * QST))[c2] = 0u;
        ((uint32_t*)(sQl + u * QST))[c2] = 0u;
        ((uint32_t*)(sKh + u * QST))[c2] = 0u;
        ((uint32_t*)(sKl + u * QST))[c2] = 0u;
    }

    const float* Qb = QK + (size_t)(n * 3 + s) * 25600;
    const float* Kb = Qb + QKOFF;

    uint32_t q_off = (uint32_t)(((mt << 4) + (lane & 15)) * (QST * 2) +
                                ((lane >> 4) << 4));
    uint32_t k_off = (uint32_t)((lane & 15) * (QST * 2) + ((lane >> 4) << 4));
    uint32_t qh_a = smem_u32(sQh) + q_off, ql_a = smem_u32(sQl) + q_off;
    uint32_t kh_a = smem_u32(sKh) + k_off, kl_a = smem_u32(sKl) + k_off;

    float acc[4][4];
#pragma unroll
    for (int i = 0; i < 4; i++)
#pragma unroll
        for (int j = 0; j < 4; j++) acc[i][j] = 0.f;

    for (int cc = 0; cc < 2; cc++) {
        int ch = (z << 1) + cc;
        __syncthreads();
        for (int idx = tid; idx < 1600; idx += 256) {
            int half = idx >= 800;
            int id = idx - (half ? 800 : 0);
            int u = id >> 5, w = id & 31;
            const float* src = (half ? Kb : Qb) + u * 1024 + (ch << 7) + (w << 2);
            float4 v = *(const float4*)src;
            float h0 = __bfloat162float(__float2bfloat16_rn(v.x));
            float h1 = __bfloat162float(__float2bfloat16_rn(v.y));
            float h2 = __bfloat162float(__float2bfloat16_rn(v.z));
            float h3 = __bfloat162float(__float2bfloat16_rn(v.w));
            int so = u * QST + (w << 2);
            if (half) {
                *(uint2*)&sKh[so] = make_uint2(pkbf(h0, h1), pkbf(h2, h3));
                *(uint2*)&sKl[so] = make_uint2(pkbf(v.x - h0, v.y - h1),
                                               pkbf(v.z - h2, v.w - h3));
            } else {
                *(uint2*)&sQh[so] = make_uint2(pkbf(h0, h1), pkbf(h2, h3));
                *(uint2*)&sQl[so] = make_uint2(pkbf(v.x - h0, v.y - h1),
                                               pkbf(v.z - h2, v.w - h3));
            }
        }
        __syncthreads();
#pragma unroll
        for (int ks2 = 0; ks2 < 2; ks2++) {
            int ks = (kg << 1) + ks2;
            uint32_t qh[4], ql[4];
            ldm4(qh, qh_a + ks * 32);
            ldm4(ql, ql_a + ks * 32);
            uint32_t kh[4], kl[4];
            ldm4(kh, kh_a + ks * 32);
            ldm4(kl, kl_a + ks * 32);
            mma16816(acc[0], qh, kh[0], kh[2]);
            mma16816(acc[0], qh, kl[0], kl[2]);
            mma16816(acc[0], ql, kh[0], kh[2]);
            mma16816(acc[1], qh, kh[1], kh[3]);
            mma16816(acc[1], qh, kl[1], kl[3]);
            mma16816(acc[1], ql, kh[1], kh[3]);
            uint32_t kh2[4], kl2[4];
            ldm4(kh2, kh_a + 16 * (QST * 2) + ks * 32);
            ldm4(kl2, kl_a + 16 * (QST * 2) + ks * 32);
            mma16816(acc[2], qh, kh2[0], kh2[2]);
            mma16816(acc[2], qh, kl2[0], kl2[2]);
            mma16816(acc[2], ql, kh2[0], kh2[2]);
            mma16816(acc[3], qh, kh2[1], kh2[3]);
            mma16816(acc[3], qh, kl2[1], kl2[3]);
            mma16816(acc[3], ql, kh2[1], kh2[3]);
        }
    }
    int row0 = (mt << 4) + g;
#pragma unroll
    for (int nt = 0; nt < 4; nt++) {
        int col = ((nt & 1) << 3) + ((nt >> 1) << 4) + (tig << 1);
        psum[((kg << 5) + row0) * 32 + col] = acc[nt][0];
        psum[((kg << 5) + row0) * 32 + col + 1] = acc[nt][1];
        psum[((kg << 5) + row0 + 8) * 32 + col] = acc[nt][2];
        psum[((kg << 5) + row0 + 8) * 32 + col + 1] = acc[nt][3];
    }
    __syncthreads();
    for (int idx = tid; idx < 1024; idx += 256) {
        int u = idx >> 5, v = idx & 31;
        if (u < 25 && v < 25) {
            float raw = psum[idx] + psum[1024 + idx] + psum[2048 + idx] +
                        psum[3072 + idx];
            int p = u * 25 + v;
            part[((size_t)z * 128 + n) * 1875 + p * 3 + s] = raw;
        }
    }
}

// ---------------------------------------------------------------------------
// att_s combine: sum 4 K-split partials, apply tanh*alpha + att0
// ---------------------------------------------------------------------------
__global__ void att_s2_kernel(const float* __restrict__ part,
                              const float* __restrict__ alphas,
                              const float* __restrict__ att0, float* __restrict__ attS) {
    int e = blockIdx.x * 256 + threadIdx.x;
    if (e >= 240000) return;
    float raw = part[e] + part[240000 + e] + part[480000 + e] + part[720000 + e];
    int s = e % 3;
    attS[e] = tanhf(raw * (1.f / 1024.f)) * alphas[s] + att0[e % 1875];
}

// ---------------------------------------------------------------------------
// mix_s via HMMA (round-11 proven)
// ---------------------------------------------------------------------------
#define MXA 40   // A smem stride (elems)
#define MXB 136  // B smem stride (elems)
__global__ void __launch_bounds__(256)
mix_s_hmma_kernel(const float* __restrict__ x, const float* __restrict__ attS,
                  float* __restrict__ ycat) {
    __shared__ __align__(16) __nv_bfloat16 sAh[80 * MXA], sAl[80 * MXA];
    __shared__ __align__(16) __nv_bfloat16 sBh[32 * MXB], sBl[32 * MXB];
    int n = blockIdx.x, ch = blockIdx.y;
    int tid = threadIdx.x, warp = tid >> 5, lane = tid & 31;
    int g = lane >> 2, tig = lane & 3;

    for (int i = tid; i < 1600; i += 256) {
        ((uint32_t*)sAh)[i] = 0u;
        ((uint32_t*)sAl)[i] = 0u;
    }
    for (int i = tid; i < 7 * 68; i += 256) {
        int u = 25 + i / 68, c2 = (i % 68);
        ((uint32_t*)(sBh + u * MXB))[c2] = 0u;
        ((uint32_t*)(sBl + u * MXB))[c2] = 0u;
    }
    __syncthreads();

    for (int e = tid; e < 1875; e += 256) {
        float a = attS[(size_t)n * 1875 + e];
        int u = e / 75, m = e - u * 75;
        float h = __bfloat162float(__float2bfloat16_rn(a));
        sAh[m * MXA + u] = __float2bfloat16_rn(h);
        sAl[m * MXA + u] = __float2bfloat16_rn(a - h);
    }
    for (int idx = tid; idx < 800; idx += 256) {
        int u = idx >> 5, c4 = (idx & 31) << 2;
        float4 v = *(const float4*)&x[((size_t)(n * 25 + u)) * 4096 + (ch << 7) + c4];
        float h0 = __bfloat162float(__float2bfloat16_rn(v.x));
        float h1 = __bfloat162float(__float2bfloat16_rn(v.y));
        float h2 = __bfloat162float(__float2bfloat16_rn(v.z));
        float h3 = __bfloat162float(__float2bfloat16_rn(v.w));
        *(uint2*)&sBh[u * MXB + c4] = make_uint2(pkbf(h0, h1), pkbf(h2, h3));
        *(uint2*)&sBl[u * MXB + c4] =
            make_uint2(pkbf(v.x - h0, v.y - h1), pkbf(v.z - h2, v.w - h3));
    }
    __syncthreads();

    uint32_t a_base = smem_u32(sAh) + (uint32_t)((lane & 15) * (MXA * 2) +
                                                 ((lane >> 4) << 4));
    uint32_t al_base = smem_u32(sAl) + (uint32_t)((lane & 15) * (MXA * 2) +
                                                  ((lane >> 4) << 4));
    uint32_t b_off = (uint32_t)(((lane & 7) + (lane & 8)) * (MXB * 2) +
                                (((warp << 4) + ((lane >> 4) << 3)) << 1));
    uint32_t bh_addr = smem_u32(sBh) + b_off;
    uint32_t bl_addr = smem_u32(sBl) + b_off;

    float acc[5][2][4];
#pragma unroll
    for (int mt = 0; mt < 5; mt++)
#pragma unroll
        for (int q = 0; q < 2; q++)
#pragma unroll
            for (int j = 0; j < 4; j++) acc[mt][q][j] = 0.f;

#pragma unroll
    for (int ks = 0; ks < 2; ks++) {
        uint32_t bh[4], bl[4];
        uint32_t ko = (uint32_t)(ks * 16 * (MXB * 2));
        ldm4t(bh, bh_addr + ko);
        ldm4t(bl, bl_addr + ko);
#pragma unroll
        for (int mt = 0; mt < 5; mt++) {
            uint32_t ah[4], al[4];
            uint32_t ao = (uint32_t)(mt * 16 * (MXA * 2) + ks * 32);
            ldm4(ah, a_base + ao);
            ldm4(al, al_base + ao);
            mma16816(acc[mt][0], ah, bh[0], bh[1]);
            mma16816(acc[mt][0], ah, bl[0], bl[1]);
            mma16816(acc[mt][0], al, bh[0], bh[1]);
            mma16816(acc[mt][1], ah, bh[2], bh[3]);
            mma16816(acc[mt][1], ah, bl[2], bl[3]);
            mma16816(acc[mt][1], al, bh[2], bh[3]);
        }
    }

#pragma unroll
    for (int mt = 0; mt < 5; mt++) {
#pragma unroll
        for (int nt8 = 0; nt8 < 2; nt8++) {
            int col = (warp << 4) + (nt8 << 3) + (tig << 1);
            int tc = (ch << 7) + col;
            int t = tc >> 6, c = tc & 63;
#pragma unroll
            for (int h = 0; h < 2; h++) {
                int m = (mt << 4) + g + (h << 3);
                if (m < 75) {
                    int v = m / 3, s = m - 3 * v;
                    size_t oa = (((size_t)(n * 25 + v)) * 64 + t) * 192 + s * 64 + c;
                    *(float2*)&ycat[oa] =
                        make_float2(acc[mt][nt8][h << 1], acc[mt][nt8][(h << 1) + 1]);
                }
            }
        }
    }
}

// ---------------------------------------------------------------------------
// LayerNorm over (V,C) per (n,t) + residual + GELU; padded=1 -> conv z buffer.
// Warp-shuffle reduction (round-15 proven).
// ---------------------------------------------------------------------------
__global__ void ln_t_kernel(const float* __restrict__ in, const float* __restrict__ resid,
                            const float* __restrict__ gg, const float* __restrict__ bb,
                            float* __restrict__ out, int padded) {
    int grp = blockIdx.x;   // n*64+t
    int tid = threadIdx.x;
    int warp = tid >> 5, lane = tid & 31;
    __shared__ float wred[8];
    const float* ip = in + (size_t)grp * 1600;
    float vals[7];
    float s = 0.f;
#pragma unroll
    for (int r = 0; r < 7; r++) {
        int i = tid + (r << 8);
        vals[r] = (i < 1600) ? ip[i] : 0.f;
        s += vals[r];
    }
#pragma unroll
    for (int o = 16; o; o >>= 1) s += __shfl_xor_sync(0xffffffffu, s, o);
    if (lane == 0) wred[warp] = s;
    __syncthreads();
    float mean = (wred[0] + wred[1] + wred[2] + wred[3] +
                  wred[4] + wred[5] + wred[6] + wred[7]) * (1.f / 1600.f);
    float sq = 0.f;
#pragma unroll
    for (int r = 0; r < 7; r++) {
        int i = tid + (r << 8);
        float d = (i < 1600) ? (vals[r] - mean) : 0.f;
        sq += d * d;
    }
#pragma unroll
    for (int o = 16; o; o >>= 1) sq += __shfl_xor_sync(0xffffffffu, sq, o);
    __syncthreads();   // wred reuse: all reads of pass-1 done
    if (lane == 0) wred[warp] = sq;
    __syncthreads();
    float inv = rsqrtf((wred[0] + wred[1] + wred[2] + wred[3] +
                        wred[4] + wred[5] + wred[6] + wred[7]) * (1.f / 1600.f) + 1e-5f);
    const float* rp = resid + (size_t)grp * 1600;
    int n = grp >> 6, t = grp & 63;
    size_t obase = padded ? ((size_t)(n * TPAD + 3 + t) * 1600) : ((size_t)grp * 1600);
#pragma unroll
    for (int r = 0; r < 7; r++) {
        int i = tid + (r << 8);
        if (i < 1600) {
            float y = (vals[r] - mean) * inv * gg[i] + bb[i];
            out[obase + i] = gelu_f(rp[i] + y);
        }
    }
}

// ---------------------------------------------------------------------------
// Temporal attention via HMMA (round-8 proven)
// ---------------------------------------------------------------------------
#define BST 88
__global__ void __launch_bounds__(256)
att_t_hmma_kernel(const float* __restrict__ qkt, const float* __restrict__ af,
                  const float* __restrict__ ab, float* __restrict__ attO) {
    __shared__ __align__(16) __nv_bfloat16 sQh[64 * BST], sQl[64 * BST];
    __shared__ __align__(16) __nv_bfloat16 sKh[64 * BST], sKl[64 * BST];
    int n = blockIdx.x, combo = blockIdx.y;
    int dir = combo >> 1, s = combo & 1;
    int jq = (dir * 2 + s) << 4, jk = (4 + dir * 2 + s) << 4;
    int tid = threadIdx.x, warp = tid >> 5, lane = tid & 31;
    int g = lane >> 2, tig = lane & 3;
    int mtile = warp & 3, nbase = (warp >> 2) << 5;
    float acc[4][4];
#pragma unroll
    for (int i = 0; i < 4; i++)
#pragma unroll
        for (int j = 0; j < 4; j++) acc[i][j] = 0.f;

    const float* base = qkt + (size_t)n * 204800;
    uint32_t q_off = (uint32_t)((((mtile << 4) + (lane & 15)) * (BST * 2)) +
                                ((lane >> 4) << 4));
    uint32_t k_off = (uint32_t)(((nbase + (lane & 15)) * (BST * 2)) +
                                ((lane >> 4) << 4));
    uint32_t qh_a = smem_u32(sQh) + q_off, ql_a = smem_u32(sQl) + q_off;
    uint32_t kh_a = smem_u32(sKh) + k_off, kl_a = smem_u32(sKl) + k_off;

    for (int vc = 0; vc < 5; vc++) {
        for (int idx = tid; idx < 2560; idx += 256) {
            int half = idx >= 1280;
            int id = idx - (half ? 1280 : 0);
            int t = id / 20, cq = id - t * 20;
            int vi = cq >> 2, icq = (cq & 3) << 2;
            const float* p = base + (size_t)(t * 25 + vc * 5 + vi) * 128 +
                             (half ? jk : jq) + icq;
            float4 v = *(const float4*)p;
            float h0 = __bfloat162float(__float2bfloat16_rn(v.x));
            float h1 = __bfloat162float(__float2bfloat16_rn(v.y));
            float h2 = __bfloat162float(__float2bfloat16_rn(v.z));
            float h3 = __bfloat162float(__float2bfloat16_rn(v.w));
            int so = t * BST + (vi << 4) + icq;
            if (half) {
                *(uint2*)&sKh[so] = make_uint2(pkbf(h0, h1), pkbf(h2, h3));
                *(uint2*)&sKl[so] = make_uint2(pkbf(v.x - h0, v.y - h1),
                                               pkbf(v.z - h2, v.w - h3));
            } else {
                *(uint2*)&sQh[so] = make_uint2(pkbf(h0, h1), pkbf(h2, h3));
                *(uint2*)&sQl[so] = make_uint2(pkbf(v.x - h0, v.y - h1),
                                               pkbf(v.z - h2, v.w - h3));
            }
        }
        __syncthreads();
#pragma unroll
        for (int ks = 0; ks < 5; ks++) {
            uint32_t qh[4], ql[4];
            ldm4(qh, qh_a + ks * 32);
            ldm4(ql, ql_a + ks * 32);
            uint32_t kh[4], kl[4];
            ldm4(kh, kh_a + ks * 32);
            ldm4(kl, kl_a + ks * 32);
            mma16816(acc[0], qh, kh[0], kh[2]);
            mma16816(acc[0], qh, kl[0], kl[2]);
            mma16816(acc[0], ql, kh[0], kh[2]);
            mma16816(acc[1], qh, kh[1], kh[3]);
            mma16816(acc[1], qh, kl[1], kl[3]);
            mma16816(acc[1], ql, kh[1], kh[3]);
            uint32_t kh2[4], kl2[4];
            ldm4(kh2, kh_a + 16 * (BST * 2) + ks * 32);
            ldm4(kl2, kl_a + 16 * (BST * 2) + ks * 32);
            mma16816(acc[2], qh, kh2[0], kh2[2]);
            mma16816(acc[2], qh, kl2[0], kl2[2]);
            mma16816(acc[2], ql, kh2[0], kh2[2]);
            mma16816(acc[3], qh, kh2[1], kh2[3]);
            mma16816(acc[3], qh, kl2[1], kl2[3]);
            mma16816(acc[3], ql, kh2[1], kh2[3]);
        }
        __syncthreads();
    }
    float alpha = dir ? ab[s] : af[s];
    size_t ob = ((size_t)n * 4 + combo) << 12;
    int t0 = (mtile << 4) + g;
#pragma unroll
    for (int nt = 0; nt < 4; nt++) {
        int q = nbase + ((nt & 1) << 3) + ((nt >> 1) << 4) + (tig << 1);
        float v00 = tanhf(acc[nt][0] * (1.f / 400.f)) * alpha;
        float v01 = tanhf(acc[nt][1] * (1.f / 400.f)) * alpha;
        float v10 = tanhf(acc[nt][2] * (1.f / 400.f)) * alpha;
        float v11 = tanhf(acc[nt][3] * (1.f / 400.f)) * alpha;
        int t1 = t0 + 8;
        bool k00 = dir ? (q >= t0) : (t0 >= q);
        bool k01 = dir ? (q + 1 >= t0) : (t0 >= q + 1);
        bool k10 = dir ? (q >= t1) : (t1 >= q);
        bool k11 = dir ? (q + 1 >= t1) : (t1 >= q + 1);
        *(float2*)&attO[ob + (t0 << 6) + q] =
            make_float2(k00 ? v00 : 0.f, k01 ? v01 : 0.f);
        *(float2*)&attO[ob + (t1 << 6) + q] =
            make_float2(k10 ? v10 : 0.f, k11 ? v11 : 0.f);
    }
}

// ---------------------------------------------------------------------------
// mix_t via HMMA (round-8 proven)
// ---------------------------------------------------------------------------
__global__ void __launch_bounds__(256)
mix_t_hmma_kernel(const float* __restrict__ attT_g, const float* __restrict__ yt,
                  float* __restrict__ zcat) {
    __shared__ __align__(16) __nv_bfloat16 sAh[64 * AST], sAl[64 * AST];
    __shared__ __align__(16) __nv_bfloat16 sBh[64 * AST], sBl[64 * AST];
    int n = blockIdx.x, combo = blockIdx.y, vg = blockIdx.z;
    int tid = threadIdx.x, warp = tid >> 5, lane = tid & 31;
    int g = lane >> 2, tig = lane & 3;
    int mtile = warp & 3, nbase = (warp >> 2) << 5;

    const float* ap = attT_g + (((size_t)n * 4 + combo) << 12);
    for (int i = tid; i < 1024; i += 256) {
        int t = i >> 4, q4 = (i & 15) << 2;
        float4 v = *(const float4*)&ap[(t << 6) + q4];
        float h0 = __bfloat162float(__float2bfloat16_rn(v.x));
        float h1 = __bfloat162float(__float2bfloat16_rn(v.y));
        float h2 = __bfloat162float(__float2bfloat16_rn(v.z));
        float h3 = __bfloat162float(__float2bfloat16_rn(v.w));
        sAh[(q4 + 0) * AST + t] = __float2bfloat16_rn(h0);
        sAh[(q4 + 1) * AST + t] = __float2bfloat16_rn(h1);
        sAh[(q4 + 2) * AST + t] = __float2bfloat16_rn(h2);
        sAh[(q4 + 3) * AST + t] = __float2bfloat16_rn(h3);
        sAl[(q4 + 0) * AST + t] = __float2bfloat16_rn(v.x - h0);
        sAl[(q4 + 1) * AST + t] = __float2bfloat16_rn(v.y - h1);
        sAl[(q4 + 2) * AST + t] = __float2bfloat16_rn(v.z - h2);
        sAl[(q4 + 3) * AST + t] = __float2bfloat16_rn(v.w - h3);
    }

    uint32_t a_off = (uint32_t)(((mtile << 4) + (lane & 15)) * (AST * 2) +
                                ((lane >> 4) << 4));
    uint32_t ah_addr = smem_u32(sAh) + a_off;
    uint32_t al_addr = smem_u32(sAl) + a_off;
    uint32_t b_off = (uint32_t)(((lane & 7) + (lane & 8)) * (AST * 2) +
                                ((nbase + ((lane >> 4) << 3)) << 1));
    uint32_t bh_addr = smem_u32(sBh) + b_off;
    uint32_t bl_addr = smem_u32(sBl) + b_off;

    for (int vi = 0; vi < 5; vi++) {
        int v = vg * 5 + vi;
        for (int i = tid; i < 1024; i += 256) {
            int t = i >> 4, c4 = (i & 15) << 2;
            float4 w = *(const float4*)&yt[((size_t)(n * 64 + t) * 25 + v) * 64 + c4];
            float h0 = __bfloat162float(__float2bfloat16_rn(w.x));
            float h1 = __bfloat162float(__float2bfloat16_rn(w.y));
            float h2 = __bfloat162float(__float2bfloat16_rn(w.z));
            float h3 = __bfloat162float(__float2bfloat16_rn(w.w));
            *(uint2*)&sBh[t * AST + c4] =
                make_uint2(pkbf(h0, h1), pkbf(h2, h3));
            *(uint2*)&sBl[t * AST + c4] =
                make_uint2(pkbf(w.x - h0, w.y - h1), pkbf(w.z - h2, w.w - h3));
        }
        __syncthreads();
        float acc[4][4];
#pragma unroll
        for (int i = 0; i < 4; i++)
#pragma unroll
            for (int j = 0; j < 4; j++) acc[i][j] = 0.f;
#pragma unroll
        for (int ks = 0; ks < 4; ks++) {
            uint32_t a_h[4], a_l[4];
            ldm4(a_h, ah_addr + ks * 32);
            ldm4(a_l, al_addr + ks * 32);
#pragma unroll
            for (int nt2 = 0; nt2 < 2; nt2++) {
                uint32_t bh[4], bl[4];
                uint32_t ko = (uint32_t)(ks * 16 * (AST * 2) + nt2 * 32);
                ldm4t(bh, bh_addr + ko);
                ldm4t(bl, bl_addr + ko);
                mma16816(acc[nt2 * 2 + 0], a_h, bh[0], bh[1]);
                mma16816(acc[nt2 * 2 + 0], a_h, bl[0], bl[1]);
                mma16816(acc[nt2 * 2 + 0], a_l, bh[0], bh[1]);
                mma16816(acc[nt2 * 2 + 1], a_h, bh[2], bh[3]);
                mma16816(acc[nt2 * 2 + 1], a_h, bl[2], bl[3]);
                mma16816(acc[nt2 * 2 + 1], a_l, bh[2], bh[3]);
            }
        }
        int q0 = (mtile << 4) + g;
        size_t ob0 = (((size_t)(n * 64 + q0) * 25 + v) << 8) + (combo << 6);
        size_t ob1 = (((size_t)(n * 64 + q0 + 8) * 25 + v) << 8) + (combo << 6);
#pragma unroll
        for (int nt = 0; nt < 4; nt++) {
            int col = nbase + (nt << 3) + (tig << 1);
            *(float2*)&zcat[ob0 + col] = make_float2(acc[nt][0], acc[nt][1]);
            *(float2*)&zcat[ob1 + col] = make_float2(acc[nt][2], acc[nt][3]);
        }
        __syncthreads();
    }
}

// ---------------------------------------------------------------------------
// BN apply + residual + GELU + final transpose to output (n,v,t,c)
// float4-vectorized: one thread handles 4 consecutive c's.
// ---------------------------------------------------------------------------
__global__ void bn_final_kernel(const float* __restrict__ z, const float* __restrict__ z1,
                                const float* __restrict__ bg, const float* __restrict__ bb,
                                float* __restrict__ out) {
    size_t e4 = (size_t)blockIdx.x * 256 + threadIdx.x;   // over 3,276,800
    int c = (int)((e4 & 15) << 2);
    size_t r = e4 >> 4;            // (n*25+v)*64+t
    int t = (int)(r & 63);
    size_t r2 = r >> 6;
    int v = (int)(r2 % 25);
    int n = (int)(r2 / 25);
    size_t paddr = ((size_t)(n * TPAD + 3 + t) * 25 + v) * 64 + c;
    float4 zv = *(const float4*)&z[paddr];
    float4 z1v = *(const float4*)&z1[paddr];
    float4 mg = *(const float4*)&bg[c];
    float4 mb = *(const float4*)&bb[c];
    float4 ms = *(const float4*)&g_bnstats[c];
    float4 mq = *(const float4*)&g_bnstats[64 + c];
    float4 o;
    {
        float mean = ms.x * (1.f / 204800.f);
        float var = mq.x * (1.f / 204800.f) - mean * mean;
        o.x = gelu_f(zv.x + (z1v.x - mean) * rsqrtf(var + 1e-5f) * mg.x + mb.x);
        mean = ms.y * (1.f / 204800.f);
        var = mq.y * (1.f / 204800.f) - mean * mean;
        o.y = gelu_f(zv.y + (z1v.y - mean) * rsqrtf(var + 1e-5f) * mg.y + mb.y);
        mean = ms.z * (1.f / 204800.f);
        var = mq.z * (1.f / 204800.f) - mean * mean;
        o.z = gelu_f(zv.z + (z1v.z - mean) * rsqrtf(var + 1e-5f) * mg.z + mb.z);
        mean = ms.w * (1.f / 204800.f);
        var = mq.w * (1.f / 204800.f) - mean * mean;
        o.w = gelu_f(zv.w + (z1v.w - mean) * rsqrtf(var + 1e-5f) * mg.w + mb.w);
    }
    *(float4*)&out[(r << 6) + c] = o;
}

// ---------------------------------------------------------------------------
// Host launcher
// ---------------------------------------------------------------------------
extern "C" void kernel_launch(void* const* d_in, const int* in_sizes, int n_in,
                              void* d_out, int out_size) {
    const float* x          = (const float*)d_in[0];
    const float* w_in_s     = (const float*)d_in[1];
    const float* b_in_s     = (const float*)d_in[2];
    const float* alphas     = (const float*)d_in[3];
    const float* att0s      = (const float*)d_in[4];
    const float* w_out_s    = (const float*)d_in[5];
    const float* b_out_s    = (const float*)d_in[6];
    const float* ln_out_s_g = (const float*)d_in[7];
    const float* ln_out_s_b = (const float*)d_in[8];
    const float* w_ff_s     = (const float*)d_in[9];
    const float* b_ff_s     = (const float*)d_in[10];
    const float* ln_ff_s_g  = (const float*)d_in[11];
    const float* ln_ff_s_b  = (const float*)d_in[12];
    const float* w_in_t     = (const float*)d_in[13];
    const float* b_in_t     = (const float*)d_in[14];
    const float* alphat_f   = (const float*)d_in[15];
    const float* alphat_b   = (const float*)d_in[16];
    const float* w_out_t    = (const float*)d_in[17];
    const float* b_out_t    = (const float*)d_in[18];
    const float* ln_out_t_g = (const float*)d_in[19];
    const float* ln_out_t_b = (const float*)d_in[20];
    const float* w_ff_t     = (const float*)d_in[21];
    const float* b_ff_t     = (const float*)d_in[22];
    const float* ln_ff_t_g  = (const float*)d_in[23];
    const float* ln_ff_t_b  = (const float*)d_in[24];
    const float* conv_w     = (const float*)d_in[25];
    const float* conv_b     = (const float*)d_in[26];
    const float* bn_g       = (const float*)d_in[27];
    const float* bn_b       = (const float*)d_in[28];
    float* out = (float*)d_out;

    float *bufA, *bufB, *bufC, *bufD, *bufE, *bufF, *attS, *attT, *bis, *bit;
    cudaGetSymbolAddress((void**)&bufA, g_bufA);
    cudaGetSymbolAddress((void**)&bufB, g_bufB);
    cudaGetSymbolAddress((void**)&bufC, g_bufC);
    cudaGetSymbolAddress((void**)&bufD, g_bufD);
    cudaGetSymbolAddress((void**)&bufE, g_bufE);
    cudaGetSymbolAddress((void**)&bufF, g_bufF);
    cudaGetSymbolAddress((void**)&attS, g_attS);
    cudaGetSymbolAddress((void**)&attT, g_attT);
    cudaGetSymbolAddress((void**)&bis, g_bis);
    cudaGetSymbolAddress((void**)&bit, g_bit);
    uint4 *Fqk, *Fouts, *Fffs, *Fint, *Foutt, *Ffft, *Fconv;
    cudaGetSymbolAddress((void**)&Fqk, g_Fqk);
    cudaGetSymbolAddress((void**)&Fouts, g_Fouts);
    cudaGetSymbolAddress((void**)&Fffs, g_Fffs);
    cudaGetSymbolAddress((void**)&Fint, g_Fint);
    cudaGetSymbolAddress((void**)&Foutt, g_Foutt);
    cudaGetSymbolAddress((void**)&Ffft, g_Ffft);
    cudaGetSymbolAddress((void**)&Fconv, g_Fconv);
    float* zbase = bufF + GUARD;

    cudaFuncSetAttribute(att_s_hmma_kernel,
                         cudaFuncAttributeMaxDynamicSharedMemorySize, 51200);

    prep_kernel<<<28, 256>>>(w_in_s, b_in_s, w_out_s, w_ff_s, w_in_t, b_in_t,
                             w_out_t, w_ff_t, conv_w);
    zero_pads_kernel<<<4800, 256>>>(zbase);

    // ---- spatial stage ----
    mma_gemm_qk_kernel<<<1600, 256>>>(x, Fqk, bis, bufB, 64);
    att_s_hmma_kernel<<<dim3(NN, 3, 4), 256, 51200>>>(bufB, bufC);
    att_s2_kernel<<<938, 256>>>(bufC, alphas, att0s, attS);
    mix_s_hmma_kernel<<<dim3(NN, 32), 256>>>(x, attS, bufA);
    mma_gemm_lns_kernel<0><<<1600, 256>>>(bufA, Fouts, b_out_s, x,
                                          ln_out_s_g, ln_out_s_b, bufD, 192);
    mma_gemm_lns_kernel<1><<<1600, 256>>>(bufD, Fffs, b_ff_s, x,
                                          ln_ff_s_g, ln_ff_s_b, bufE, 64);

    // ---- temporal stage ----
    mma_gemm_kernel<128><<<1600, 256>>>(bufE, Fint, bit, bufB, 64);
    att_t_hmma_kernel<<<dim3(NN, 4), 256>>>(bufB, alphat_f, alphat_b, attT);
    mix_t_hmma_kernel<<<dim3(NN, 4, 5), 256>>>(attT, bufE, bufA);
    mma_gemm_kernel<64><<<1600, 256>>>(bufA, Foutt, b_out_t, bufC, 256);
    ln_t_kernel<<<8192, 256>>>(bufC, bufE, ln_out_t_g, ln_out_t_b, bufD, 0);
    mma_gemm_kernel<64><<<1600, 256>>>(bufD, Ffft, b_ff_t, bufC, 64);
    ln_t_kernel<<<8192, 256>>>(bufC, bufE, ln_ff_t_g, ln_ff_t_b, zbase, 1);

    // ---- conv + batchnorm + output ----
    mma_gemm_conv_kernel<<<1750, 256>>>(zbase, Fconv, conv_b, bufD, 448);
    bn_final_kernel<<<12800, 256>>>(zbase, bufD, bn_g, bn_b, out);
}

// round 17
// speedup vs baseline: 1.0652x; 1.0022x over previous
#include <cuda_runtime.h>
#include <cuda_bf16.h>
#include <math.h>
#include <stdint.h>

// ---------------------------------------------------------------------------
// Problem constants: x (N=128, V=25, T=64, C=64), IC=16, S=3, TS=2
// ---------------------------------------------------------------------------
#define NN 128
#define NVT 204800          // N*V*T == N*T*V
#define TPAD 70             // T + 6 (conv halo)
#define MPAD 224000         // N*TPAD*V rows for padded z
#define GUARD 4800          // 3*V*C guard floats (75 rows) before/after padded z
#define QKOFF 9830400       // 128*3*25600 floats (Q region size; K follows)

// ---------------------------------------------------------------------------
// Scratch (static device globals; no runtime allocation allowed)
// ---------------------------------------------------------------------------
__device__ float g_bufA[(size_t)NVT * 256];                 // ycat / zcat
__device__ float g_bufB[(size_t)NVT * 128];                 // Q/K (spatial) / qkt
__device__ float g_bufC[(size_t)NVT * 64];                  // gemm outputs / att_s partials
__device__ float g_bufD[(size_t)NVT * 64];                  // y1 / z-mid / conv out
__device__ float g_bufE[(size_t)NVT * 64];                  // y transposed (n,t,v,c)
__device__ float g_bufF[GUARD + (size_t)MPAD * 64 + GUARD]; // padded z + guards
__device__ float g_attS[(size_t)NN * 625 * 3];
__device__ float g_attT[(size_t)NN * 4 * 64 * 64];
__device__ float g_bis[96];                                 // b_in_s col-permuted
__device__ float g_bit[128];                                // b_in_t col-permuted
__device__ float g_bnstats[128];                            // sum[64], sumsq[64]

// Pre-packed mma.sync B fragments: per (k16-chunk, ntile, lane) a uint4 =
// {b_hi_reg0, b_hi_reg1, b_lo_reg0, b_lo_reg1}
__device__ uint4 g_Fqk[4 * 12 * 32];      // K=64,  Nc=96
__device__ uint4 g_Fouts[12 * 8 * 32];    // K=192, Nc=64
__device__ uint4 g_Fffs[4 * 8 * 32];      // K=64,  Nc=64
__device__ uint4 g_Fint[4 * 16 * 32];     // K=64,  Nc=128 (col-permuted j*16+ic)
__device__ uint4 g_Foutt[16 * 8 * 32];    // K=256, Nc=64
__device__ uint4 g_Ffft[4 * 8 * 32];      // K=64,  Nc=64
__device__ uint4 g_Fconv[28 * 8 * 32];    // K=448, Nc=64

__device__ __forceinline__ float gelu_f(float x) {
    return 0.5f * x * (1.f + erff(x * 0.70710678118654752f));
}

__device__ __forceinline__ uint32_t smem_u32(const void* p) {
    uint32_t a;
    asm("{ .reg .u64 t; cvta.to.shared.u64 t, %1; cvt.u32.u64 %0, t; }" : "=r"(a) : "l"(p));
    return a;
}
__device__ __forceinline__ void ldm4(uint32_t* r, uint32_t addr) {
    asm volatile("ldmatrix.sync.aligned.m8n8.x4.shared.b16 {%0,%1,%2,%3}, [%4];"
                 : "=r"(r[0]), "=r"(r[1]), "=r"(r[2]), "=r"(r[3]) : "r"(addr));
}
__device__ __forceinline__ void ldm4t(uint32_t* r, uint32_t addr) {
    asm volatile("ldmatrix.sync.aligned.m8n8.x4.trans.shared.b16 {%0,%1,%2,%3}, [%4];"
                 : "=r"(r[0]), "=r"(r[1]), "=r"(r[2]), "=r"(r[3]) : "r"(addr));
}
__device__ __forceinline__ void mma16816(float* c, const uint32_t* a,
                                         uint32_t b0, uint32_t b1) {
    asm volatile(
        "mma.sync.aligned.m16n8k16.row.col.f32.bf16.bf16.f32 "
        "{%0,%1,%2,%3}, {%4,%5,%6,%7}, {%8,%9}, {%0,%1,%2,%3};"
        : "+f"(c[0]), "+f"(c[1]), "+f"(c[2]), "+f"(c[3])
        : "r"(a[0]), "r"(a[1]), "r"(a[2]), "r"(a[3]), "r"(b0), "r"(b1));
}
__device__ __forceinline__ uint32_t pkbf(float a, float b) {
    __nv_bfloat162 t = __floats2bfloat162_rn(a, b);
    return *(uint32_t*)&t;
}

// ---------------------------------------------------------------------------
// Prep: build B fragments (hi/lo split, permuted), permuted biases, zero bn
// ---------------------------------------------------------------------------
__device__ __forceinline__ void mk_frag(uint4* dst, int i, int NT,
                                        float w00, float w01, float w10, float w11) {
    float h00 = __bfloat162float(__float2bfloat16_rn(w00));
    float h01 = __bfloat162float(__float2bfloat16_rn(w01));
    float h10 = __bfloat162float(__float2bfloat16_rn(w10));
    float h11 = __bfloat162float(__float2bfloat16_rn(w11));
    dst[i] = make_uint4(pkbf(h00, h01), pkbf(h10, h11),
                        pkbf(w00 - h00, w01 - h01), pkbf(w10 - h10, w11 - h11));
}
#define FRAG_IDX(NT) \
    int lane = i & 31, nt = (i >> 5) % (NT), kc = (i >> 5) / (NT); \
    int g = lane >> 2, tig = lane & 3; \
    int n = nt * 8 + g; int k0 = kc * 16 + 2 * tig; (void)kc;

__global__ void prep_kernel(const float* __restrict__ wqk, const float* __restrict__ bqk,
                            const float* __restrict__ ws, const float* __restrict__ wffs,
                            const float* __restrict__ wint, const float* __restrict__ bint,
                            const float* __restrict__ wt,
                            const float* __restrict__ wfft, const float* __restrict__ cw) {
    int i = blockIdx.x * 256 + threadIdx.x;
    if (i < 4 * 12 * 32) {     // qk: Nc=96, K=64
        FRAG_IDX(12)
        int cc = (n < 48) ? n : n - 48;
        int s = cc >> 4, ic = cc & 15;
        int old = ic * 6 + s + ((n < 48) ? 0 : 3);
        mk_frag(g_Fqk, i, 12,
                wqk[k0 * 96 + old], wqk[(k0 + 1) * 96 + old],
                wqk[(k0 + 8) * 96 + old], wqk[(k0 + 9) * 96 + old]);
    }
    if (i < 96) {
        int cc = (i < 48) ? i : i - 48;
        int s = cc >> 4, ic = cc & 15;
        g_bis[i] = bqk[ic * 6 + s + ((i < 48) ? 0 : 3)];
    }
    if (i < 128) {             // in_t bias: new col n = j*16+ic -> old ic*8+j
        int j = i >> 4, ic = i & 15;
        g_bit[i] = bint[ic * 8 + j];
    }
    if (i < 12 * 8 * 32) {     // out_s: k = s*64+c -> orig row c*3+s, Nc=64
        FRAG_IDX(8)
        float w[4];
#pragma unroll
        for (int e = 0; e < 4; e++) {
            int k = k0 + (e >> 1) * 8 + (e & 1);
            int s = k >> 6, c = k & 63;
            w[e] = ws[(c * 3 + s) * 64 + n];
        }
        mk_frag(g_Fouts, i, 8, w[0], w[1], w[2], w[3]);
    }
    if (i < 4 * 8 * 32) {      // ff_s / ff_t: [K=64][64]
        FRAG_IDX(8)
        mk_frag(g_Fffs, i, 8, wffs[k0 * 64 + n], wffs[(k0 + 1) * 64 + n],
                wffs[(k0 + 8) * 64 + n], wffs[(k0 + 9) * 64 + n]);
        mk_frag(g_Ffft, i, 8, wfft[k0 * 64 + n], wfft[(k0 + 1) * 64 + n],
                wfft[(k0 + 8) * 64 + n], wfft[(k0 + 9) * 64 + n]);
    }
    if (i < 4 * 16 * 32) {     // in_t: [K=64][128], cols permuted n=j*16+ic
        FRAG_IDX(16)
        int j = n >> 4, ic = n & 15;
        int old = ic * 8 + j;
        mk_frag(g_Fint, i, 16, wint[k0 * 128 + old], wint[(k0 + 1) * 128 + old],
                wint[(k0 + 8) * 128 + old], wint[(k0 + 9) * 128 + old]);
    }
    if (i < 16 * 8 * 32) {     // out_t: k = dir*128+s*64+c -> orig dir*128+c*2+s
        FRAG_IDX(8)
        float w[4];
#pragma unroll
        for (int e = 0; e < 4; e++) {
            int k = k0 + (e >> 1) * 8 + (e & 1);
            int dir = k >> 7, s = (k >> 6) & 1, c = k & 63;
            w[e] = wt[(dir * 128 + c * 2 + s) * 64 + n];
        }
        mk_frag(g_Foutt, i, 8, w[0], w[1], w[2], w[3]);
    }
    if (i < 28 * 8 * 32) {     // conv: k = dt*64+ci, orig (co,ci,dt)
        FRAG_IDX(8)
        float w[4];
#pragma unroll
        for (int e = 0; e < 4; e++) {
            int k = k0 + (e >> 1) * 8 + (e & 1);
            int dt = k >> 6, ci = k & 63;
            w[e] = cw[(n * 64 + ci) * 7 + dt];
        }
        mk_frag(g_Fconv, i, 8, w[0], w[1], w[2], w[3]);
    }
    if (i < 128) g_bnstats[i] = 0.f;
}

// float4-vectorized pad zeroing: 128*6*400 float4 = 307200
__global__ void zero_pads_kernel(float* __restrict__ zbase) {
    int e4 = blockIdx.x * 256 + threadIdx.x;   // over 307200
    int n = e4 / 2400, r = e4 - n * 2400;
    int k = r / 400, rem4 = (r - k * 400) << 2;
    int tp = (k < 3) ? k : (k + 64);          // pad rows {0,1,2,67,68,69}
    *(float4*)&zbase[((size_t)(n * TPAD + tp)) * 1600 + rem4] =
        make_float4(0.f, 0.f, 0.f, 0.f);
}

// ---------------------------------------------------------------------------
// Shared GEMM mainloop macro (MF=1, round-8 proven config): fp32 A -> bf16
// hi/lo smem, 3xHMMA per k16. 256 thr, 128-row M tile. B fragments in gmem.
// ---------------------------------------------------------------------------
#define AST 72   // smem bf16 row stride (144 B) -> conflict-free ldmatrix

#define GEMM_MAINLOOP(NT_, CONV_)                                                  \
    int tid = threadIdx.x, warp = tid >> 5, lane = tid & 31;                       \
    int g = lane >> 2, tig = lane & 3;                                             \
    int bm = blockIdx.x << 7;                                                      \
    int lda = (CONV_) ? 64 : K;                                                    \
    float acc[NT_][4];                                                             \
    _Pragma("unroll") for (int i_ = 0; i_ < NT_; i_++)                             \
        _Pragma("unroll") for (int j_ = 0; j_ < 4; j_++) acc[i_][j_] = 0.f;        \
    uint32_t arow_off =                                                            \
        (uint32_t)(((warp << 4) + (lane & 15)) * (AST * 2) + ((lane >> 4) << 4));  \
    uint32_t ah_addr = smem_u32(sAh) + arow_off;                                   \
    uint32_t al_addr = smem_u32(sAl) + arow_off;                                   \
    int crow = tid >> 1, ccol = (tid & 1) << 5;                                    \
    char* sh = (char*)sAh + crow * (AST * 2) + ccol * 2;                           \
    char* sl = (char*)sAl + crow * (AST * 2) + ccol * 2;                           \
    int chunks = K >> 6;                                                           \
    for (int ch = 0; ch < chunks; ch++) {                                          \
        long rshift = (CONV_) ? (long)(ch - 3) * 25 : 0;                           \
        int col0 = (CONV_) ? 0 : (ch << 6);                                        \
        const float* ap = A + ((long)bm + rshift + crow) * lda + col0 + ccol;      \
        _Pragma("unroll") for (int j = 0; j < 8; j++) {                            \
            float4 v = *(const float4*)(ap + (j << 2));                            \
            float hx = __bfloat162float(__float2bfloat16_rn(v.x));                 \
            float hy = __bfloat162float(__float2bfloat16_rn(v.y));                 \
            float hz = __bfloat162float(__float2bfloat16_rn(v.z));                 \
            float hw = __bfloat162float(__float2bfloat16_rn(v.w));                 \
            *(uint2*)(sh + (j << 3)) = make_uint2(pkbf(hx, hy), pkbf(hz, hw));     \
            *(uint2*)(sl + (j << 3)) =                                             \
                make_uint2(pkbf(v.x - hx, v.y - hy), pkbf(v.z - hz, v.w - hw));    \
        }                                                                          \
        __syncthreads();                                                           \
        _Pragma("unroll") for (int ks = 0; ks < 4; ks++) {                         \
            uint32_t a_h[4], a_l[4];                                               \
            ldm4(a_h, ah_addr + ks * 32);                                          \
            ldm4(a_l, al_addr + ks * 32);                                          \
            const uint4* Fp = F + ((size_t)((ch << 2) + ks) * NT_) * 32 + lane;    \
            _Pragma("unroll") for (int nt = 0; nt < NT_; nt++) {                   \
                uint4 bf = Fp[nt * 32];                                            \
                mma16816(acc[nt], a_h, bf.x, bf.y);                                \
                mma16816(acc[nt], a_h, bf.z, bf.w);                                \
                mma16816(acc[nt], a_l, bf.x, bf.y);                                \
            }                                                                      \
        }                                                                          \
        __syncthreads();                                                           \
    }

// ---------------------------------------------------------------------------
// Plain GEMM (in_t Nc=128, out_t/ff_t Nc=64)
// ---------------------------------------------------------------------------
template <int NC>
__global__ void __launch_bounds__(256)
mma_gemm_kernel(const float* __restrict__ A, const uint4* __restrict__ F,
                const float* __restrict__ bias, float* __restrict__ C, int K) {
    __shared__ __align__(16) __nv_bfloat16 sAh[128 * AST];
    __shared__ __align__(16) __nv_bfloat16 sAl[128 * AST];
    constexpr int NT = NC / 8;
    GEMM_MAINLOOP(NT, 0)
    size_t r0 = (size_t)bm + (warp << 4) + g;
#pragma unroll
    for (int nt = 0; nt < NT; nt++) {
        int col = (nt << 3) + (tig << 1);
        float bx = bias[col], by = bias[col + 1];
        *(float2*)&C[r0 * NC + col] = make_float2(acc[nt][0] + bx, acc[nt][1] + by);
        *(float2*)&C[(r0 + 8) * NC + col] = make_float2(acc[nt][2] + bx, acc[nt][3] + by);
    }
}

// ---------------------------------------------------------------------------
// qk GEMM (Nc=96) with att-friendly epilogue: Q at [(n*3+s)*25600 + u*1024 +
// t*16 + ic], K at +QKOFF.
// ---------------------------------------------------------------------------
__global__ void __launch_bounds__(256)
mma_gemm_qk_kernel(const float* __restrict__ A, const uint4* __restrict__ F,
                   const float* __restrict__ bias, float* __restrict__ QK, int K) {
    __shared__ __align__(16) __nv_bfloat16 sAh[128 * AST];
    __shared__ __align__(16) __nv_bfloat16 sAl[128 * AST];
    GEMM_MAINLOOP(12, 0)
    size_t r0 = (size_t)bm + (warp << 4) + g;
    int n = (int)(r0 / 1600);
    int rem = (int)(r0 - (size_t)n * 1600);
    int u = rem >> 6, t0 = rem & 63;
#pragma unroll
    for (int nt = 0; nt < 12; nt++) {
        int col = (nt << 3) + (tig << 1);
        float bx = bias[col], by = bias[col + 1];
        int half = col >= 48;
        int cc = col - (half ? 48 : 0);
        int s = cc >> 4, ic = cc & 15;
        float* dst = QK + (half ? QKOFF : 0) +
                     ((size_t)(n * 3 + s) * 25600) + u * 1024 + ic;
        *(float2*)&dst[t0 << 4] = make_float2(acc[nt][0] + bx, acc[nt][1] + by);
        *(float2*)&dst[(t0 + 8) << 4] = make_float2(acc[nt][2] + bx, acc[nt][3] + by);
    }
}

// ---------------------------------------------------------------------------
// GEMM + LayerNorm((T,C) groups of 64 rows) + residual + GELU fused epilogue.
// ---------------------------------------------------------------------------
template <int TRANSPOSE>
__global__ void __launch_bounds__(256)
mma_gemm_lns_kernel(const float* __restrict__ A, const uint4* __restrict__ F,
                    const float* __restrict__ bias, const float* __restrict__ resid,
                    const float* __restrict__ gg, const float* __restrict__ bb,
                    float* __restrict__ out, int K) {
    __shared__ __align__(16) __nv_bfloat16 sAh[128 * AST];
    __shared__ __align__(16) __nv_bfloat16 sAl[128 * AST];
    __shared__ float wsum[8], wsq[8];
    GEMM_MAINLOOP(8, 0)

    float vals[8][4];
    float psum = 0.f;
#pragma unroll
    for (int nt = 0; nt < 8; nt++) {
        int col = (nt << 3) + (tig << 1);
        float bx = bias[col], by = bias[col + 1];
        vals[nt][0] = acc[nt][0] + bx; vals[nt][1] = acc[nt][1] + by;
        vals[nt][2] = acc[nt][2] + bx; vals[nt][3] = acc[nt][3] + by;
        psum += vals[nt][0] + vals[nt][1] + vals[nt][2] + vals[nt][3];
    }
#pragma unroll
    for (int o = 16; o; o >>= 1) psum += __shfl_xor_sync(0xffffffffu, psum, o);
    if (lane == 0) wsum[warp] = psum;
    __syncthreads();
    int grp4 = (warp >> 2) << 2;
    float mean = (wsum[grp4] + wsum[grp4 + 1] + wsum[grp4 + 2] + wsum[grp4 + 3]) *
                 (1.f / 4096.f);
    float psq = 0.f;
#pragma unroll
    for (int nt = 0; nt < 8; nt++)
#pragma unroll
        for (int j = 0; j < 4; j++) { float d = vals[nt][j] - mean; psq += d * d; }
#pragma unroll
    for (int o = 16; o; o >>= 1) psq += __shfl_xor_sync(0xffffffffu, psq, o);
    if (lane == 0) wsq[warp] = psq;
    __syncthreads();
    float inv = rsqrtf((wsq[grp4] + wsq[grp4 + 1] + wsq[grp4 + 2] + wsq[grp4 + 3]) *
                           (1.f / 4096.f) + 1e-5f);

    size_t r0 = (size_t)bm + (warp << 4) + g;
    size_t r1 = r0 + 8;
    int tl0 = (int)(r0 & 63), tl1 = tl0 + 8;
    size_t oa0, oa1;
    if (TRANSPOSE) {
        int n0 = (int)(r0 / 1600), rem0 = (int)(r0 - (size_t)n0 * 1600);
        int v0 = rem0 >> 6;
        oa0 = ((size_t)(n0 * 64 + tl0) * 25 + v0) << 6;
        oa1 = ((size_t)(n0 * 64 + tl1) * 25 + v0) << 6;
    } else {
        oa0 = r0 << 6; oa1 = r1 << 6;
    }
#pragma unroll
    for (int nt = 0; nt < 8; nt++) {
        int col = (nt << 3) + (tig << 1);
        float2 g0 = *(const float2*)&gg[tl0 * 64 + col];
        float2 b0 = *(const float2*)&bb[tl0 * 64 + col];
        float2 g1 = *(const float2*)&gg[tl1 * 64 + col];
        float2 b1 = *(const float2*)&bb[tl1 * 64 + col];
        float2 rx0 = *(const float2*)&resid[(r0 << 6) + col];
        float2 rx1 = *(const float2*)&resid[(r1 << 6) + col];
        float2 o0, o1;
        o0.x = gelu_f(rx0.x + (vals[nt][0] - mean) * inv * g0.x + b0.x);
        o0.y = gelu_f(rx0.y + (vals[nt][1] - mean) * inv * g0.y + b0.y);
        o1.x = gelu_f(rx1.x + (vals[nt][2] - mean) * inv * g1.x + b1.x);
        o1.y = gelu_f(rx1.y + (vals[nt][3] - mean) * inv * g1.y + b1.y);
        *(float2*)&out[oa0 + col] = o0;
        *(float2*)&out[oa1 + col] = o1;
    }
}

// ---------------------------------------------------------------------------
// Conv implicit-GEMM (K=448, row-shifted A) + fused BN partial-sum reduce.
// ---------------------------------------------------------------------------
__global__ void __launch_bounds__(256)
mma_gemm_conv_kernel(const float* __restrict__ A, const uint4* __restrict__ F,
                     const float* __restrict__ bias, float* __restrict__ C, int K) {
    __shared__ __align__(16) __nv_bfloat16 sAh[128 * AST];
    __shared__ __align__(16) __nv_bfloat16 sAl[128 * AST];
    __shared__ float ss[64], sqq[64];
    if (threadIdx.x < 64) { ss[threadIdx.x] = 0.f; sqq[threadIdx.x] = 0.f; }
    GEMM_MAINLOOP(8, 1)

    size_t r0 = (size_t)bm + (warp << 4) + g;
    size_t r1 = r0 + 8;
    int rem0 = (int)(r0 % 1750), rem1 = (int)(r1 % 1750);
    bool va0 = (rem0 >= 75) && (rem0 < 1675);
    bool va1 = (rem1 >= 75) && (rem1 < 1675);
#pragma unroll
    for (int nt = 0; nt < 8; nt++) {
        int col = (nt << 3) + (tig << 1);
        float bx = bias[col], by = bias[col + 1];
        float v00 = acc[nt][0] + bx, v01 = acc[nt][1] + by;
        float v10 = acc[nt][2] + bx, v11 = acc[nt][3] + by;
        *(float2*)&C[(r0 << 6) + col] = make_float2(v00, v01);
        *(float2*)&C[(r1 << 6) + col] = make_float2(v10, v11);
        float s0 = (va0 ? v00 : 0.f) + (va1 ? v10 : 0.f);
        float s1 = (va0 ? v01 : 0.f) + (va1 ? v11 : 0.f);
        float q0 = (va0 ? v00 * v00 : 0.f) + (va1 ? v10 * v10 : 0.f);
        float q1 = (va0 ? v01 * v01 : 0.f) + (va1 ? v11 * v11 : 0.f);
        atomicAdd(&ss[col], s0); atomicAdd(&ss[col + 1], s1);
        atomicAdd(&sqq[col], q0); atomicAdd(&sqq[col + 1], q1);
    }
    __syncthreads();
    if (tid < 64) {
        atomicAdd(&g_bnstats[tid], ss[tid]);
        atomicAdd(&g_bnstats[64 + tid], sqq[tid]);
    }
}

// ---------------------------------------------------------------------------
// Spatial attention via HMMA, split-K z=4 (2 chunks each). One block per
// (n,s,z). Writes RAW partial 25x25 sums to part buffer. (round-12 proven)
// ---------------------------------------------------------------------------
#define QST 136   // bf16 row stride (272 B)
__global__ void __launch_bounds__(256)
att_s_hmma_kernel(const float* __restrict__ QK, float* __restrict__ part) {
    extern __shared__ char dsm[];
    __nv_bfloat16* sQh = (__nv_bfloat16*)dsm;
    __nv_bfloat16* sQl = (__nv_bfloat16*)(dsm + 8704);
    __nv_bfloat16* sKh = (__nv_bfloat16*)(dsm + 17408);
    __nv_bfloat16* sKl = (__nv_bfloat16*)(dsm + 26112);
    float* psum = (float*)(dsm + 34816);   // [4 kg][32 u][32 v]
    int n = blockIdx.x, s = blockIdx.y, z = blockIdx.z;
    int tid = threadIdx.x, warp = tid >> 5, lane = tid & 31;
    int g = lane >> 2, tig = lane & 3;
    int mt = warp & 1, kg = warp >> 1;

    for (int i = tid; i < 476; i += 256) {
        int u = 25 + i / 68, c2 = i % 68;
        ((uint32_t*)(sQh + u * QST))[c2] = 0u;
        ((uint32_t*)(sQl + u * QST))[c2] = 0u;
        ((uint32_t*)(sKh + u * QST))[c2] = 0u;
        ((uint32_t*)(sKl + u * QST))[c2] = 0u;
    }

    const float* Qb = QK + (size_t)(n * 3 + s) * 25600;
    const float* Kb = Qb + QKOFF;

    uint32_t q_off = (uint32_t)(((mt << 4) + (lane & 15)) * (QST * 2) +
                                ((lane >> 4) << 4));
    uint32_t k_off = (uint32_t)((lane & 15) * (QST * 2) + ((lane >> 4) << 4));
    uint32_t qh_a = smem_u32(sQh) + q_off, ql_a = smem_u32(sQl) + q_off;
    uint32_t kh_a = smem_u32(sKh) + k_off, kl_a = smem_u32(sKl) + k_off;

    float acc[4][4];
#pragma unroll
    for (int i = 0; i < 4; i++)
#pragma unroll
        for (int j = 0; j < 4; j++) acc[i][j] = 0.f;

    for (int cc = 0; cc < 2; cc++) {
        int ch = (z << 1) + cc;
        __syncthreads();
        for (int idx = tid; idx < 1600; idx += 256) {
            int half = idx >= 800;
            int id = idx - (half ? 800 : 0);
            int u = id >> 5, w = id & 31;
            const float* src = (half ? Kb : Qb) + u * 1024 + (ch << 7) + (w << 2);
            float4 v = *(const float4*)src;
            float h0 = __bfloat162float(__float2bfloat16_rn(v.x));
            float h1 = __bfloat162float(__float2bfloat16_rn(v.y));
            float h2 = __bfloat162float(__float2bfloat16_rn(v.z));
            float h3 = __bfloat162float(__float2bfloat16_rn(v.w));
            int so = u * QST + (w << 2);
            if (half) {
                *(uint2*)&sKh[so] = make_uint2(pkbf(h0, h1), pkbf(h2, h3));
                *(uint2*)&sKl[so] = make_uint2(pkbf(v.x - h0, v.y - h1),
                                               pkbf(v.z - h2, v.w - h3));
            } else {
                *(uint2*)&sQh[so] = make_uint2(pkbf(h0, h1), pkbf(h2, h3));
                *(uint2*)&sQl[so] = make_uint2(pkbf(v.x - h0, v.y - h1),
                                               pkbf(v.z - h2, v.w - h3));
            }
        }
        __syncthreads();
#pragma unroll
        for (int ks2 = 0; ks2 < 2; ks2++) {
            int ks = (kg << 1) + ks2;
            uint32_t qh[4], ql[4];
            ldm4(qh, qh_a + ks * 32);
            ldm4(ql, ql_a + ks * 32);
            uint32_t kh[4], kl[4];
            ldm4(kh, kh_a + ks * 32);
            ldm4(kl, kl_a + ks * 32);
            mma16816(acc[0], qh, kh[0], kh[2]);
            mma16816(acc[0], qh, kl[0], kl[2]);
            mma16816(acc[0], ql, kh[0], kh[2]);
            mma16816(acc[1], qh, kh[1], kh[3]);
            mma16816(acc[1], qh, kl[1], kl[3]);
            mma16816(acc[1], ql, kh[1], kh[3]);
            uint32_t kh2[4], kl2[4];
            ldm4(kh2, kh_a + 16 * (QST * 2) + ks * 32);
            ldm4(kl2, kl_a + 16 * (QST * 2) + ks * 32);
            mma16816(acc[2], qh, kh2[0], kh2[2]);
            mma16816(acc[2], qh, kl2[0], kl2[2]);
            mma16816(acc[2], ql, kh2[0], kh2[2]);
            mma16816(acc[3], qh, kh2[1], kh2[3]);
            mma16816(acc[3], qh, kl2[1], kl2[3]);
            mma16816(acc[3], ql, kh2[1], kh2[3]);
        }
    }
    int row0 = (mt << 4) + g;
#pragma unroll
    for (int nt = 0; nt < 4; nt++) {
        int col = ((nt & 1) << 3) + ((nt >> 1) << 4) + (tig << 1);
        psum[((kg << 5) + row0) * 32 + col] = acc[nt][0];
        psum[((kg << 5) + row0) * 32 + col + 1] = acc[nt][1];
        psum[((kg << 5) + row0 + 8) * 32 + col] = acc[nt][2];
        psum[((kg << 5) + row0 + 8) * 32 + col + 1] = acc[nt][3];
    }
    __syncthreads();
    for (int idx = tid; idx < 1024; idx += 256) {
        int u = idx >> 5, v = idx & 31;
        if (u < 25 && v < 25) {
            float raw = psum[idx] + psum[1024 + idx] + psum[2048 + idx] +
                        psum[3072 + idx];
            int p = u * 25 + v;
            part[((size_t)z * 128 + n) * 1875 + p * 3 + s] = raw;
        }
    }
}

// ---------------------------------------------------------------------------
// att_s combine: sum 4 K-split partials, apply tanh*alpha + att0
// ---------------------------------------------------------------------------
__global__ void att_s2_kernel(const float* __restrict__ part,
                              const float* __restrict__ alphas,
                              const float* __restrict__ att0, float* __restrict__ attS) {
    int e = blockIdx.x * 256 + threadIdx.x;
    if (e >= 240000) return;
    float raw = part[e] + part[240000 + e] + part[480000 + e] + part[720000 + e];
    int s = e % 3;
    attS[e] = tanhf(raw * (1.f / 1024.f)) * alphas[s] + att0[e % 1875];
}

// ---------------------------------------------------------------------------
// mix_s via HMMA (round-11 proven)
// ---------------------------------------------------------------------------
#define MXA 40   // A smem stride (elems)
#define MXB 136  // B smem stride (elems)
__global__ void __launch_bounds__(256)
mix_s_hmma_kernel(const float* __restrict__ x, const float* __restrict__ attS,
                  float* __restrict__ ycat) {
    __shared__ __align__(16) __nv_bfloat16 sAh[80 * MXA], sAl[80 * MXA];
    __shared__ __align__(16) __nv_bfloat16 sBh[32 * MXB], sBl[32 * MXB];
    int n = blockIdx.x, ch = blockIdx.y;
    int tid = threadIdx.x, warp = tid >> 5, lane = tid & 31;
    int g = lane >> 2, tig = lane & 3;

    for (int i = tid; i < 1600; i += 256) {
        ((uint32_t*)sAh)[i] = 0u;
        ((uint32_t*)sAl)[i] = 0u;
    }
    for (int i = tid; i < 7 * 68; i += 256) {
        int u = 25 + i / 68, c2 = (i % 68);
        ((uint32_t*)(sBh + u * MXB))[c2] = 0u;
        ((uint32_t*)(sBl + u * MXB))[c2] = 0u;
    }
    __syncthreads();

    for (int e = tid; e < 1875; e += 256) {
        float a = attS[(size_t)n * 1875 + e];
        int u = e / 75, m = e - u * 75;
        float h = __bfloat162float(__float2bfloat16_rn(a));
        sAh[m * MXA + u] = __float2bfloat16_rn(h);
        sAl[m * MXA + u] = __float2bfloat16_rn(a - h);
    }
    for (int idx = tid; idx < 800; idx += 256) {
        int u = idx >> 5, c4 = (idx & 31) << 2;
        float4 v = *(const float4*)&x[((size_t)(n * 25 + u)) * 4096 + (ch << 7) + c4];
        float h0 = __bfloat162float(__float2bfloat16_rn(v.x));
        float h1 = __bfloat162float(__float2bfloat16_rn(v.y));
        float h2 = __bfloat162float(__float2bfloat16_rn(v.z));
        float h3 = __bfloat162float(__float2bfloat16_rn(v.w));
        *(uint2*)&sBh[u * MXB + c4] = make_uint2(pkbf(h0, h1), pkbf(h2, h3));
        *(uint2*)&sBl[u * MXB + c4] =
            make_uint2(pkbf(v.x - h0, v.y - h1), pkbf(v.z - h2, v.w - h3));
    }
    __syncthreads();

    uint32_t a_base = smem_u32(sAh) + (uint32_t)((lane & 15) * (MXA * 2) +
                                                 ((lane >> 4) << 4));
    uint32_t al_base = smem_u32(sAl) + (uint32_t)((lane & 15) * (MXA * 2) +
                                                  ((lane >> 4) << 4));
    uint32_t b_off = (uint32_t)(((lane & 7) + (lane & 8)) * (MXB * 2) +
                                (((warp << 4) + ((lane >> 4) << 3)) << 1));
    uint32_t bh_addr = smem_u32(sBh) + b_off;
    uint32_t bl_addr = smem_u32(sBl) + b_off;

    float acc[5][2][4];
#pragma unroll
    for (int mt = 0; mt < 5; mt++)
#pragma unroll
        for (int q = 0; q < 2; q++)
#pragma unroll
            for (int j = 0; j < 4; j++) acc[mt][q][j] = 0.f;

#pragma unroll
    for (int ks = 0; ks < 2; ks++) {
        uint32_t bh[4], bl[4];
        uint32_t ko = (uint32_t)(ks * 16 * (MXB * 2));
        ldm4t(bh, bh_addr + ko);
        ldm4t(bl, bl_addr + ko);
#pragma unroll
        for (int mt = 0; mt < 5; mt++) {
            uint32_t ah[4], al[4];
            uint32_t ao = (uint32_t)(mt * 16 * (MXA * 2) + ks * 32);
            ldm4(ah, a_base + ao);
            ldm4(al, al_base + ao);
            mma16816(acc[mt][0], ah, bh[0], bh[1]);
            mma16816(acc[mt][0], ah, bl[0], bl[1]);
            mma16816(acc[mt][0], al, bh[0], bh[1]);
            mma16816(acc[mt][1], ah, bh[2], bh[3]);
            mma16816(acc[mt][1], ah, bl[2], bl[3]);
            mma16816(acc[mt][1], al, bh[2], bh[3]);
        }
    }

#pragma unroll
    for (int mt = 0; mt < 5; mt++) {
#pragma unroll
        for (int nt8 = 0; nt8 < 2; nt8++) {
            int col = (warp << 4) + (nt8 << 3) + (tig << 1);
            int tc = (ch << 7) + col;
            int t = tc >> 6, c = tc & 63;
#pragma unroll
            for (int h = 0; h < 2; h++) {
                int m = (mt << 4) + g + (h << 3);
                if (m < 75) {
                    int v = m / 3, s = m - 3 * v;
                    size_t oa = (((size_t)(n * 25 + v)) * 64 + t) * 192 + s * 64 + c;
                    *(float2*)&ycat[oa] =
                        make_float2(acc[mt][nt8][h << 1], acc[mt][nt8][(h << 1) + 1]);
                }
            }
        }
    }
}

// ---------------------------------------------------------------------------
// LayerNorm over (V,C) per (n,t) + residual + GELU; padded=1 -> conv z buffer.
// float4-vectorized + warp-shuffle reduction.
// ---------------------------------------------------------------------------
__global__ void ln_t_kernel(const float* __restrict__ in, const float* __restrict__ resid,
                            const float* __restrict__ gg, const float* __restrict__ bb,
                            float* __restrict__ out, int padded) {
    int grp = blockIdx.x;   // n*64+t
    int tid = threadIdx.x;
    int warp = tid >> 5, lane = tid & 31;
    __shared__ float wred[8];
    const float* ip = in + (size_t)grp * 1600;
    bool has2 = tid < 144;   // 400 float4 total: tid and tid+256
    float4 v0 = *(const float4*)&ip[tid << 2];
    float4 v1 = make_float4(0.f, 0.f, 0.f, 0.f);
    if (has2) v1 = *(const float4*)&ip[(tid + 256) << 2];
    float s = v0.x + v0.y + v0.z + v0.w + v1.x + v1.y + v1.z + v1.w;
#pragma unroll
    for (int o = 16; o; o >>= 1) s += __shfl_xor_sync(0xffffffffu, s, o);
    if (lane == 0) wred[warp] = s;
    __syncthreads();
    float mean = (wred[0] + wred[1] + wred[2] + wred[3] +
                  wred[4] + wred[5] + wred[6] + wred[7]) * (1.f / 1600.f);
    float sq;
    {
        float d0 = v0.x - mean, d1 = v0.y - mean, d2 = v0.z - mean, d3 = v0.w - mean;
        sq = d0 * d0 + d1 * d1 + d2 * d2 + d3 * d3;
        if (has2) {
            float e0 = v1.x - mean, e1 = v1.y - mean, e2 = v1.z - mean, e3 = v1.w - mean;
            sq += e0 * e0 + e1 * e1 + e2 * e2 + e3 * e3;
        }
    }
#pragma unroll
    for (int o = 16; o; o >>= 1) sq += __shfl_xor_sync(0xffffffffu, sq, o);
    __syncthreads();   // wred reuse: all reads of pass-1 done
    if (lane == 0) wred[warp] = sq;
    __syncthreads();
    float inv = rsqrtf((wred[0] + wred[1] + wred[2] + wred[3] +
                        wred[4] + wred[5] + wred[6] + wred[7]) * (1.f / 1600.f) + 1e-5f);
    const float* rp = resid + (size_t)grp * 1600;
    int n = grp >> 6, t = grp & 63;
    size_t obase = padded ? ((size_t)(n * TPAD + 3 + t) * 1600) : ((size_t)grp * 1600);
    {
        int i = tid << 2;
        float4 gv = *(const float4*)&gg[i];
        float4 bv = *(const float4*)&bb[i];
        float4 rv = *(const float4*)&rp[i];
        float4 o;
        o.x = gelu_f(rv.x + (v0.x - mean) * inv * gv.x + bv.x);
        o.y = gelu_f(rv.y + (v0.y - mean) * inv * gv.y + bv.y);
        o.z = gelu_f(rv.z + (v0.z - mean) * inv * gv.z + bv.z);
        o.w = gelu_f(rv.w + (v0.w - mean) * inv * gv.w + bv.w);
        *(float4*)&out[obase + i] = o;
    }
    if (has2) {
        int i = (tid + 256) << 2;
        float4 gv = *(const float4*)&gg[i];
        float4 bv = *(const float4*)&bb[i];
        float4 rv = *(const float4*)&rp[i];
        float4 o;
        o.x = gelu_f(rv.x + (v1.x - mean) * inv * gv.x + bv.x);
        o.y = gelu_f(rv.y + (v1.y - mean) * inv * gv.y + bv.y);
        o.z = gelu_f(rv.z + (v1.z - mean) * inv * gv.z + bv.z);
        o.w = gelu_f(rv.w + (v1.w - mean) * inv * gv.w + bv.w);
        *(float4*)&out[obase + i] = o;
    }
}

// ---------------------------------------------------------------------------
// Temporal attention via HMMA (round-8 proven)
// ---------------------------------------------------------------------------
#define BST 88
__global__ void __launch_bounds__(256)
att_t_hmma_kernel(const float* __restrict__ qkt, const float* __restrict__ af,
                  const float* __restrict__ ab, float* __restrict__ attO) {
    __shared__ __align__(16) __nv_bfloat16 sQh[64 * BST], sQl[64 * BST];
    __shared__ __align__(16) __nv_bfloat16 sKh[64 * BST], sKl[64 * BST];
    int n = blockIdx.x, combo = blockIdx.y;
    int dir = combo >> 1, s = combo & 1;
    int jq = (dir * 2 + s) << 4, jk = (4 + dir * 2 + s) << 4;
    int tid = threadIdx.x, warp = tid >> 5, lane = tid & 31;
    int g = lane >> 2, tig = lane & 3;
    int mtile = warp & 3, nbase = (warp >> 2) << 5;
    float acc[4][4];
#pragma unroll
    for (int i = 0; i < 4; i++)
#pragma unroll
        for (int j = 0; j < 4; j++) acc[i][j] = 0.f;

    const float* base = qkt + (size_t)n * 204800;
    uint32_t q_off = (uint32_t)((((mtile << 4) + (lane & 15)) * (BST * 2)) +
                                ((lane >> 4) << 4));
    uint32_t k_off = (uint32_t)(((nbase + (lane & 15)) * (BST * 2)) +
                                ((lane >> 4) << 4));
    uint32_t qh_a = smem_u32(sQh) + q_off, ql_a = smem_u32(sQl) + q_off;
    uint32_t kh_a = smem_u32(sKh) + k_off, kl_a = smem_u32(sKl) + k_off;

    for (int vc = 0; vc < 5; vc++) {
        for (int idx = tid; idx < 2560; idx += 256) {
            int half = idx >= 1280;
            int id = idx - (half ? 1280 : 0);
            int t = id / 20, cq = id - t * 20;
            int vi = cq >> 2, icq = (cq & 3) << 2;
            const float* p = base + (size_t)(t * 25 + vc * 5 + vi) * 128 +
                             (half ? jk : jq) + icq;
            float4 v = *(const float4*)p;
            float h0 = __bfloat162float(__float2bfloat16_rn(v.x));
            float h1 = __bfloat162float(__float2bfloat16_rn(v.y));
            float h2 = __bfloat162float(__float2bfloat16_rn(v.z));
            float h3 = __bfloat162float(__float2bfloat16_rn(v.w));
            int so = t * BST + (vi << 4) + icq;
            if (half) {
                *(uint2*)&sKh[so] = make_uint2(pkbf(h0, h1), pkbf(h2, h3));
                *(uint2*)&sKl[so] = make_uint2(pkbf(v.x - h0, v.y - h1),
                                               pkbf(v.z - h2, v.w - h3));
            } else {
                *(uint2*)&sQh[so] = make_uint2(pkbf(h0, h1), pkbf(h2, h3));
                *(uint2*)&sQl[so] = make_uint2(pkbf(v.x - h0, v.y - h1),
                                               pkbf(v.z - h2, v.w - h3));
            }
        }
        __syncthreads();
#pragma unroll
        for (int ks = 0; ks < 5; ks++) {
            uint32_t qh[4], ql[4];
            ldm4(qh, qh_a + ks * 32);
            ldm4(ql, ql_a + ks * 32);
            uint32_t kh[4], kl[4];
            ldm4(kh, kh_a + ks * 32);
            ldm4(kl, kl_a + ks * 32);
            mma16816(acc[0], qh, kh[0], kh[2]);
            mma16816(acc[0], qh, kl[0], kl[2]);
            mma16816(acc[0], ql, kh[0], kh[2]);
            mma16816(acc[1], qh, kh[1], kh[3]);
            mma16816(acc[1], qh, kl[1], kl[3]);
            mma16816(acc[1], ql, kh[1], kh[3]);
            uint32_t kh2[4], kl2[4];
            ldm4(kh2, kh_a + 16 * (BST * 2) + ks * 32);
            ldm4(kl2, kl_a + 16 * (BST * 2) + ks * 32);
            mma16816(acc[2], qh, kh2[0], kh2[2]);
            mma16816(acc[2], qh, kl2[0], kl2[2]);
            mma16816(acc[2], ql, kh2[0], kh2[2]);
            mma16816(acc[3], qh, kh2[1], kh2[3]);
            mma16816(acc[3], qh, kl2[1], kl2[3]);
            mma16816(acc[3], ql, kh2[1], kh2[3]);
        }
        __syncthreads();
    }
    float alpha = dir ? ab[s] : af[s];
    size_t ob = ((size_t)n * 4 + combo) << 12;
    int t0 = (mtile << 4) + g;
#pragma unroll
    for (int nt = 0; nt < 4; nt++) {
        int q = nbase + ((nt & 1) << 3) + ((nt >> 1) << 4) + (tig << 1);
        float v00 = tanhf(acc[nt][0] * (1.f / 400.f)) * alpha;
        float v01 = tanhf(acc[nt][1] * (1.f / 400.f)) * alpha;
        float v10 = tanhf(acc[nt][2] * (1.f / 400.f)) * alpha;
        float v11 = tanhf(acc[nt][3] * (1.f / 400.f)) * alpha;
        int t1 = t0 + 8;
        bool k00 = dir ? (q >= t0) : (t0 >= q);
        bool k01 = dir ? (q + 1 >= t0) : (t0 >= q + 1);
        bool k10 = dir ? (q >= t1) : (t1 >= q);
        bool k11 = dir ? (q + 1 >= t1) : (t1 >= q + 1);
        *(float2*)&attO[ob + (t0 << 6) + q] =
            make_float2(k00 ? v00 : 0.f, k01 ? v01 : 0.f);
        *(float2*)&attO[ob + (t1 << 6) + q] =
            make_float2(k10 ? v10 : 0.f, k11 ? v11 : 0.f);
    }
}

// ---------------------------------------------------------------------------
// mix_t via HMMA (round-8 proven)
// ---------------------------------------------------------------------------
__global__ void __launch_bounds__(256)
mix_t_hmma_kernel(const float* __restrict__ attT_g, const float* __restrict__ yt,
                  float* __restrict__ zcat) {
    __shared__ __align__(16) __nv_bfloat16 sAh[64 * AST], sAl[64 * AST];
    __shared__ __align__(16) __nv_bfloat16 sBh[64 * AST], sBl[64 * AST];
    int n = blockIdx.x, combo = blockIdx.y, vg = blockIdx.z;
    int tid = threadIdx.x, warp = tid >> 5, lane = tid & 31;
    int g = lane >> 2, tig = lane & 3;
    int mtile = warp & 3, nbase = (warp >> 2) << 5;

    const float* ap = attT_g + (((size_t)n * 4 + combo) << 12);
    for (int i = tid; i < 1024; i += 256) {
        int t = i >> 4, q4 = (i & 15) << 2;
        float4 v = *(const float4*)&ap[(t << 6) + q4];
        float h0 = __bfloat162float(__float2bfloat16_rn(v.x));
        float h1 = __bfloat162float(__float2bfloat16_rn(v.y));
        float h2 = __bfloat162float(__float2bfloat16_rn(v.z));
        float h3 = __bfloat162float(__float2bfloat16_rn(v.w));
        sAh[(q4 + 0) * AST + t] = __float2bfloat16_rn(h0);
        sAh[(q4 + 1) * AST + t] = __float2bfloat16_rn(h1);
        sAh[(q4 + 2) * AST + t] = __float2bfloat16_rn(h2);
        sAh[(q4 + 3) * AST + t] = __float2bfloat16_rn(h3);
        sAl[(q4 + 0) * AST + t] = __float2bfloat16_rn(v.x - h0);
        sAl[(q4 + 1) * AST + t] = __float2bfloat16_rn(v.y - h1);
        sAl[(q4 + 2) * AST + t] = __float2bfloat16_rn(v.z - h2);
        sAl[(q4 + 3) * AST + t] = __float2bfloat16_rn(v.w - h3);
    }

    uint32_t a_off = (uint32_t)(((mtile << 4) + (lane & 15)) * (AST * 2) +
                                ((lane >> 4) << 4));
    uint32_t ah_addr = smem_u32(sAh) + a_off;
    uint32_t al_addr = smem_u32(sAl) + a_off;
    uint32_t b_off = (uint32_t)(((lane & 7) + (lane & 8)) * (AST * 2) +
                                ((nbase + ((lane >> 4) << 3)) << 1));
    uint32_t bh_addr = smem_u32(sBh) + b_off;
    uint32_t bl_addr = smem_u32(sBl) + b_off;

    for (int vi = 0; vi < 5; vi++) {
        int v = vg * 5 + vi;
        for (int i = tid; i < 1024; i += 256) {
            int t = i >> 4, c4 = (i & 15) << 2;
            float4 w = *(const float4*)&yt[((size_t)(n * 64 + t) * 25 + v) * 64 + c4];
            float h0 = __bfloat162float(__float2bfloat16_rn(w.x));
            float h1 = __bfloat162float(__float2bfloat16_rn(w.y));
            float h2 = __bfloat162float(__float2bfloat16_rn(w.z));
            float h3 = __bfloat162float(__float2bfloat16_rn(w.w));
            *(uint2*)&sBh[t * AST + c4] =
                make_uint2(pkbf(h0, h1), pkbf(h2, h3));
            *(uint2*)&sBl[t * AST + c4] =
                make_uint2(pkbf(w.x - h0, w.y - h1), pkbf(w.z - h2, w.w - h3));
        }
        __syncthreads();
        float acc[4][4];
#pragma unroll
        for (int i = 0; i < 4; i++)
#pragma unroll
            for (int j = 0; j < 4; j++) acc[i][j] = 0.f;
#pragma unroll
        for (int ks = 0; ks < 4; ks++) {
            uint32_t a_h[4], a_l[4];
            ldm4(a_h, ah_addr + ks * 32);
            ldm4(a_l, al_addr + ks * 32);
#pragma unroll
            for (int nt2 = 0; nt2 < 2; nt2++) {
                uint32_t bh[4], bl[4];
                uint32_t ko = (uint32_t)(ks * 16 * (AST * 2) + nt2 * 32);
                ldm4t(bh, bh_addr + ko);
                ldm4t(bl, bl_addr + ko);
                mma16816(acc[nt2 * 2 + 0], a_h, bh[0], bh[1]);
                mma16816(acc[nt2 * 2 + 0], a_h, bl[0], bl[1]);
                mma16816(acc[nt2 * 2 + 0], a_l, bh[0], bh[1]);
                mma16816(acc[nt2 * 2 + 1], a_h, bh[2], bh[3]);
                mma16816(acc[nt2 * 2 + 1], a_h, bl[2], bl[3]);
                mma16816(acc[nt2 * 2 + 1], a_l, bh[2], bh[3]);
            }
        }
        int q0 = (mtile << 4) + g;
        size_t ob0 = (((size_t)(n * 64 + q0) * 25 + v) << 8) + (combo << 6);
        size_t ob1 = (((size_t)(n * 64 + q0 + 8) * 25 + v) << 8) + (combo << 6);
#pragma unroll
        for (int nt = 0; nt < 4; nt++) {
            int col = nbase + (nt << 3) + (tig << 1);
            *(float2*)&zcat[ob0 + col] = make_float2(acc[nt][0], acc[nt][1]);
            *(float2*)&zcat[ob1 + col] = make_float2(acc[nt][2], acc[nt][3]);
        }
        __syncthreads();
    }
}

// ---------------------------------------------------------------------------
// BN apply + residual + GELU + final transpose to output (n,v,t,c)
// float4-vectorized (round-16 proven).
// ---------------------------------------------------------------------------
__global__ void bn_final_kernel(const float* __restrict__ z, const float* __restrict__ z1,
                                const float* __restrict__ bg, const float* __restrict__ bb,
                                float* __restrict__ out) {
    size_t e4 = (size_t)blockIdx.x * 256 + threadIdx.x;   // over 3,276,800
    int c = (int)((e4 & 15) << 2);
    size_t r = e4 >> 4;            // (n*25+v)*64+t
    int t = (int)(r & 63);
    size_t r2 = r >> 6;
    int v = (int)(r2 % 25);
    int n = (int)(r2 / 25);
    size_t paddr = ((size_t)(n * TPAD + 3 + t) * 25 + v) * 64 + c;
    float4 zv = *(const float4*)&z[paddr];
    float4 z1v = *(const float4*)&z1[paddr];
    float4 mg = *(const float4*)&bg[c];
    float4 mb = *(const float4*)&bb[c];
    float4 ms = *(const float4*)&g_bnstats[c];
    float4 mq = *(const float4*)&g_bnstats[64 + c];
    float4 o;
    {
        float mean = ms.x * (1.f / 204800.f);
        float var = mq.x * (1.f / 204800.f) - mean * mean;
        o.x = gelu_f(zv.x + (z1v.x - mean) * rsqrtf(var + 1e-5f) * mg.x + mb.x);
        mean = ms.y * (1.f / 204800.f);
        var = mq.y * (1.f / 204800.f) - mean * mean;
        o.y = gelu_f(zv.y + (z1v.y - mean) * rsqrtf(var + 1e-5f) * mg.y + mb.y);
        mean = ms.z * (1.f / 204800.f);
        var = mq.z * (1.f / 204800.f) - mean * mean;
        o.z = gelu_f(zv.z + (z1v.z - mean) * rsqrtf(var + 1e-5f) * mg.z + mb.z);
        mean = ms.w * (1.f / 204800.f);
        var = mq.w * (1.f / 204800.f) - mean * mean;
        o.w = gelu_f(zv.w + (z1v.w - mean) * rsqrtf(var + 1e-5f) * mg.w + mb.w);
    }
    *(float4*)&out[(r << 6) + c] = o;
}

// ---------------------------------------------------------------------------
// Host launcher
// ---------------------------------------------------------------------------
extern "C" void kernel_launch(void* const* d_in, const int* in_sizes, int n_in,
                              void* d_out, int out_size) {
    const float* x          = (const float*)d_in[0];
    const float* w_in_s     = (const float*)d_in[1];
    const float* b_in_s     = (const float*)d_in[2];
    const float* alphas     = (const float*)d_in[3];
    const float* att0s      = (const float*)d_in[4];
    const float* w_out_s    = (const float*)d_in[5];
    const float* b_out_s    = (const float*)d_in[6];
    const float* ln_out_s_g = (const float*)d_in[7];
    const float* ln_out_s_b = (const float*)d_in[8];
    const float* w_ff_s     = (const float*)d_in[9];
    const float* b_ff_s     = (const float*)d_in[10];
    const float* ln_ff_s_g  = (const float*)d_in[11];
    const float* ln_ff_s_b  = (const float*)d_in[12];
    const float* w_in_t     = (const float*)d_in[13];
    const float* b_in_t     = (const float*)d_in[14];
    const float* alphat_f   = (const float*)d_in[15];
    const float* alphat_b   = (const float*)d_in[16];
    const float* w_out_t    = (const float*)d_in[17];
    const float* b_out_t    = (const float*)d_in[18];
    const float* ln_out_t_g = (const float*)d_in[19];
    const float* ln_out_t_b = (const float*)d_in[20];
    const float* w_ff_t     = (const float*)d_in[21];
    const float* b_ff_t     = (const float*)d_in[22];
    const float* ln_ff_t_g  = (const float*)d_in[23];
    const float* ln_ff_t_b  = (const float*)d_in[24];
    const float* conv_w     = (const float*)d_in[25];
    const float* conv_b     = (const float*)d_in[26];
    const float* bn_g       = (const float*)d_in[27];
    const float* bn_b       = (const float*)d_in[28];
    float* out = (float*)d_out;

    float *bufA, *bufB, *bufC, *bufD, *bufE, *bufF, *attS, *attT, *bis, *bit;
    cudaGetSymbolAddress((void**)&bufA, g_bufA);
    cudaGetSymbolAddress((void**)&bufB, g_bufB);
    cudaGetSymbolAddress((void**)&bufC, g_bufC);
    cudaGetSymbolAddress((void**)&bufD, g_bufD);
    cudaGetSymbolAddress((void**)&bufE, g_bufE);
    cudaGetSymbolAddress((void**)&bufF, g_bufF);
    cudaGetSymbolAddress((void**)&attS, g_attS);
    cudaGetSymbolAddress((void**)&attT, g_attT);
    cudaGetSymbolAddress((void**)&bis, g_bis);
    cudaGetSymbolAddress((void**)&bit, g_bit);
    uint4 *Fqk, *Fouts, *Fffs, *Fint, *Foutt, *Ffft, *Fconv;
    cudaGetSymbolAddress((void**)&Fqk, g_Fqk);
    cudaGetSymbolAddress((void**)&Fouts, g_Fouts);
    cudaGetSymbolAddress((void**)&Fffs, g_Fffs);
    cudaGetSymbolAddress((void**)&Fint, g_Fint);
    cudaGetSymbolAddress((void**)&Foutt, g_Foutt);
    cudaGetSymbolAddress((void**)&Ffft, g_Ffft);
    cudaGetSymbolAddress((void**)&Fconv, g_Fconv);
    float* zbase = bufF + GUARD;

    cudaFuncSetAttribute(att_s_hmma_kernel,
                         cudaFuncAttributeMaxDynamicSharedMemorySize, 51200);

    prep_kernel<<<28, 256>>>(w_in_s, b_in_s, w_out_s, w_ff_s, w_in_t, b_in_t,
                             w_out_t, w_ff_t, conv_w);
    zero_pads_kernel<<<1200, 256>>>(zbase);

    // ---- spatial stage ----
    mma_gemm_qk_kernel<<<1600, 256>>>(x, Fqk, bis, bufB, 64);
    att_s_hmma_kernel<<<dim3(NN, 3, 4), 256, 51200>>>(bufB, bufC);
    att_s2_kernel<<<938, 256>>>(bufC, alphas, att0s, attS);
    mix_s_hmma_kernel<<<dim3(NN, 32), 256>>>(x, attS, bufA);
    mma_gemm_lns_kernel<0><<<1600, 256>>>(bufA, Fouts, b_out_s, x,
                                          ln_out_s_g, ln_out_s_b, bufD, 192);
    mma_gemm_lns_kernel<1><<<1600, 256>>>(bufD, Fffs, b_ff_s, x,
                                          ln_ff_s_g, ln_ff_s_b, bufE, 64);

    // ---- temporal stage ----
    mma_gemm_kernel<128><<<1600, 256>>>(bufE, Fint, bit, bufB, 64);
    att_t_hmma_kernel<<<dim3(NN, 4), 256>>>(bufB, alphat_f, alphat_b, attT);
    mix_t_hmma_kernel<<<dim3(NN, 4, 5), 256>>>(attT, bufE, bufA);
    mma_gemm_kernel<64><<<1600, 256>>>(bufA, Foutt, b_out_t, bufC, 256);
    ln_t_kernel<<<8192, 256>>>(bufC, bufE, ln_out_t_g, ln_out_t_b, bufD, 0);
    mma_gemm_kernel<64><<<1600, 256>>>(bufD, Ffft, b_ff_t, bufC, 64);
    ln_t_kernel<<<8192, 256>>>(bufC, bufE, ln_ff_t_g, ln_ff_t_b, zbase, 1);

    // ---- conv + batchnorm + output ----
    mma_gemm_conv_kernel<<<1750, 256>>>(zbase, Fconv, conv_b, bufD, 448);
    bn_final_kernel<<<12800, 256>>>(zbase, bufD, bn_g, bn_b, out);
}